// round 9
// baseline (speedup 1.0000x reference)
#include <cuda_runtime.h>
#include <cuda_bf16.h>
#include <math.h>
#include <stdint.h>

#define QL 512
#define ML 512
#define KL 1024
#define BS 8
#define NH 16
#define DH 64
#define DM 1024
#define DI 4096
#define NV 32000
#define NLAY 6
#define NQ (QL*BS)
#define NK (KL*BS)
#define ASCALE 0.125f

// ---------------- persistent scratch ----------------------------------------
static __device__ float g_core[NQ*DM];
static __device__ float g_xk[NK*DM];
static __device__ float g_q[NQ*DM];
static __device__ float g_kv[(size_t)NK*2*DM];
static __device__ float g_posbuf[KL*DM];
static __device__ float g_rk[KL*DM];
static __device__ float g_P[(size_t)BS*NH*QL*KL];
static __device__ float g_BD[(size_t)BS*NH*QL*KL];
static __device__ float g_att[NQ*DM];
static __device__ float g_tmp[NQ*DM];
static __device__ float g_ff[(size_t)NQ*DI];
static __device__ float g_logits[(size_t)NQ*NV];
// bf16 triple-K operand buffers
static __device__ __nv_bfloat16 g_a3[(size_t)NQ*3*DI];
static __device__ __nv_bfloat16 g_w3[(size_t)DI*3*DM];
static __device__ __nv_bfloat16 g_emb3[(size_t)NV*3*DM];
static __device__ __nv_bfloat16 g_pos3[(size_t)KL*3*DM];

__device__ __forceinline__ uint32_t smem_u32(const void* p) {
    uint32_t a;
    asm("{ .reg .u64 t; cvta.to.shared.u64 t, %1; cvt.u32.u64 %0, t; }" : "=r"(a) : "l"(p));
    return a;
}

// ==================== HMMA bf16x3 GEMM (mma.sync + ldmatrix) =================
// C[M,N] = A3[M,K3] . B3[N,K3]^T, fp32 accumulate.
// A3 rows are [h|l|h]; B3 rows are [h|h|l]  =>  hh + lh + hl  (drops ll ~2^-16)
// M,N multiples of 128; K3 multiple of 32.
#define AST 40                      // smem row stride in bf16 (80B; conflict-free)
#define TILE_ELEMS (128*AST)

template<int EPI>   // 0 none, 1 +bias, 2 +bias+relu
__global__ __launch_bounds__(256)
void tc_gemm(const __nv_bfloat16* __restrict__ A3, const __nv_bfloat16* __restrict__ B3,
             float* __restrict__ C, const float* __restrict__ bias,
             int M, int N, int K3) {
    __shared__ __align__(16) __nv_bfloat16 As[2][TILE_ELEMS];
    __shared__ __align__(16) __nv_bfloat16 Bs[2][TILE_ELEMS];
    int tid = threadIdx.x, wid = tid >> 5, lane = tid & 31;
    int warp_m = wid >> 2, warp_n = wid & 3;        // 2 x 4 warp grid
    int gid = lane >> 2, tig = lane & 3;            // mma fragment coords
    int n0 = blockIdx.x * 128, m0 = blockIdx.y * 128;
    const __nv_bfloat16* Ag = A3 + (size_t)m0 * K3;
    const __nv_bfloat16* Bg = B3 + (size_t)n0 * K3;
    int NC = K3 >> 5;
    uint32_t sA = smem_u32(As), sB = smem_u32(Bs);
    int lrow = tid >> 2, lseg = tid & 3;            // 16B segment loader coords

    // prefetch tile 0
    #pragma unroll
    for (int i = 0; i < 2; i++) {
        int row = lrow + i * 64;
        uint32_t da = sA + (uint32_t)(row * AST + lseg * 8) * 2;
        uint32_t db = sB + (uint32_t)(row * AST + lseg * 8) * 2;
        const void* ga = Ag + (size_t)row * K3 + lseg * 8;
        const void* gb = Bg + (size_t)row * K3 + lseg * 8;
        asm volatile("cp.async.cg.shared.global [%0], [%1], 16;\n" :: "r"(da), "l"(ga));
        asm volatile("cp.async.cg.shared.global [%0], [%1], 16;\n" :: "r"(db), "l"(gb));
    }
    asm volatile("cp.async.commit_group;\n");

    float acc[4][4][4] = {};

    for (int c = 0; c < NC; c++) {
        int cur = c & 1;
        if (c + 1 < NC) {
            int nx = cur ^ 1, k0 = (c + 1) * 32;
            #pragma unroll
            for (int i = 0; i < 2; i++) {
                int row = lrow + i * 64;
                uint32_t da = sA + (uint32_t)(nx * TILE_ELEMS + row * AST + lseg * 8) * 2;
                uint32_t db = sB + (uint32_t)(nx * TILE_ELEMS + row * AST + lseg * 8) * 2;
                const void* ga = Ag + (size_t)row * K3 + k0 + lseg * 8;
                const void* gb = Bg + (size_t)row * K3 + k0 + lseg * 8;
                asm volatile("cp.async.cg.shared.global [%0], [%1], 16;\n" :: "r"(da), "l"(ga));
                asm volatile("cp.async.cg.shared.global [%0], [%1], 16;\n" :: "r"(db), "l"(gb));
            }
            asm volatile("cp.async.commit_group;\n");
            asm volatile("cp.async.wait_group 1;\n");
        } else {
            asm volatile("cp.async.wait_group 0;\n");
        }
        __syncthreads();

        uint32_t aBase = sA + (uint32_t)cur * TILE_ELEMS * 2;
        uint32_t bBase = sB + (uint32_t)cur * TILE_ELEMS * 2;
        #pragma unroll
        for (int ks = 0; ks < 2; ks++) {
            uint32_t a_frag[4][4];
            uint32_t b_frag[4][2];
            // A: x4 ldmatrix; lanes 0-15 give rows, lanes>>4 selects k-half.
            // Result regs: 0=(g,k0) 1=(g+8,k0) 2=(g,k0+8) 3=(g+8,k0+8)  ✓ mma A order
            #pragma unroll
            for (int mt = 0; mt < 4; mt++) {
                uint32_t addr = aBase +
                    (uint32_t)((warp_m * 64 + mt * 16 + (lane & 15)) * AST +
                               ks * 16 + (lane >> 4) * 8) * 2;
                asm volatile("ldmatrix.sync.aligned.m8n8.x4.shared.b16 {%0,%1,%2,%3}, [%4];\n"
                    : "=r"(a_frag[mt][0]), "=r"(a_frag[mt][1]),
                      "=r"(a_frag[mt][2]), "=r"(a_frag[mt][3]) : "r"(addr));
            }
            // B: x4 ldmatrix covering two n8-tiles: matrices = (n,k0),(n,k0+8),(n+8,k0),(n+8,k0+8)
            #pragma unroll
            for (int np = 0; np < 2; np++) {
                uint32_t addr = bBase +
                    (uint32_t)((warp_n * 32 + np * 16 + (lane & 7) + ((lane >> 4) & 1) * 8) * AST +
                               ks * 16 + ((lane >> 3) & 1) * 8) * 2;
                asm volatile("ldmatrix.sync.aligned.m8n8.x4.shared.b16 {%0,%1,%2,%3}, [%4];\n"
                    : "=r"(b_frag[2*np][0]), "=r"(b_frag[2*np][1]),
                      "=r"(b_frag[2*np+1][0]), "=r"(b_frag[2*np+1][1]) : "r"(addr));
            }
            #pragma unroll
            for (int mt = 0; mt < 4; mt++)
                #pragma unroll
                for (int nt = 0; nt < 4; nt++) {
                    asm volatile(
                        "mma.sync.aligned.m16n8k16.row.col.f32.bf16.bf16.f32 "
                        "{%0,%1,%2,%3}, {%4,%5,%6,%7}, {%8,%9}, {%0,%1,%2,%3};\n"
                        : "+f"(acc[mt][nt][0]), "+f"(acc[mt][nt][1]),
                          "+f"(acc[mt][nt][2]), "+f"(acc[mt][nt][3])
                        : "r"(a_frag[mt][0]), "r"(a_frag[mt][1]),
                          "r"(a_frag[mt][2]), "r"(a_frag[mt][3]),
                          "r"(b_frag[nt][0]), "r"(b_frag[nt][1]));
                }
        }
        __syncthreads();
    }

    // epilogue: c0,c1=(gid, tig*2..+1); c2,c3=(gid+8, ...)
    #pragma unroll
    for (int mt = 0; mt < 4; mt++) {
        #pragma unroll
        for (int nt = 0; nt < 4; nt++) {
            int row0 = m0 + warp_m * 64 + mt * 16 + gid;
            int col  = n0 + warp_n * 32 + nt * 8 + tig * 2;
            float2 v0, v1;
            v0.x = acc[mt][nt][0]; v0.y = acc[mt][nt][1];
            v1.x = acc[mt][nt][2]; v1.y = acc[mt][nt][3];
            if (EPI >= 1) {
                float bx = bias[col], by = bias[col + 1];
                v0.x += bx; v0.y += by; v1.x += bx; v1.y += by;
            }
            if (EPI == 2) {
                v0.x = fmaxf(v0.x, 0.f); v0.y = fmaxf(v0.y, 0.f);
                v1.x = fmaxf(v1.x, 0.f); v1.y = fmaxf(v1.y, 0.f);
            }
            *(float2*)(C + (size_t)row0 * N + col)       = v0;
            *(float2*)(C + (size_t)(row0 + 8) * N + col) = v1;
        }
    }
}

// ==================== fp32 -> bf16 triple-K conversions ======================
// MODE 0 (A operand): Y row = [h | l | h]
// MODE 1 (B operand): Y row = [h | h | l]
template<int MODE>
__global__ void split_rows_kernel(const float* __restrict__ X, __nv_bfloat16* __restrict__ Y,
                                  int kshift, long total) {
    long e = ((long)blockIdx.x * 256 + threadIdx.x) * 4;
    if (e >= total) return;
    int K = 1 << kshift;
    long r = e >> kshift; int c = (int)(e & (K - 1));
    float4 v = *(const float4*)(X + e);
    __nv_bfloat16 hx = __float2bfloat16(v.x), hy = __float2bfloat16(v.y);
    __nv_bfloat16 hz = __float2bfloat16(v.z), hw = __float2bfloat16(v.w);
    __nv_bfloat16 lx = __float2bfloat16(v.x - __bfloat162float(hx));
    __nv_bfloat16 ly = __float2bfloat16(v.y - __bfloat162float(hy));
    __nv_bfloat16 lz = __float2bfloat16(v.z - __bfloat162float(hz));
    __nv_bfloat16 lw = __float2bfloat16(v.w - __bfloat162float(hw));
    __nv_bfloat16* yb = Y + r * 3 * K;
    __nv_bfloat162 h01; h01.x = hx; h01.y = hy;
    __nv_bfloat162 h23; h23.x = hz; h23.y = hw;
    __nv_bfloat162 l01; l01.x = lx; l01.y = ly;
    __nv_bfloat162 l23; l23.x = lz; l23.y = lw;
    *(__nv_bfloat162*)(yb + c)     = h01; *(__nv_bfloat162*)(yb + c + 2)     = h23;
    if (MODE == 0) {   // [h | l | h]
        *(__nv_bfloat162*)(yb + K + c)   = l01; *(__nv_bfloat162*)(yb + K + c + 2)   = l23;
        *(__nv_bfloat162*)(yb + 2*K + c) = h01; *(__nv_bfloat162*)(yb + 2*K + c + 2) = h23;
    } else {           // [h | h | l]
        *(__nv_bfloat162*)(yb + K + c)   = h01; *(__nv_bfloat162*)(yb + K + c + 2)   = h23;
        *(__nv_bfloat162*)(yb + 2*K + c) = l01; *(__nv_bfloat162*)(yb + 2*K + c + 2) = l23;
    }
}

// W[K,N] -> Y[N,3K] = [h | h | l]  (B operand: transpose + split)
__global__ void split_tr_kernel(const float* __restrict__ W, __nv_bfloat16* __restrict__ Y,
                                int K, int N) {
    __shared__ float s[32][33];
    int n0 = blockIdx.x * 32, k0 = blockIdx.y * 32;
    int tx = threadIdx.x, ty = threadIdx.y;
    for (int i = ty; i < 32; i += 8)
        s[i][tx] = W[(size_t)(k0 + i) * N + n0 + tx];
    __syncthreads();
    for (int i = ty; i < 32; i += 8) {
        int n = n0 + i, k = k0 + tx;
        float v = s[tx][i];
        __nv_bfloat16 h = __float2bfloat16(v);
        __nv_bfloat16 l = __float2bfloat16(v - __bfloat162float(h));
        __nv_bfloat16* yb = Y + (size_t)n * 3 * K;
        yb[k] = h; yb[K + k] = h; yb[2*K + k] = l;
    }
}

// ==================== misc kernels ===========================================
__global__ void embed_kernel(const int* __restrict__ data, const float* __restrict__ embW) {
    int t = blockIdx.x;
    int tok = data[t];
    int c = threadIdx.x * 4;
    float4 v = *(const float4*)(embW + (size_t)tok * DM + c);
    *(float4*)(g_core + (size_t)t * DM + c) = v;
}

__global__ void pos_kernel() {
    int p = blockIdx.x;
    float ps = (float)(KL - 1 - p);
    for (int j = threadIdx.x; j < 512; j += 256) {
        float f = powf(10000.0f, -(float)j / 512.0f);
        float a = ps * f;
        g_posbuf[p * DM + j]       = sinf(a);
        g_posbuf[p * DM + 512 + j] = cosf(a);
    }
}

__global__ void concat_kernel(const float* __restrict__ mem_i) {
    int i = blockIdx.x * 256 + threadIdx.x;
    const int HALF = ML * BS * DM / 4;
    float4 v = (i < HALF) ? ((const float4*)mem_i)[i]
                          : ((const float4*)g_core)[i - HALF];
    ((float4*)g_xk)[i] = v;
}

__global__ void copyout_kernel(float* __restrict__ dst) {
    int i = blockIdx.x * 256 + threadIdx.x;
    ((float4*)dst)[i] = ((const float4*)g_core)[i];
}

__global__ void ac_kernel(const float* __restrict__ rwb) {
    int jt = blockIdx.x, it = blockIdx.y, bn = blockIdx.z;
    int b = bn >> 4, n = bn & 15;
    __shared__ float Qs[64][68];
    __shared__ float Ks[64][68];
    int tid = threadIdx.x;
    int i0 = it * 64, j0 = jt * 64;
    for (int l = tid; l < 1024; l += 256) {
        int r = l >> 4, c = (l & 15) * 4;
        float4 qv = *(const float4*)&g_q[((size_t)(i0 + r) * BS + b) * DM + n * DH + c];
        float4 bv = *(const float4*)&rwb[n * DH + c];
        Qs[c+0][r] = qv.x + bv.x; Qs[c+1][r] = qv.y + bv.y;
        Qs[c+2][r] = qv.z + bv.z; Qs[c+3][r] = qv.w + bv.w;
        float4 kv = *(const float4*)&g_kv[((size_t)(j0 + r) * BS + b) * (2*DM) + n * DH + c];
        Ks[c+0][r] = kv.x; Ks[c+1][r] = kv.y; Ks[c+2][r] = kv.z; Ks[c+3][r] = kv.w;
    }
    __syncthreads();
    int tx = tid & 15, ty = tid >> 4;
    float acc[4][4] = {};
    #pragma unroll 8
    for (int d = 0; d < 64; d++) {
        float4 a = *(float4*)&Qs[d][ty * 4];
        float4 k = *(float4*)&Ks[d][tx * 4];
        float av[4] = {a.x,a.y,a.z,a.w}, kv2[4] = {k.x,k.y,k.z,k.w};
        #pragma unroll
        for (int e = 0; e < 4; e++)
            #pragma unroll
            for (int f = 0; f < 4; f++)
                acc[e][f] += av[e] * kv2[f];
    }
    #pragma unroll
    for (int e = 0; e < 4; e++) {
        int i = i0 + ty * 4 + e;
        float4 o = {acc[e][0], acc[e][1], acc[e][2], acc[e][3]};
        *(float4*)&g_P[((size_t)bn * QL + i) * KL + j0 + tx * 4] = o;
    }
}

__global__ void bd_kernel(const float* __restrict__ rrb) {
    int jt = blockIdx.x, it = blockIdx.y, bn = blockIdx.z;
    int b = bn >> 4, n = bn & 15;
    __shared__ float Qs[64][68];
    __shared__ float Rs[64][68];
    int tid = threadIdx.x;
    int i0 = it * 64, j0 = jt * 64;
    for (int l = tid; l < 1024; l += 256) {
        int r = l >> 4, c = (l & 15) * 4;
        float4 qv = *(const float4*)&g_q[((size_t)(i0 + r) * BS + b) * DM + n * DH + c];
        float4 bv = *(const float4*)&rrb[n * DH + c];
        Qs[c+0][r] = qv.x + bv.x; Qs[c+1][r] = qv.y + bv.y;
        Qs[c+2][r] = qv.z + bv.z; Qs[c+3][r] = qv.w + bv.w;
        float4 rv = *(const float4*)&g_rk[(size_t)(j0 + r) * DM + n * DH + c];
        Rs[c+0][r] = rv.x; Rs[c+1][r] = rv.y; Rs[c+2][r] = rv.z; Rs[c+3][r] = rv.w;
    }
    __syncthreads();
    int tx = tid & 15, ty = tid >> 4;
    float acc[4][4] = {};
    #pragma unroll 8
    for (int d = 0; d < 64; d++) {
        float4 a = *(float4*)&Qs[d][ty * 4];
        float4 k = *(float4*)&Rs[d][tx * 4];
        float av[4] = {a.x,a.y,a.z,a.w}, kv2[4] = {k.x,k.y,k.z,k.w};
        #pragma unroll
        for (int e = 0; e < 4; e++)
            #pragma unroll
            for (int f = 0; f < 4; f++)
                acc[e][f] += av[e] * kv2[f];
    }
    #pragma unroll
    for (int e = 0; e < 4; e++) {
        int i = i0 + ty * 4 + e;
        float4 o = {acc[e][0], acc[e][1], acc[e][2], acc[e][3]};
        *(float4*)&g_BD[((size_t)bn * QL + i) * KL + j0 + tx * 4] = o;
    }
}

__global__ void softmax_kernel() {
    int i = blockIdx.x, bn = blockIdx.y;
    const float* ac = &g_P[((size_t)bn * QL + i) * KL];
    const float* bd = &g_BD[((size_t)bn * QL + i) * KL];
    int tid = threadIdx.x;
    int lim = i + ML;
    float v[4]; float mx = -1e30f;
    #pragma unroll
    for (int r = 0; r < 4; r++) {
        int j = r * 256 + tid;
        float s = (j <= lim) ? ASCALE * (ac[j] + bd[j + QL - 1 - i]) : -1e30f;
        v[r] = s; mx = fmaxf(mx, s);
    }
    __shared__ float red[256];
    red[tid] = mx; __syncthreads();
    for (int st = 128; st > 0; st >>= 1) {
        if (tid < st) red[tid] = fmaxf(red[tid], red[tid + st]);
        __syncthreads();
    }
    mx = red[0]; __syncthreads();
    float sum = 0.f;
    #pragma unroll
    for (int r = 0; r < 4; r++) { v[r] = __expf(v[r] - mx); sum += v[r]; }
    red[tid] = sum; __syncthreads();
    for (int st = 128; st > 0; st >>= 1) {
        if (tid < st) red[tid] += red[tid + st];
        __syncthreads();
    }
    float inv = 1.0f / red[0];
    float* p = &g_P[((size_t)bn * QL + i) * KL];
    #pragma unroll
    for (int r = 0; r < 4; r++) p[r * 256 + tid] = v[r] * inv;
}

__global__ void pv_kernel() {
    int it = blockIdx.x, bn = blockIdx.y;
    int b = bn >> 4, n = bn & 15;
    __shared__ float Ps[32][68];
    __shared__ float Vs[32][68];
    int tid = threadIdx.x;
    int i0 = it * 64;
    int tx = tid & 15, ty = tid >> 4;
    float acc[4][4] = {};
    for (int jc = 0; jc < KL; jc += 32) {
        for (int l = tid; l < 512; l += 256) {
            int r = l >> 3, c = (l & 7) * 4;
            float4 pv = *(const float4*)&g_P[((size_t)bn * QL + i0 + r) * KL + jc + c];
            Ps[c+0][r] = pv.x; Ps[c+1][r] = pv.y; Ps[c+2][r] = pv.z; Ps[c+3][r] = pv.w;
            int vr = l >> 4, vc = (l & 15) * 4;
            float4 vv = *(const float4*)&g_kv[((size_t)(jc + vr) * BS + b) * (2*DM) + DM + n * DH + vc];
            *(float4*)&Vs[vr][vc] = vv;
        }
        __syncthreads();
        #pragma unroll
        for (int k = 0; k < 32; k++) {
            float4 a = *(float4*)&Ps[k][ty * 4];
            float4 w = *(float4*)&Vs[k][tx * 4];
            float av[4] = {a.x,a.y,a.z,a.w}, wv[4] = {w.x,w.y,w.z,w.w};
            #pragma unroll
            for (int e = 0; e < 4; e++)
                #pragma unroll
                for (int f = 0; f < 4; f++)
                    acc[e][f] += av[e] * wv[f];
        }
        __syncthreads();
    }
    #pragma unroll
    for (int e = 0; e < 4; e++) {
        int i = i0 + ty * 4 + e;
        float4 o = {acc[e][0], acc[e][1], acc[e][2], acc[e][3]};
        *(float4*)&g_att[((size_t)i * BS + b) * DM + n * DH + tx * 4] = o;
    }
}

__global__ void add_ln_kernel(float* __restrict__ io, const float* __restrict__ add,
                              const float* __restrict__ g, const float* __restrict__ bt) {
    int t = blockIdx.x, tid = threadIdx.x;
    size_t base = (size_t)t * DM;
    float x[4]; float s = 0.f, sq = 0.f;
    #pragma unroll
    for (int r = 0; r < 4; r++) {
        int d = r * 256 + tid;
        float v = io[base + d] + add[base + d];
        x[r] = v; s += v; sq += v * v;
    }
    __shared__ float rs[256], rq[256];
    rs[tid] = s; rq[tid] = sq; __syncthreads();
    for (int st = 128; st > 0; st >>= 1) {
        if (tid < st) { rs[tid] += rs[tid + st]; rq[tid] += rq[tid + st]; }
        __syncthreads();
    }
    float mean = rs[0] * (1.0f / DM);
    float var  = rq[0] * (1.0f / DM) - mean * mean;
    float rstd = rsqrtf(var + 1e-5f);
    #pragma unroll
    for (int r = 0; r < 4; r++) {
        int d = r * 256 + tid;
        io[base + d] = (x[r] - mean) * rstd * g[d] + bt[d];
    }
}

__global__ void loss_kernel(const int* __restrict__ target, float* __restrict__ out) {
    int t = blockIdx.x, tid = threadIdx.x;
    const float* row = &g_logits[(size_t)t * NV];
    float mx = -1e30f;
    for (int j = tid; j < NV; j += 256) mx = fmaxf(mx, row[j]);
    __shared__ float red[256];
    red[tid] = mx; __syncthreads();
    for (int st = 128; st > 0; st >>= 1) {
        if (tid < st) red[tid] = fmaxf(red[tid], red[tid + st]);
        __syncthreads();
    }
    mx = red[0]; __syncthreads();
    float s = 0.f;
    for (int j = tid; j < NV; j += 256) s += __expf(row[j] - mx);
    red[tid] = s; __syncthreads();
    for (int st = 128; st > 0; st >>= 1) {
        if (tid < st) red[tid] += red[tid + st];
        __syncthreads();
    }
    if (tid == 0) {
        float lse = logf(red[0]) + mx;
        out[t] = lse - row[target[t]];
    }
}

// ==================== host orchestration =====================================
static void gemm3(const __nv_bfloat16* A3, const __nv_bfloat16* B3, float* C,
                  const float* bias, int M, int N, int K3, int epi) {
    dim3 grid(N / 128, M / 128);
    if (epi == 0)      tc_gemm<0><<<grid, 256>>>(A3, B3, C, bias, M, N, K3);
    else if (epi == 1) tc_gemm<1><<<grid, 256>>>(A3, B3, C, bias, M, N, K3);
    else               tc_gemm<2><<<grid, 256>>>(A3, B3, C, bias, M, N, K3);
}
static void split_rowsA(const float* X, __nv_bfloat16* Y, long R, int kshift) {
    long total = R << kshift;
    long blocks = (total / 4 + 255) / 256;
    split_rows_kernel<0><<<(int)blocks, 256>>>(X, Y, kshift, total);
}
static void split_rowsB(const float* X, __nv_bfloat16* Y, long R, int kshift) {
    long total = R << kshift;
    long blocks = (total / 4 + 255) / 256;
    split_rows_kernel<1><<<(int)blocks, 256>>>(X, Y, kshift, total);
}
static void split_tr(const float* W, __nv_bfloat16* Y, int K, int N) {
    split_tr_kernel<<<dim3(N / 32, K / 32), dim3(32, 8)>>>(W, Y, K, N);
}

extern "C" void kernel_launch(void* const* d_in, const int* in_sizes, int n_in,
                              void* d_out, int out_size) {
    const int*   data   = (const int*)d_in[0];
    const int*   target = (const int*)d_in[1];
    const float* memory = (const float*)d_in[2];
    const float* embW   = (const float*)d_in[3];
    const float* rwb    = (const float*)d_in[4];
    const float* rrb    = (const float*)d_in[5];
    const float* Wq     = (const float*)d_in[6];
    const float* Wkv    = (const float*)d_in[7];
    const float* Wr     = (const float*)d_in[8];
    const float* Wo     = (const float*)d_in[9];
    const float* W1     = (const float*)d_in[10];
    const float* b1     = (const float*)d_in[11];
    const float* W2     = (const float*)d_in[12];
    const float* b2     = (const float*)d_in[13];
    const float* ln1g   = (const float*)d_in[14];
    const float* ln1b   = (const float*)d_in[15];
    const float* ln2g   = (const float*)d_in[16];
    const float* ln2b   = (const float*)d_in[17];

    float* out = (float*)d_out;
    const long SLAB = (long)ML * BS * DM;
    float* out_mems = (out_size >= 4096L + NLAY * SLAB) ? out + 4096 : nullptr;

    float *p_core, *p_q, *p_kv, *p_pos, *p_rk, *p_att, *p_tmp, *p_ff, *p_xk, *p_logits;
    __nv_bfloat16 *p_a3, *p_w3, *p_emb3, *p_pos3;
    cudaGetSymbolAddress((void**)&p_core,   g_core);
    cudaGetSymbolAddress((void**)&p_xk,     g_xk);
    cudaGetSymbolAddress((void**)&p_q,      g_q);
    cudaGetSymbolAddress((void**)&p_kv,     g_kv);
    cudaGetSymbolAddress((void**)&p_pos,    g_posbuf);
    cudaGetSymbolAddress((void**)&p_rk,     g_rk);
    cudaGetSymbolAddress((void**)&p_att,    g_att);
    cudaGetSymbolAddress((void**)&p_tmp,    g_tmp);
    cudaGetSymbolAddress((void**)&p_ff,     g_ff);
    cudaGetSymbolAddress((void**)&p_logits, g_logits);
    cudaGetSymbolAddress((void**)&p_a3,     g_a3);
    cudaGetSymbolAddress((void**)&p_w3,     g_w3);
    cudaGetSymbolAddress((void**)&p_emb3,   g_emb3);
    cudaGetSymbolAddress((void**)&p_pos3,   g_pos3);

    embed_kernel<<<NQ, 256>>>(data, embW);
    pos_kernel<<<KL, 256>>>();
    split_rowsA(p_pos, p_pos3, KL, 10);         // pos is an A operand -> [h|l|h]
    split_rowsB(embW, p_emb3, NV, 10);          // emb is the logits B operand -> [h|h|l]

    for (int L = 0; L < NLAY; L++) {
        if (out_mems)
            copyout_kernel<<<4096, 256>>>(out_mems + (long)L * SLAB);
        concat_kernel<<<8192, 256>>>(memory + (long)L * SLAB);

        // q = core @ Wq
        split_rowsA(p_core, p_a3, NQ, 10);
        split_tr(Wq + (long)L*DM*DM, p_w3, DM, DM);
        gemm3(p_a3, p_w3, p_q, nullptr, NQ, DM, 3*DM, 0);
        // kv = xk @ Wkv
        split_rowsA(p_xk, p_a3, NK, 10);
        split_tr(Wkv + (long)L*DM*2*DM, p_w3, DM, 2*DM);
        gemm3(p_a3, p_w3, p_kv, nullptr, NK, 2*DM, 3*DM, 0);
        // rk = pos @ Wr
        split_tr(Wr + (long)L*DM*DM, p_w3, DM, DM);
        gemm3(p_pos3, p_w3, p_rk, nullptr, KL, DM, 3*DM, 0);

        ac_kernel<<<dim3(16, 8, 128), 256>>>(rwb);
        bd_kernel<<<dim3(16, 8, 128), 256>>>(rrb);
        softmax_kernel<<<dim3(QL, 128), 256>>>();
        pv_kernel<<<dim3(8, 128), 256>>>();

        // attn_out = att @ Wo
        split_rowsA(p_att, p_a3, NQ, 10);
        split_tr(Wo + (long)L*DM*DM, p_w3, DM, DM);
        gemm3(p_a3, p_w3, p_tmp, nullptr, NQ, DM, 3*DM, 0);
        add_ln_kernel<<<NQ, 256>>>(p_core, p_tmp, ln1g + L*DM, ln1b + L*DM);

        // ff = relu(core@W1+b1) @ W2 + b2
        split_rowsA(p_core, p_a3, NQ, 10);
        split_tr(W1 + (long)L*DM*DI, p_w3, DM, DI);
        gemm3(p_a3, p_w3, p_ff, b1 + L*DI, NQ, DI, 3*DM, 2);
        split_rowsA(p_ff, p_a3, NQ, 12);
        split_tr(W2 + (long)L*DI*DM, p_w3, DI, DM);
        gemm3(p_a3, p_w3, p_tmp, b2 + L*DM, NQ, DM, 3*DI, 1);
        add_ln_kernel<<<NQ, 256>>>(p_core, p_tmp, ln2g + L*DM, ln2b + L*DM);
    }

    // logits = core @ embW^T ; loss
    split_rowsA(p_core, p_a3, NQ, 10);
    gemm3(p_a3, p_emb3, p_logits, nullptr, NQ, NV, 3*DM, 0);
    loss_kernel<<<NQ, 256>>>(target, out);
}

// round 10
// speedup vs baseline: 1.6660x; 1.6660x over previous
#include <cuda_runtime.h>
#include <cuda_bf16.h>
#include <math.h>
#include <stdint.h>

#define QL 512
#define ML 512
#define KL 1024
#define BS 8
#define NH 16
#define DH 64
#define DM 1024
#define DI 4096
#define NV 32000
#define NLAY 6
#define NQ (QL*BS)
#define NK (KL*BS)
#define ASCALE 0.125f

// ---------------- persistent scratch ----------------------------------------
static __device__ float g_core[NQ*DM];
static __device__ float g_xk[NK*DM];
static __device__ float g_q[NQ*DM];
static __device__ float g_kv[(size_t)NK*2*DM];
static __device__ float g_posbuf[KL*DM];
static __device__ float g_rk[KL*DM];
static __device__ float g_P[(size_t)BS*NH*QL*KL];
static __device__ float g_BD[(size_t)BS*NH*QL*KL];
static __device__ float g_att[NQ*DM];
static __device__ float g_tmp[NQ*DM];
static __device__ float g_ff[(size_t)NQ*DI];
static __device__ float g_logits[(size_t)NQ*NV];
// bf16 triple-K operand buffers (dense GEMMs)
static __device__ __nv_bfloat16 g_a3[(size_t)NQ*3*DI];
static __device__ __nv_bfloat16 g_w3[(size_t)DI*3*DM];
static __device__ __nv_bfloat16 g_emb3[(size_t)NV*3*DM];
static __device__ __nv_bfloat16 g_pos3[(size_t)KL*3*DM];
// bf16 triple-K operand buffers (attention)
static __device__ __nv_bfloat16 g_q3a[(size_t)BS*NH*QL*192];   // (q+rwb)  A-layout
static __device__ __nv_bfloat16 g_q3b[(size_t)BS*NH*QL*192];   // (q+rrb)  A-layout
static __device__ __nv_bfloat16 g_k3 [(size_t)BS*NH*KL*192];   // K        B-layout
static __device__ __nv_bfloat16 g_rk3[(size_t)NH*KL*192];      // r_k      B-layout
static __device__ __nv_bfloat16 g_v3 [(size_t)BS*NH*DH*3*KL];  // V^T      B-layout over KL
static __device__ __nv_bfloat16 g_p3 [(size_t)BS*NH*QL*3*KL];  // probs    A-layout over KL

__device__ __forceinline__ uint32_t smem_u32(const void* p) {
    uint32_t a;
    asm("{ .reg .u64 t; cvta.to.shared.u64 t, %1; cvt.u32.u64 %0, t; }" : "=r"(a) : "l"(p));
    return a;
}
__device__ __forceinline__ void split1(float v, __nv_bfloat16& h, __nv_bfloat16& l) {
    h = __float2bfloat16(v);
    l = __float2bfloat16(v - __bfloat162float(h));
}

// ==================== HMMA bf16x3 GEMM (R8 core: mma.sync + direct LDS) ======
// C[M,N] = A3[M,K3] . B3[N,K3]^T, fp32 accumulate.
// A3 rows are [h|l|h]; B3 rows are [h|h|l]  =>  hh + lh + hl
#define AST 40                      // smem row stride in bf16 (80B; conflict-free)
#define TILE_ELEMS (128*AST)

template<int EPI>   // 0 none, 1 +bias, 2 +bias+relu
__global__ __launch_bounds__(256, 2)
void tc_gemm(const __nv_bfloat16* __restrict__ A3, const __nv_bfloat16* __restrict__ B3,
             float* __restrict__ C, const float* __restrict__ bias,
             int M, int N, int K3) {
    __shared__ __align__(16) __nv_bfloat16 As[2][TILE_ELEMS];
    __shared__ __align__(16) __nv_bfloat16 Bs[2][TILE_ELEMS];
    int tid = threadIdx.x, wid = tid >> 5, lane = tid & 31;
    int warp_m = wid >> 2, warp_n = wid & 3;
    int gid = lane >> 2, tig = lane & 3;
    int n0 = blockIdx.x * 128, m0 = blockIdx.y * 128;
    const __nv_bfloat16* Ag = A3 + (size_t)m0 * K3;
    const __nv_bfloat16* Bg = B3 + (size_t)n0 * K3;
    int NC = K3 >> 5;
    uint32_t sA = smem_u32(As), sB = smem_u32(Bs);
    int lrow = tid >> 2, lseg = tid & 3;

    #pragma unroll
    for (int i = 0; i < 2; i++) {
        int row = lrow + i * 64;
        uint32_t da = sA + (uint32_t)(row * AST + lseg * 8) * 2;
        uint32_t db = sB + (uint32_t)(row * AST + lseg * 8) * 2;
        const void* ga = Ag + (size_t)row * K3 + lseg * 8;
        const void* gb = Bg + (size_t)row * K3 + lseg * 8;
        asm volatile("cp.async.cg.shared.global [%0], [%1], 16;\n" :: "r"(da), "l"(ga));
        asm volatile("cp.async.cg.shared.global [%0], [%1], 16;\n" :: "r"(db), "l"(gb));
    }
    asm volatile("cp.async.commit_group;\n");

    float acc[4][4][4] = {};

    for (int c = 0; c < NC; c++) {
        int cur = c & 1;
        if (c + 1 < NC) {
            int nx = cur ^ 1, k0 = (c + 1) * 32;
            #pragma unroll
            for (int i = 0; i < 2; i++) {
                int row = lrow + i * 64;
                uint32_t da = sA + (uint32_t)(nx * TILE_ELEMS + row * AST + lseg * 8) * 2;
                uint32_t db = sB + (uint32_t)(nx * TILE_ELEMS + row * AST + lseg * 8) * 2;
                const void* ga = Ag + (size_t)row * K3 + k0 + lseg * 8;
                const void* gb = Bg + (size_t)row * K3 + k0 + lseg * 8;
                asm volatile("cp.async.cg.shared.global [%0], [%1], 16;\n" :: "r"(da), "l"(ga));
                asm volatile("cp.async.cg.shared.global [%0], [%1], 16;\n" :: "r"(db), "l"(gb));
            }
            asm volatile("cp.async.commit_group;\n");
            asm volatile("cp.async.wait_group 1;\n");
        } else {
            asm volatile("cp.async.wait_group 0;\n");
        }
        __syncthreads();

        const __nv_bfloat16* Ab = &As[cur][0];
        const __nv_bfloat16* Bb = &Bs[cur][0];
        #pragma unroll
        for (int ks = 0; ks < 2; ks++) {
            int kk = ks * 16;
            uint32_t a_frag[4][4];
            uint32_t b_frag[4][2];
            #pragma unroll
            for (int mt = 0; mt < 4; mt++) {
                int r0 = (warp_m * 64 + mt * 16 + gid) * AST + kk + tig * 2;
                a_frag[mt][0] = *(const uint32_t*)(Ab + r0);
                a_frag[mt][1] = *(const uint32_t*)(Ab + r0 + 8 * AST);
                a_frag[mt][2] = *(const uint32_t*)(Ab + r0 + 8);
                a_frag[mt][3] = *(const uint32_t*)(Ab + r0 + 8 * AST + 8);
            }
            #pragma unroll
            for (int nt = 0; nt < 4; nt++) {
                int rn = (warp_n * 32 + nt * 8 + gid) * AST + kk + tig * 2;
                b_frag[nt][0] = *(const uint32_t*)(Bb + rn);
                b_frag[nt][1] = *(const uint32_t*)(Bb + rn + 8);
            }
            #pragma unroll
            for (int mt = 0; mt < 4; mt++)
                #pragma unroll
                for (int nt = 0; nt < 4; nt++) {
                    asm volatile(
                        "mma.sync.aligned.m16n8k16.row.col.f32.bf16.bf16.f32 "
                        "{%0,%1,%2,%3}, {%4,%5,%6,%7}, {%8,%9}, {%0,%1,%2,%3};\n"
                        : "+f"(acc[mt][nt][0]), "+f"(acc[mt][nt][1]),
                          "+f"(acc[mt][nt][2]), "+f"(acc[mt][nt][3])
                        : "r"(a_frag[mt][0]), "r"(a_frag[mt][1]),
                          "r"(a_frag[mt][2]), "r"(a_frag[mt][3]),
                          "r"(b_frag[nt][0]), "r"(b_frag[nt][1]));
                }
        }
        __syncthreads();
    }

    #pragma unroll
    for (int mt = 0; mt < 4; mt++) {
        #pragma unroll
        for (int nt = 0; nt < 4; nt++) {
            int row0 = m0 + warp_m * 64 + mt * 16 + gid;
            int col  = n0 + warp_n * 32 + nt * 8 + tig * 2;
            float2 v0, v1;
            v0.x = acc[mt][nt][0]; v0.y = acc[mt][nt][1];
            v1.x = acc[mt][nt][2]; v1.y = acc[mt][nt][3];
            if (EPI >= 1) {
                float bx = bias[col], by = bias[col + 1];
                v0.x += bx; v0.y += by; v1.x += bx; v1.y += by;
            }
            if (EPI == 2) {
                v0.x = fmaxf(v0.x, 0.f); v0.y = fmaxf(v0.y, 0.f);
                v1.x = fmaxf(v1.x, 0.f); v1.y = fmaxf(v1.y, 0.f);
            }
            *(float2*)(C + (size_t)row0 * N + col)       = v0;
            *(float2*)(C + (size_t)(row0 + 8) * N + col) = v1;
        }
    }
}

// ---- batched variant (blockIdx.z selects (b,n) slice) for AC / BD scores ----
__global__ __launch_bounds__(256, 2)
void tc_gemm_bat(const __nv_bfloat16* __restrict__ A3, long strideA,
                 const __nv_bfloat16* __restrict__ B3, long strideB, int bmask,
                 float* __restrict__ C, long strideC, int ldc,
                 int N, int K3) {
    __shared__ __align__(16) __nv_bfloat16 As[2][TILE_ELEMS];
    __shared__ __align__(16) __nv_bfloat16 Bs[2][TILE_ELEMS];
    int tid = threadIdx.x, wid = tid >> 5, lane = tid & 31;
    int warp_m = wid >> 2, warp_n = wid & 3;
    int gid = lane >> 2, tig = lane & 3;
    int n0 = blockIdx.x * 128, m0 = blockIdx.y * 128, bz = blockIdx.z;
    const __nv_bfloat16* Ag = A3 + (size_t)bz * strideA + (size_t)m0 * K3;
    const __nv_bfloat16* Bg = B3 + (size_t)(bz & bmask) * strideB + (size_t)n0 * K3;
    float* Cg = C + (size_t)bz * strideC;
    int NC = K3 >> 5;
    uint32_t sA = smem_u32(As), sB = smem_u32(Bs);
    int lrow = tid >> 2, lseg = tid & 3;

    #pragma unroll
    for (int i = 0; i < 2; i++) {
        int row = lrow + i * 64;
        uint32_t da = sA + (uint32_t)(row * AST + lseg * 8) * 2;
        uint32_t db = sB + (uint32_t)(row * AST + lseg * 8) * 2;
        const void* ga = Ag + (size_t)row * K3 + lseg * 8;
        const void* gb = Bg + (size_t)row * K3 + lseg * 8;
        asm volatile("cp.async.cg.shared.global [%0], [%1], 16;\n" :: "r"(da), "l"(ga));
        asm volatile("cp.async.cg.shared.global [%0], [%1], 16;\n" :: "r"(db), "l"(gb));
    }
    asm volatile("cp.async.commit_group;\n");

    float acc[4][4][4] = {};

    for (int c = 0; c < NC; c++) {
        int cur = c & 1;
        if (c + 1 < NC) {
            int nx = cur ^ 1, k0 = (c + 1) * 32;
            #pragma unroll
            for (int i = 0; i < 2; i++) {
                int row = lrow + i * 64;
                uint32_t da = sA + (uint32_t)(nx * TILE_ELEMS + row * AST + lseg * 8) * 2;
                uint32_t db = sB + (uint32_t)(nx * TILE_ELEMS + row * AST + lseg * 8) * 2;
                const void* ga = Ag + (size_t)row * K3 + k0 + lseg * 8;
                const void* gb = Bg + (size_t)row * K3 + k0 + lseg * 8;
                asm volatile("cp.async.cg.shared.global [%0], [%1], 16;\n" :: "r"(da), "l"(ga));
                asm volatile("cp.async.cg.shared.global [%0], [%1], 16;\n" :: "r"(db), "l"(gb));
            }
            asm volatile("cp.async.commit_group;\n");
            asm volatile("cp.async.wait_group 1;\n");
        } else {
            asm volatile("cp.async.wait_group 0;\n");
        }
        __syncthreads();

        const __nv_bfloat16* Ab = &As[cur][0];
        const __nv_bfloat16* Bb = &Bs[cur][0];
        #pragma unroll
        for (int ks = 0; ks < 2; ks++) {
            int kk = ks * 16;
            uint32_t a_frag[4][4];
            uint32_t b_frag[4][2];
            #pragma unroll
            for (int mt = 0; mt < 4; mt++) {
                int r0 = (warp_m * 64 + mt * 16 + gid) * AST + kk + tig * 2;
                a_frag[mt][0] = *(const uint32_t*)(Ab + r0);
                a_frag[mt][1] = *(const uint32_t*)(Ab + r0 + 8 * AST);
                a_frag[mt][2] = *(const uint32_t*)(Ab + r0 + 8);
                a_frag[mt][3] = *(const uint32_t*)(Ab + r0 + 8 * AST + 8);
            }
            #pragma unroll
            for (int nt = 0; nt < 4; nt++) {
                int rn = (warp_n * 32 + nt * 8 + gid) * AST + kk + tig * 2;
                b_frag[nt][0] = *(const uint32_t*)(Bb + rn);
                b_frag[nt][1] = *(const uint32_t*)(Bb + rn + 8);
            }
            #pragma unroll
            for (int mt = 0; mt < 4; mt++)
                #pragma unroll
                for (int nt = 0; nt < 4; nt++) {
                    asm volatile(
                        "mma.sync.aligned.m16n8k16.row.col.f32.bf16.bf16.f32 "
                        "{%0,%1,%2,%3}, {%4,%5,%6,%7}, {%8,%9}, {%0,%1,%2,%3};\n"
                        : "+f"(acc[mt][nt][0]), "+f"(acc[mt][nt][1]),
                          "+f"(acc[mt][nt][2]), "+f"(acc[mt][nt][3])
                        : "r"(a_frag[mt][0]), "r"(a_frag[mt][1]),
                          "r"(a_frag[mt][2]), "r"(a_frag[mt][3]),
                          "r"(b_frag[nt][0]), "r"(b_frag[nt][1]));
                }
        }
        __syncthreads();
    }

    #pragma unroll
    for (int mt = 0; mt < 4; mt++) {
        #pragma unroll
        for (int nt = 0; nt < 4; nt++) {
            int row0 = m0 + warp_m * 64 + mt * 16 + gid;
            int col  = n0 + warp_n * 32 + nt * 8 + tig * 2;
            float2 v0, v1;
            v0.x = acc[mt][nt][0]; v0.y = acc[mt][nt][1];
            v1.x = acc[mt][nt][2]; v1.y = acc[mt][nt][3];
            *(float2*)(Cg + (size_t)row0 * ldc + col)       = v0;
            *(float2*)(Cg + (size_t)(row0 + 8) * ldc + col) = v1;
        }
    }
}

// ---- PV: tile 128x64, batched over (b,n). A=g_p3, B=g_v3, C=g_att -----------
__global__ __launch_bounds__(256, 2)
void pv_gemm() {
    __shared__ __align__(16) __nv_bfloat16 As[2][128*AST];
    __shared__ __align__(16) __nv_bfloat16 Bs[2][64*AST];
    int tid = threadIdx.x, wid = tid >> 5, lane = tid & 31;
    int warp_m = wid >> 1, warp_n = wid & 1;     // 4 x 2 warp grid
    int gid = lane >> 2, tig = lane & 3;
    int m0 = blockIdx.y * 128, bz = blockIdx.z;
    int b = bz >> 4, n = bz & 15;
    const int K3 = 3 * KL, NC = K3 >> 5;
    const __nv_bfloat16* Ag = g_p3 + ((size_t)bz * QL + m0) * K3;
    const __nv_bfloat16* Bg = g_v3 + (size_t)bz * DH * K3;
    uint32_t sA = smem_u32(As), sB = smem_u32(Bs);
    int lrow = tid >> 2, lseg = tid & 3;

    // prefetch tile 0
    #pragma unroll
    for (int i = 0; i < 2; i++) {
        int row = lrow + i * 64;
        uint32_t da = sA + (uint32_t)(row * AST + lseg * 8) * 2;
        const void* ga = Ag + (size_t)row * K3 + lseg * 8;
        asm volatile("cp.async.cg.shared.global [%0], [%1], 16;\n" :: "r"(da), "l"(ga));
    }
    {   // B: 64 rows x 4 segs = 256 threads exactly
        uint32_t db = sB + (uint32_t)(lrow * AST + lseg * 8) * 2;
        const void* gb = Bg + (size_t)lrow * K3 + lseg * 8;
        asm volatile("cp.async.cg.shared.global [%0], [%1], 16;\n" :: "r"(db), "l"(gb));
    }
    asm volatile("cp.async.commit_group;\n");

    float acc[2][4][4] = {};

    for (int c = 0; c < NC; c++) {
        int cur = c & 1;
        if (c + 1 < NC) {
            int nx = cur ^ 1, k0 = (c + 1) * 32;
            #pragma unroll
            for (int i = 0; i < 2; i++) {
                int row = lrow + i * 64;
                uint32_t da = sA + (uint32_t)(nx * 128*AST + row * AST + lseg * 8) * 2;
                const void* ga = Ag + (size_t)row * K3 + k0 + lseg * 8;
                asm volatile("cp.async.cg.shared.global [%0], [%1], 16;\n" :: "r"(da), "l"(ga));
            }
            {
                uint32_t db = sB + (uint32_t)(nx * 64*AST + lrow * AST + lseg * 8) * 2;
                const void* gb = Bg + (size_t)lrow * K3 + k0 + lseg * 8;
                asm volatile("cp.async.cg.shared.global [%0], [%1], 16;\n" :: "r"(db), "l"(gb));
            }
            asm volatile("cp.async.commit_group;\n");
            asm volatile("cp.async.wait_group 1;\n");
        } else {
            asm volatile("cp.async.wait_group 0;\n");
        }
        __syncthreads();

        const __nv_bfloat16* Ab = &As[cur][0];
        const __nv_bfloat16* Bb = &Bs[cur][0];
        #pragma unroll
        for (int ks = 0; ks < 2; ks++) {
            int kk = ks * 16;
            uint32_t a_frag[2][4];
            uint32_t b_frag[4][2];
            #pragma unroll
            for (int mt = 0; mt < 2; mt++) {
                int r0 = (warp_m * 32 + mt * 16 + gid) * AST + kk + tig * 2;
                a_frag[mt][0] = *(const uint32_t*)(Ab + r0);
                a_frag[mt][1] = *(const uint32_t*)(Ab + r0 + 8 * AST);
                a_frag[mt][2] = *(const uint32_t*)(Ab + r0 + 8);
                a_frag[mt][3] = *(const uint32_t*)(Ab + r0 + 8 * AST + 8);
            }
            #pragma unroll
            for (int nt = 0; nt < 4; nt++) {
                int rn = (warp_n * 32 + nt * 8 + gid) * AST + kk + tig * 2;
                b_frag[nt][0] = *(const uint32_t*)(Bb + rn);
                b_frag[nt][1] = *(const uint32_t*)(Bb + rn + 8);
            }
            #pragma unroll
            for (int mt = 0; mt < 2; mt++)
                #pragma unroll
                for (int nt = 0; nt < 4; nt++) {
                    asm volatile(
                        "mma.sync.aligned.m16n8k16.row.col.f32.bf16.bf16.f32 "
                        "{%0,%1,%2,%3}, {%4,%5,%6,%7}, {%8,%9}, {%0,%1,%2,%3};\n"
                        : "+f"(acc[mt][nt][0]), "+f"(acc[mt][nt][1]),
                          "+f"(acc[mt][nt][2]), "+f"(acc[mt][nt][3])
                        : "r"(a_frag[mt][0]), "r"(a_frag[mt][1]),
                          "r"(a_frag[mt][2]), "r"(a_frag[mt][3]),
                          "r"(b_frag[nt][0]), "r"(b_frag[nt][1]));
                }
        }
        __syncthreads();
    }

    // C: g_att[(i*BS + b)*DM + n*64 + col]
    float* Cb = g_att + (size_t)b * DM + n * DH;
    #pragma unroll
    for (int mt = 0; mt < 2; mt++) {
        #pragma unroll
        for (int nt = 0; nt < 4; nt++) {
            int row0 = m0 + warp_m * 32 + mt * 16 + gid;
            int col  = warp_n * 32 + nt * 8 + tig * 2;
            float2 v0, v1;
            v0.x = acc[mt][nt][0]; v0.y = acc[mt][nt][1];
            v1.x = acc[mt][nt][2]; v1.y = acc[mt][nt][3];
            *(float2*)(Cb + (size_t)row0 * (BS*DM) + col)       = v0;
            *(float2*)(Cb + (size_t)(row0 + 8) * (BS*DM) + col) = v1;
        }
    }
}

// ==================== fp32 -> bf16 triple-K conversions ======================
template<int MODE>  // 0: [h|l|h] (A)  1: [h|h|l] (B)
__global__ void split_rows_kernel(const float* __restrict__ X, __nv_bfloat16* __restrict__ Y,
                                  int kshift, long total) {
    long e = ((long)blockIdx.x * 256 + threadIdx.x) * 4;
    if (e >= total) return;
    int K = 1 << kshift;
    long r = e >> kshift; int c = (int)(e & (K - 1));
    float4 v = *(const float4*)(X + e);
    __nv_bfloat16 hx, hy, hz, hw, lx, ly, lz, lw;
    split1(v.x, hx, lx); split1(v.y, hy, ly); split1(v.z, hz, lz); split1(v.w, hw, lw);
    __nv_bfloat16* yb = Y + r * 3 * K;
    __nv_bfloat162 h01; h01.x = hx; h01.y = hy;
    __nv_bfloat162 h23; h23.x = hz; h23.y = hw;
    __nv_bfloat162 l01; l01.x = lx; l01.y = ly;
    __nv_bfloat162 l23; l23.x = lz; l23.y = lw;
    *(__nv_bfloat162*)(yb + c)     = h01; *(__nv_bfloat162*)(yb + c + 2)     = h23;
    if (MODE == 0) {
        *(__nv_bfloat162*)(yb + K + c)   = l01; *(__nv_bfloat162*)(yb + K + c + 2)   = l23;
        *(__nv_bfloat162*)(yb + 2*K + c) = h01; *(__nv_bfloat162*)(yb + 2*K + c + 2) = h23;
    } else {
        *(__nv_bfloat162*)(yb + K + c)   = h01; *(__nv_bfloat162*)(yb + K + c + 2)   = h23;
        *(__nv_bfloat162*)(yb + 2*K + c) = l01; *(__nv_bfloat162*)(yb + 2*K + c + 2) = l23;
    }
}

// W[K,N] -> Y[N,3K] = [h|h|l]
__global__ void split_tr_kernel(const float* __restrict__ W, __nv_bfloat16* __restrict__ Y,
                                int K, int N) {
    __shared__ float s[32][33];
    int n0 = blockIdx.x * 32, k0 = blockIdx.y * 32;
    int tx = threadIdx.x, ty = threadIdx.y;
    for (int i = ty; i < 32; i += 8)
        s[i][tx] = W[(size_t)(k0 + i) * N + n0 + tx];
    __syncthreads();
    for (int i = ty; i < 32; i += 8) {
        int n = n0 + i, k = k0 + tx;
        __nv_bfloat16 h, l; split1(s[tx][i], h, l);
        __nv_bfloat16* yb = Y + (size_t)n * 3 * K;
        yb[k] = h; yb[K + k] = h; yb[2*K + k] = l;
    }
}

// ---- attention operand prep -------------------------------------------------
// q3: (q + bias) -> [bn][i][192] A-layout
__global__ void q3_kernel(const float* __restrict__ bias, __nv_bfloat16* __restrict__ out) {
    int i = blockIdx.x, bn = blockIdx.y, b = bn >> 4, n = bn & 15, d = threadIdx.x;
    float v = g_q[((size_t)i * BS + b) * DM + n * DH + d] + bias[n * DH + d];
    __nv_bfloat16 h, l; split1(v, h, l);
    __nv_bfloat16* o = out + ((size_t)bn * QL + i) * 192;
    o[d] = h; o[64 + d] = l; o[128 + d] = h;
}
// k3: K -> [bn][j][192] B-layout
__global__ void k3_kernel() {
    int j = blockIdx.x, bn = blockIdx.y, b = bn >> 4, n = bn & 15, d = threadIdx.x;
    float v = g_kv[((size_t)j * BS + b) * (2*DM) + n * DH + d];
    __nv_bfloat16 h, l; split1(v, h, l);
    __nv_bfloat16* o = g_k3 + ((size_t)bn * KL + j) * 192;
    o[d] = h; o[64 + d] = h; o[128 + d] = l;
}
// rk3: r_k -> [n][j][192] B-layout
__global__ void rk3_kernel() {
    int j = blockIdx.x, n = blockIdx.y, d = threadIdx.x;
    float v = g_rk[(size_t)j * DM + n * DH + d];
    __nv_bfloat16 h, l; split1(v, h, l);
    __nv_bfloat16* o = g_rk3 + ((size_t)n * KL + j) * 192;
    o[d] = h; o[64 + d] = h; o[128 + d] = l;
}
// vt3: V^T -> [bn][d][3*KL] B-layout over KL (transpose via smem tile)
__global__ void vt3_kernel() {
    __shared__ float s[32][33];
    int j0 = blockIdx.x * 32, d0 = blockIdx.y * 32, bn = blockIdx.z;
    int b = bn >> 4, n = bn & 15;
    int tx = threadIdx.x, ty = threadIdx.y;
    for (int jj = ty; jj < 32; jj += 8)
        s[jj][tx] = g_kv[((size_t)(j0 + jj) * BS + b) * (2*DM) + DM + n * DH + d0 + tx];
    __syncthreads();
    for (int dd = ty; dd < 32; dd += 8) {
        __nv_bfloat16 h, l; split1(s[tx][dd], h, l);   // row j0+tx, dim d0+dd
        __nv_bfloat16* o = g_v3 + ((size_t)bn * DH + d0 + dd) * (3*KL) + j0 + tx;
        o[0] = h; o[KL] = h; o[2*KL] = l;
    }
}

// ==================== misc kernels ===========================================
__global__ void embed_kernel(const int* __restrict__ data, const float* __restrict__ embW) {
    int t = blockIdx.x;
    int tok = data[t];
    int c = threadIdx.x * 4;
    float4 v = *(const float4*)(embW + (size_t)tok * DM + c);
    *(float4*)(g_core + (size_t)t * DM + c) = v;
}

__global__ void pos_kernel() {
    int p = blockIdx.x;
    float ps = (float)(KL - 1 - p);
    for (int j = threadIdx.x; j < 512; j += 256) {
        float f = powf(10000.0f, -(float)j / 512.0f);
        float a = ps * f;
        g_posbuf[p * DM + j]       = sinf(a);
        g_posbuf[p * DM + 512 + j] = cosf(a);
    }
}

__global__ void concat_kernel(const float* __restrict__ mem_i) {
    int i = blockIdx.x * 256 + threadIdx.x;
    const int HALF = ML * BS * DM / 4;
    float4 v = (i < HALF) ? ((const float4*)mem_i)[i]
                          : ((const float4*)g_core)[i - HALF];
    ((float4*)g_xk)[i] = v;
}

__global__ void copyout_kernel(float* __restrict__ dst) {
    int i = blockIdx.x * 256 + threadIdx.x;
    ((float4*)dst)[i] = ((const float4*)g_core)[i];
}

__global__ void softmax_kernel() {
    int i = blockIdx.x, bn = blockIdx.y;
    const float* ac = &g_P[((size_t)bn * QL + i) * KL];
    const float* bd = &g_BD[((size_t)bn * QL + i) * KL];
    int tid = threadIdx.x;
    int lim = i + ML;
    float v[4]; float mx = -1e30f;
    #pragma unroll
    for (int r = 0; r < 4; r++) {
        int j = r * 256 + tid;
        float s = (j <= lim) ? ASCALE * (ac[j] + bd[j + QL - 1 - i]) : -1e30f;
        v[r] = s; mx = fmaxf(mx, s);
    }
    __shared__ float red[256];
    red[tid] = mx; __syncthreads();
    for (int st = 128; st > 0; st >>= 1) {
        if (tid < st) red[tid] = fmaxf(red[tid], red[tid + st]);
        __syncthreads();
    }
    mx = red[0]; __syncthreads();
    float sum = 0.f;
    #pragma unroll
    for (int r = 0; r < 4; r++) { v[r] = __expf(v[r] - mx); sum += v[r]; }
    red[tid] = sum; __syncthreads();
    for (int st = 128; st > 0; st >>= 1) {
        if (tid < st) red[tid] += red[tid + st];
        __syncthreads();
    }
    float inv = 1.0f / red[0];
    float* p = &g_P[((size_t)bn * QL + i) * KL];
    #pragma unroll
    for (int r = 0; r < 4; r++) p[r * 256 + tid] = v[r] * inv;
}

__global__ void add_ln_kernel(float* __restrict__ io, const float* __restrict__ add,
                              const float* __restrict__ g, const float* __restrict__ bt) {
    int t = blockIdx.x, tid = threadIdx.x;
    size_t base = (size_t)t * DM;
    float x[4]; float s = 0.f, sq = 0.f;
    #pragma unroll
    for (int r = 0; r < 4; r++) {
        int d = r * 256 + tid;
        float v = io[base + d] + add[base + d];
        x[r] = v; s += v; sq += v * v;
    }
    __shared__ float rs[256], rq[256];
    rs[tid] = s; rq[tid] = sq; __syncthreads();
    for (int st = 128; st > 0; st >>= 1) {
        if (tid < st) { rs[tid] += rs[tid + st]; rq[tid] += rq[tid + st]; }
        __syncthreads();
    }
    float mean = rs[0] * (1.0f / DM);
    float var  = rq[0] * (1.0f / DM) - mean * mean;
    float rstd = rsqrtf(var + 1e-5f);
    #pragma unroll
    for (int r = 0; r < 4; r++) {
        int d = r * 256 + tid;
        io[base + d] = (x[r] - mean) * rstd * g[d] + bt[d];
    }
}

__global__ void loss_kernel(const int* __restrict__ target, float* __restrict__ out) {
    int t = blockIdx.x, tid = threadIdx.x;
    const float* row = &g_logits[(size_t)t * NV];
    float mx = -1e30f;
    for (int j = tid; j < NV; j += 256) mx = fmaxf(mx, row[j]);
    __shared__ float red[256];
    red[tid] = mx; __syncthreads();
    for (int st = 128; st > 0; st >>= 1) {
        if (tid < st) red[tid] = fmaxf(red[tid], red[tid + st]);
        __syncthreads();
    }
    mx = red[0]; __syncthreads();
    float s = 0.f;
    for (int j = tid; j < NV; j += 256) s += __expf(row[j] - mx);
    red[tid] = s; __syncthreads();
    for (int st = 128; st > 0; st >>= 1) {
        if (tid < st) red[tid] += red[tid + st];
        __syncthreads();
    }
    if (tid == 0) {
        float lse = logf(red[0]) + mx;
        out[t] = lse - row[target[t]];
    }
}

// ==================== host orchestration =====================================
static void gemm3(const __nv_bfloat16* A3, const __nv_bfloat16* B3, float* C,
                  const float* bias, int M, int N, int K3, int epi) {
    dim3 grid(N / 128, M / 128);
    if (epi == 0)      tc_gemm<0><<<grid, 256>>>(A3, B3, C, bias, M, N, K3);
    else if (epi == 1) tc_gemm<1><<<grid, 256>>>(A3, B3, C, bias, M, N, K3);
    else               tc_gemm<2><<<grid, 256>>>(A3, B3, C, bias, M, N, K3);
}
static void split_rowsA(const float* X, __nv_bfloat16* Y, long R, int kshift) {
    long total = R << kshift;
    long blocks = (total / 4 + 255) / 256;
    split_rows_kernel<0><<<(int)blocks, 256>>>(X, Y, kshift, total);
}
static void split_rowsB(const float* X, __nv_bfloat16* Y, long R, int kshift) {
    long total = R << kshift;
    long blocks = (total / 4 + 255) / 256;
    split_rows_kernel<1><<<(int)blocks, 256>>>(X, Y, kshift, total);
}
static void split_tr(const float* W, __nv_bfloat16* Y, int K, int N) {
    split_tr_kernel<<<dim3(N / 32, K / 32), dim3(32, 8)>>>(W, Y, K, N);
}

extern "C" void kernel_launch(void* const* d_in, const int* in_sizes, int n_in,
                              void* d_out, int out_size) {
    const int*   data   = (const int*)d_in[0];
    const int*   target = (const int*)d_in[1];
    const float* memory = (const float*)d_in[2];
    const float* embW   = (const float*)d_in[3];
    const float* rwb    = (const float*)d_in[4];
    const float* rrb    = (const float*)d_in[5];
    const float* Wq     = (const float*)d_in[6];
    const float* Wkv    = (const float*)d_in[7];
    const float* Wr     = (const float*)d_in[8];
    const float* Wo     = (const float*)d_in[9];
    const float* W1     = (const float*)d_in[10];
    const float* b1     = (const float*)d_in[11];
    const float* W2     = (const float*)d_in[12];
    const float* b2     = (const float*)d_in[13];
    const float* ln1g   = (const float*)d_in[14];
    const float* ln1b   = (const float*)d_in[15];
    const float* ln2g   = (const float*)d_in[16];
    const float* ln2b   = (const float*)d_in[17];

    float* out = (float*)d_out;
    const long SLAB = (long)ML * BS * DM;
    float* out_mems = (out_size >= 4096L + NLAY * SLAB) ? out + 4096 : nullptr;

    float *p_core, *p_q, *p_kv, *p_pos, *p_rk, *p_att, *p_tmp, *p_ff, *p_xk, *p_logits;
    float *p_P, *p_BD;
    __nv_bfloat16 *p_a3, *p_w3, *p_emb3, *p_pos3, *p_q3a, *p_q3b, *p_k3, *p_rk3, *p_p3;
    cudaGetSymbolAddress((void**)&p_core,   g_core);
    cudaGetSymbolAddress((void**)&p_xk,     g_xk);
    cudaGetSymbolAddress((void**)&p_q,      g_q);
    cudaGetSymbolAddress((void**)&p_kv,     g_kv);
    cudaGetSymbolAddress((void**)&p_pos,    g_posbuf);
    cudaGetSymbolAddress((void**)&p_rk,     g_rk);
    cudaGetSymbolAddress((void**)&p_att,    g_att);
    cudaGetSymbolAddress((void**)&p_tmp,    g_tmp);
    cudaGetSymbolAddress((void**)&p_ff,     g_ff);
    cudaGetSymbolAddress((void**)&p_logits, g_logits);
    cudaGetSymbolAddress((void**)&p_P,      g_P);
    cudaGetSymbolAddress((void**)&p_BD,     g_BD);
    cudaGetSymbolAddress((void**)&p_a3,     g_a3);
    cudaGetSymbolAddress((void**)&p_w3,     g_w3);
    cudaGetSymbolAddress((void**)&p_emb3,   g_emb3);
    cudaGetSymbolAddress((void**)&p_pos3,   g_pos3);
    cudaGetSymbolAddress((void**)&p_q3a,    g_q3a);
    cudaGetSymbolAddress((void**)&p_q3b,    g_q3b);
    cudaGetSymbolAddress((void**)&p_k3,     g_k3);
    cudaGetSymbolAddress((void**)&p_rk3,    g_rk3);
    cudaGetSymbolAddress((void**)&p_p3,     g_p3);

    embed_kernel<<<NQ, 256>>>(data, embW);
    pos_kernel<<<KL, 256>>>();
    split_rowsA(p_pos, p_pos3, KL, 10);
    split_rowsB(embW, p_emb3, NV, 10);

    for (int L = 0; L < NLAY; L++) {
        if (out_mems)
            copyout_kernel<<<4096, 256>>>(out_mems + (long)L * SLAB);
        concat_kernel<<<8192, 256>>>(memory + (long)L * SLAB);

        // q = core @ Wq ; kv = xk @ Wkv ; rk = pos @ Wr
        split_rowsA(p_core, p_a3, NQ, 10);
        split_tr(Wq + (long)L*DM*DM, p_w3, DM, DM);
        gemm3(p_a3, p_w3, p_q, nullptr, NQ, DM, 3*DM, 0);
        split_rowsA(p_xk, p_a3, NK, 10);
        split_tr(Wkv + (long)L*DM*2*DM, p_w3, DM, 2*DM);
        gemm3(p_a3, p_w3, p_kv, nullptr, NK, 2*DM, 3*DM, 0);
        split_tr(Wr + (long)L*DM*DM, p_w3, DM, DM);
        gemm3(p_pos3, p_w3, p_rk, nullptr, KL, DM, 3*DM, 0);

        // attention operand prep (bf16x3)
        q3_kernel<<<dim3(QL, 128), 64>>>(rwb, p_q3a);
        q3_kernel<<<dim3(QL, 128), 64>>>(rrb, p_q3b);
        k3_kernel<<<dim3(KL, 128), 64>>>();
        rk3_kernel<<<dim3(KL, NH), 64>>>();
        vt3_kernel<<<dim3(KL/32, DH/32, 128), dim3(32, 8)>>>();

        // AC = Q'a K^T  (per bn)
        tc_gemm_bat<<<dim3(KL/128, QL/128, 128), 256>>>(
            p_q3a, (long)QL*192, p_k3, (long)KL*192, 127,
            p_P, (long)QL*KL, KL, KL, 192);
        // BD_raw = Q'b rk^T  (per bn; rk shared across b -> bmask=15)
        tc_gemm_bat<<<dim3(KL/128, QL/128, 128), 256>>>(
            p_q3b, (long)QL*192, p_rk3, (long)KL*192, 15,
            p_BD, (long)QL*KL, KL, KL, 192);

        softmax_kernel<<<dim3(QL, 128), 256>>>();

        // P -> bf16x3, then PV
        split_rowsA(p_P, p_p3, (long)128*QL, 10);
        pv_gemm<<<dim3(1, QL/128, 128), 256>>>();

        // attn_out = att @ Wo ; LN ; FF ; LN
        split_rowsA(p_att, p_a3, NQ, 10);
        split_tr(Wo + (long)L*DM*DM, p_w3, DM, DM);
        gemm3(p_a3, p_w3, p_tmp, nullptr, NQ, DM, 3*DM, 0);
        add_ln_kernel<<<NQ, 256>>>(p_core, p_tmp, ln1g + L*DM, ln1b + L*DM);

        split_rowsA(p_core, p_a3, NQ, 10);
        split_tr(W1 + (long)L*DM*DI, p_w3, DM, DI);
        gemm3(p_a3, p_w3, p_ff, b1 + L*DI, NQ, DI, 3*DM, 2);
        split_rowsA(p_ff, p_a3, NQ, 12);
        split_tr(W2 + (long)L*DI*DM, p_w3, DI, DM);
        gemm3(p_a3, p_w3, p_tmp, b2 + L*DM, NQ, DM, 3*DI, 1);
        add_ln_kernel<<<NQ, 256>>>(p_core, p_tmp, ln2g + L*DM, ln2b + L*DM);
    }

    // logits = core @ embW^T ; loss
    split_rowsA(p_core, p_a3, NQ, 10);
    gemm3(p_a3, p_emb3, p_logits, nullptr, NQ, NV, 3*DM, 0);
    loss_kernel<<<NQ, 256>>>(target, out);
}

// round 12
// speedup vs baseline: 1.7731x; 1.0643x over previous
#include <cuda_runtime.h>
#include <cuda_bf16.h>
#include <math.h>
#include <stdint.h>

#define QL 512
#define ML 512
#define KL 1024
#define BS 8
#define NH 16
#define DH 64
#define DM 1024
#define DI 4096
#define NV 32000
#define NLAY 6
#define NQ (QL*BS)
#define NK (KL*BS)
#define ASCALE 0.125f

// ---------------- persistent scratch ----------------------------------------
static __device__ float g_core[NQ*DM];
static __device__ float g_q[NQ*DM];
static __device__ float g_kv[(size_t)NK*2*DM];
static __device__ float g_posbuf[KL*DM];
static __device__ float g_rk[KL*DM];
static __device__ float g_P[(size_t)BS*NH*QL*KL];
static __device__ float g_BD[(size_t)BS*NH*QL*KL];
static __device__ float g_tmp[NQ*DM];
static __device__ float g_logits[(size_t)NQ*NV];
// bf16 triple-K operand buffers
static __device__ __nv_bfloat16 g_a3[(size_t)NQ*3*DI];       // xk3 / att3 / ff3 (time-shared)
static __device__ __nv_bfloat16 g_core3[(size_t)NQ*3*DM];    // core, A-layout (maintained)
static __device__ __nv_bfloat16 g_w3[(size_t)DI*3*DM];       // weights, B-layout
static __device__ __nv_bfloat16 g_emb3[(size_t)NV*3*DM];     // emb, B-layout [h|h|l]
static __device__ __nv_bfloat16 g_pos3[(size_t)KL*3*DM];
// attention operands
static __device__ __nv_bfloat16 g_q3a[(size_t)BS*NH*QL*192];
static __device__ __nv_bfloat16 g_q3b[(size_t)BS*NH*QL*192];
static __device__ __nv_bfloat16 g_k3 [(size_t)BS*NH*KL*192];
static __device__ __nv_bfloat16 g_rk3[(size_t)NH*KL*192];
static __device__ __nv_bfloat16 g_v3 [(size_t)BS*NH*DH*3*KL];
static __device__ __nv_bfloat16 g_p3 [(size_t)BS*NH*QL*3*KL];

__device__ __forceinline__ uint32_t smem_u32(const void* p) {
    uint32_t a;
    asm("{ .reg .u64 t; cvta.to.shared.u64 t, %1; cvt.u32.u64 %0, t; }" : "=r"(a) : "l"(p));
    return a;
}
__device__ __forceinline__ void split1(float v, __nv_bfloat16& h, __nv_bfloat16& l) {
    h = __float2bfloat16(v);
    l = __float2bfloat16(v - __bfloat162float(h));
}

#define MMA_BF16(acc, af, bf) \
    asm volatile("mma.sync.aligned.m16n8k16.row.col.f32.bf16.bf16.f32 " \
        "{%0,%1,%2,%3}, {%4,%5,%6,%7}, {%8,%9}, {%0,%1,%2,%3};\n" \
        : "+f"((acc)[0]), "+f"((acc)[1]), "+f"((acc)[2]), "+f"((acc)[3]) \
        : "r"((af)[0]), "r"((af)[1]), "r"((af)[2]), "r"((af)[3]), \
          "r"((bf)[0]), "r"((bf)[1]))

#define AST 40
#define TILE_ELEMS (128*AST)

// shared 128x128 mainloop body (computes acc from Ag/Bg)
#define GEMM_MAINLOOP()                                                        \
    uint32_t sA = smem_u32(As), sB = smem_u32(Bs);                             \
    int lrow = tid >> 2, lseg = tid & 3;                                       \
    _Pragma("unroll")                                                          \
    for (int i = 0; i < 2; i++) {                                              \
        int row = lrow + i * 64;                                               \
        uint32_t da = sA + (uint32_t)(row * AST + lseg * 8) * 2;               \
        uint32_t db = sB + (uint32_t)(row * AST + lseg * 8) * 2;               \
        const void* ga = Ag + (size_t)row * K3 + lseg * 8;                     \
        const void* gb = Bg + (size_t)row * K3 + lseg * 8;                     \
        asm volatile("cp.async.cg.shared.global [%0], [%1], 16;\n" :: "r"(da), "l"(ga)); \
        asm volatile("cp.async.cg.shared.global [%0], [%1], 16;\n" :: "r"(db), "l"(gb)); \
    }                                                                          \
    asm volatile("cp.async.commit_group;\n");                                  \
    for (int c = 0; c < NC; c++) {                                             \
        int cur = c & 1;                                                       \
        if (c + 1 < NC) {                                                      \
            int nx = cur ^ 1, k0 = (c + 1) * 32;                               \
            _Pragma("unroll")                                                  \
            for (int i = 0; i < 2; i++) {                                      \
                int row = lrow + i * 64;                                       \
                uint32_t da = sA + (uint32_t)(nx * TILE_ELEMS + row * AST + lseg * 8) * 2; \
                uint32_t db = sB + (uint32_t)(nx * TILE_ELEMS + row * AST + lseg * 8) * 2; \
                const void* ga = Ag + (size_t)row * K3 + k0 + lseg * 8;        \
                const void* gb = Bg + (size_t)row * K3 + k0 + lseg * 8;        \
                asm volatile("cp.async.cg.shared.global [%0], [%1], 16;\n" :: "r"(da), "l"(ga)); \
                asm volatile("cp.async.cg.shared.global [%0], [%1], 16;\n" :: "r"(db), "l"(gb)); \
            }                                                                  \
            asm volatile("cp.async.commit_group;\n");                          \
            asm volatile("cp.async.wait_group 1;\n");                          \
        } else {                                                               \
            asm volatile("cp.async.wait_group 0;\n");                          \
        }                                                                      \
        __syncthreads();                                                       \
        const __nv_bfloat16* Ab = &As[cur][0];                                 \
        const __nv_bfloat16* Bb = &Bs[cur][0];                                 \
        _Pragma("unroll")                                                      \
        for (int ks = 0; ks < 2; ks++) {                                       \
            int kk = ks * 16;                                                  \
            uint32_t a_frag[4][4];                                             \
            uint32_t b_frag[4][2];                                             \
            _Pragma("unroll")                                                  \
            for (int mt = 0; mt < 4; mt++) {                                   \
                int r0 = (warp_m * 64 + mt * 16 + gid) * AST + kk + tig * 2;   \
                a_frag[mt][0] = *(const uint32_t*)(Ab + r0);                   \
                a_frag[mt][1] = *(const uint32_t*)(Ab + r0 + 8 * AST);         \
                a_frag[mt][2] = *(const uint32_t*)(Ab + r0 + 8);               \
                a_frag[mt][3] = *(const uint32_t*)(Ab + r0 + 8 * AST + 8);     \
            }                                                                  \
            _Pragma("unroll")                                                  \
            for (int nt = 0; nt < 4; nt++) {                                   \
                int rn = (warp_n * 32 + nt * 8 + gid) * AST + kk + tig * 2;    \
                b_frag[nt][0] = *(const uint32_t*)(Bb + rn);                   \
                b_frag[nt][1] = *(const uint32_t*)(Bb + rn + 8);               \
            }                                                                  \
            _Pragma("unroll")                                                  \
            for (int mt = 0; mt < 4; mt++)                                     \
                _Pragma("unroll")                                              \
                for (int nt = 0; nt < 4; nt++)                                 \
                    MMA_BF16(acc[mt][nt], a_frag[mt], b_frag[nt]);             \
        }                                                                      \
        __syncthreads();                                                       \
    }

// ---- generic GEMM, fp32 C, optional bias ------------------------------------
template<int EPI>   // 0 none, 1 +bias
__global__ __launch_bounds__(256, 2)
void tc_gemm(const __nv_bfloat16* __restrict__ A3, const __nv_bfloat16* __restrict__ B3,
             float* __restrict__ C, const float* __restrict__ bias,
             int M, int N, int K3) {
    __shared__ __align__(16) __nv_bfloat16 As[2][TILE_ELEMS];
    __shared__ __align__(16) __nv_bfloat16 Bs[2][TILE_ELEMS];
    int tid = threadIdx.x, wid = tid >> 5, lane = tid & 31;
    int warp_m = wid >> 2, warp_n = wid & 3;
    int gid = lane >> 2, tig = lane & 3;
    int n0 = blockIdx.x * 128, m0 = blockIdx.y * 128;
    const __nv_bfloat16* Ag = A3 + (size_t)m0 * K3;
    const __nv_bfloat16* Bg = B3 + (size_t)n0 * K3;
    int NC = K3 >> 5;
    float acc[4][4][4] = {};
    GEMM_MAINLOOP()
    #pragma unroll
    for (int mt = 0; mt < 4; mt++)
        #pragma unroll
        for (int nt = 0; nt < 4; nt++) {
            int row0 = m0 + warp_m * 64 + mt * 16 + gid;
            int col  = n0 + warp_n * 32 + nt * 8 + tig * 2;
            float2 v0, v1;
            v0.x = acc[mt][nt][0]; v0.y = acc[mt][nt][1];
            v1.x = acc[mt][nt][2]; v1.y = acc[mt][nt][3];
            if (EPI >= 1) {
                float bx = bias[col], by = bias[col + 1];
                v0.x += bx; v0.y += by; v1.x += bx; v1.y += by;
            }
            *(float2*)(C + (size_t)row0 * N + col)       = v0;
            *(float2*)(C + (size_t)(row0 + 8) * N + col) = v1;
        }
}

// ---- W1 GEMM: relu(x+bias) -> bf16x3 A-layout directly ----------------------
__global__ __launch_bounds__(256, 2)
void tc_gemm_relu3(const __nv_bfloat16* __restrict__ A3, const __nv_bfloat16* __restrict__ B3,
                   __nv_bfloat16* __restrict__ Cb, const float* __restrict__ bias,
                   int M, int N, int K3) {
    __shared__ __align__(16) __nv_bfloat16 As[2][TILE_ELEMS];
    __shared__ __align__(16) __nv_bfloat16 Bs[2][TILE_ELEMS];
    int tid = threadIdx.x, wid = tid >> 5, lane = tid & 31;
    int warp_m = wid >> 2, warp_n = wid & 3;
    int gid = lane >> 2, tig = lane & 3;
    int n0 = blockIdx.x * 128, m0 = blockIdx.y * 128;
    const __nv_bfloat16* Ag = A3 + (size_t)m0 * K3;
    const __nv_bfloat16* Bg = B3 + (size_t)n0 * K3;
    int NC = K3 >> 5;
    float acc[4][4][4] = {};
    GEMM_MAINLOOP()
    #pragma unroll
    for (int mt = 0; mt < 4; mt++)
        #pragma unroll
        for (int nt = 0; nt < 4; nt++) {
            int row0 = m0 + warp_m * 64 + mt * 16 + gid;
            int col  = n0 + warp_n * 32 + nt * 8 + tig * 2;
            float bx = bias[col], by = bias[col + 1];
            #pragma unroll
            for (int half = 0; half < 2; half++) {
                float vx = fmaxf(acc[mt][nt][half*2+0] + bx, 0.f);
                float vy = fmaxf(acc[mt][nt][half*2+1] + by, 0.f);
                __nv_bfloat16 hx, lx, hy, ly;
                split1(vx, hx, lx); split1(vy, hy, ly);
                __nv_bfloat162 hh; hh.x = hx; hh.y = hy;
                __nv_bfloat162 ll; ll.x = lx; ll.y = ly;
                __nv_bfloat16* r = Cb + (size_t)(row0 + half*8) * (3*N) + col;
                *(__nv_bfloat162*)(r)         = hh;
                *(__nv_bfloat162*)(r + N)     = ll;
                *(__nv_bfloat162*)(r + 2*N)   = hh;
            }
        }
}

// ---- batched AC/BD scores; skip_mode 1=AC causal skip, 2=BD relshift skip ---
__global__ __launch_bounds__(256, 2)
void tc_gemm_bat(const __nv_bfloat16* __restrict__ A3, long strideA,
                 const __nv_bfloat16* __restrict__ B3, long strideB, int bmask,
                 float* __restrict__ C, long strideC, int ldc,
                 int K3, int skip_mode) {
    int n0 = blockIdx.x * 128, m0 = blockIdx.y * 128, bz = blockIdx.z;
    if (skip_mode == 1 && n0 >= m0 + 640) return;      // AC: fully masked
    if (skip_mode == 2 && n0 + m0 <= 256) return;      // BD: never read
    __shared__ __align__(16) __nv_bfloat16 As[2][TILE_ELEMS];
    __shared__ __align__(16) __nv_bfloat16 Bs[2][TILE_ELEMS];
    int tid = threadIdx.x, wid = tid >> 5, lane = tid & 31;
    int warp_m = wid >> 2, warp_n = wid & 3;
    int gid = lane >> 2, tig = lane & 3;
    const __nv_bfloat16* Ag = A3 + (size_t)bz * strideA + (size_t)m0 * K3;
    const __nv_bfloat16* Bg = B3 + (size_t)(bz & bmask) * strideB + (size_t)n0 * K3;
    float* Cg = C + (size_t)bz * strideC;
    int NC = K3 >> 5;
    float acc[4][4][4] = {};
    GEMM_MAINLOOP()
    #pragma unroll
    for (int mt = 0; mt < 4; mt++)
        #pragma unroll
        for (int nt = 0; nt < 4; nt++) {
            int row0 = m0 + warp_m * 64 + mt * 16 + gid;
            int col  = n0 + warp_n * 32 + nt * 8 + tig * 2;
            float2 v0, v1;
            v0.x = acc[mt][nt][0]; v0.y = acc[mt][nt][1];
            v1.x = acc[mt][nt][2]; v1.y = acc[mt][nt][3];
            *(float2*)(Cg + (size_t)row0 * ldc + col)       = v0;
            *(float2*)(Cg + (size_t)(row0 + 8) * ldc + col) = v1;
        }
}

// ---- PV: 128x64 per (b,n); writes att3 bf16x3 into g_a3 ---------------------
__global__ __launch_bounds__(256, 2)
void pv_gemm() {
    __shared__ __align__(16) __nv_bfloat16 As[2][128*AST];
    __shared__ __align__(16) __nv_bfloat16 Bs[2][64*AST];
    int tid = threadIdx.x, wid = tid >> 5, lane = tid & 31;
    int warp_m = wid >> 1, warp_n = wid & 1;
    int gid = lane >> 2, tig = lane & 3;
    int m0 = blockIdx.y * 128, bz = blockIdx.z;
    int b = bz >> 4, n = bz & 15;
    const int K3 = 3 * KL, NC = K3 >> 5;
    const __nv_bfloat16* Ag = g_p3 + ((size_t)bz * QL + m0) * K3;
    const __nv_bfloat16* Bg = g_v3 + (size_t)bz * DH * K3;
    uint32_t sA = smem_u32(As), sB = smem_u32(Bs);
    int lrow = tid >> 2, lseg = tid & 3;

    #pragma unroll
    for (int i = 0; i < 2; i++) {
        int row = lrow + i * 64;
        uint32_t da = sA + (uint32_t)(row * AST + lseg * 8) * 2;
        const void* ga = Ag + (size_t)row * K3 + lseg * 8;
        asm volatile("cp.async.cg.shared.global [%0], [%1], 16;\n" :: "r"(da), "l"(ga));
    }
    {
        uint32_t db = sB + (uint32_t)(lrow * AST + lseg * 8) * 2;
        const void* gb = Bg + (size_t)lrow * K3 + lseg * 8;
        asm volatile("cp.async.cg.shared.global [%0], [%1], 16;\n" :: "r"(db), "l"(gb));
    }
    asm volatile("cp.async.commit_group;\n");

    float acc[2][4][4] = {};

    for (int c = 0; c < NC; c++) {
        int cur = c & 1;
        if (c + 1 < NC) {
            int nx = cur ^ 1, k0 = (c + 1) * 32;
            #pragma unroll
            for (int i = 0; i < 2; i++) {
                int row = lrow + i * 64;
                uint32_t da = sA + (uint32_t)(nx * 128*AST + row * AST + lseg * 8) * 2;
                const void* ga = Ag + (size_t)row * K3 + k0 + lseg * 8;
                asm volatile("cp.async.cg.shared.global [%0], [%1], 16;\n" :: "r"(da), "l"(ga));
            }
            {
                uint32_t db = sB + (uint32_t)(nx * 64*AST + lrow * AST + lseg * 8) * 2;
                const void* gb = Bg + (size_t)lrow * K3 + k0 + lseg * 8;
                asm volatile("cp.async.cg.shared.global [%0], [%1], 16;\n" :: "r"(db), "l"(gb));
            }
            asm volatile("cp.async.commit_group;\n");
            asm volatile("cp.async.wait_group 1;\n");
        } else {
            asm volatile("cp.async.wait_group 0;\n");
        }
        __syncthreads();

        const __nv_bfloat16* Ab = &As[cur][0];
        const __nv_bfloat16* Bb = &Bs[cur][0];
        #pragma unroll
        for (int ks = 0; ks < 2; ks++) {
            int kk = ks * 16;
            uint32_t a_frag[2][4];
            uint32_t b_frag[4][2];
            #pragma unroll
            for (int mt = 0; mt < 2; mt++) {
                int r0 = (warp_m * 32 + mt * 16 + gid) * AST + kk + tig * 2;
                a_frag[mt][0] = *(const uint32_t*)(Ab + r0);
                a_frag[mt][1] = *(const uint32_t*)(Ab + r0 + 8 * AST);
                a_frag[mt][2] = *(const uint32_t*)(Ab + r0 + 8);
                a_frag[mt][3] = *(const uint32_t*)(Ab + r0 + 8 * AST + 8);
            }
            #pragma unroll
            for (int nt = 0; nt < 4; nt++) {
                int rn = (warp_n * 32 + nt * 8 + gid) * AST + kk + tig * 2;
                b_frag[nt][0] = *(const uint32_t*)(Bb + rn);
                b_frag[nt][1] = *(const uint32_t*)(Bb + rn + 8);
            }
            #pragma unroll
            for (int mt = 0; mt < 2; mt++)
                #pragma unroll
                for (int nt = 0; nt < 4; nt++)
                    MMA_BF16(acc[mt][nt], a_frag[mt], b_frag[nt]);
        }
        __syncthreads();
    }

    // att3 (A-layout over DM): g_a3[(i*BS+b)*3072 + {0,1024,2048} + n*64 + col]
    #pragma unroll
    for (int mt = 0; mt < 2; mt++)
        #pragma unroll
        for (int nt = 0; nt < 4; nt++) {
            int i0r = m0 + warp_m * 32 + mt * 16 + gid;
            int col = warp_n * 32 + nt * 8 + tig * 2;
            #pragma unroll
            for (int half = 0; half < 2; half++) {
                int i = i0r + half * 8;
                float vx = acc[mt][nt][half*2+0], vy = acc[mt][nt][half*2+1];
                __nv_bfloat16 hx, lx, hy, ly;
                split1(vx, hx, lx); split1(vy, hy, ly);
                __nv_bfloat162 hh; hh.x = hx; hh.y = hy;
                __nv_bfloat162 ll; ll.x = lx; ll.y = ly;
                __nv_bfloat16* r = g_a3 + (size_t)(i * BS + b) * (3*DM) + n * DH + col;
                *(__nv_bfloat162*)(r)          = hh;
                *(__nv_bfloat162*)(r + DM)     = ll;
                *(__nv_bfloat162*)(r + 2*DM)   = hh;
            }
        }
}

// ==================== conversions / prep =====================================
template<int MODE>  // 0: [h|l|h] (A)   1: [h|h|l] (B)
__global__ void split_rows_kernel(const float* __restrict__ X, __nv_bfloat16* __restrict__ Y,
                                  int kshift, long total) {
    long e = ((long)blockIdx.x * 256 + threadIdx.x) * 4;
    if (e >= total) return;
    int K = 1 << kshift;
    long r = e >> kshift; int c = (int)(e & (K - 1));
    float4 v = *(const float4*)(X + e);
    __nv_bfloat16 hx, hy, hz, hw, lx, ly, lz, lw;
    split1(v.x, hx, lx); split1(v.y, hy, ly); split1(v.z, hz, lz); split1(v.w, hw, lw);
    __nv_bfloat16* yb = Y + r * 3 * K;
    __nv_bfloat162 h01; h01.x = hx; h01.y = hy;
    __nv_bfloat162 h23; h23.x = hz; h23.y = hw;
    __nv_bfloat162 l01; l01.x = lx; l01.y = ly;
    __nv_bfloat162 l23; l23.x = lz; l23.y = lw;
    *(__nv_bfloat162*)(yb + c)       = h01; *(__nv_bfloat162*)(yb + c + 2)       = h23;
    if (MODE == 0) {
        *(__nv_bfloat162*)(yb + K + c)   = l01; *(__nv_bfloat162*)(yb + K + c + 2)   = l23;
        *(__nv_bfloat162*)(yb + 2*K + c) = h01; *(__nv_bfloat162*)(yb + 2*K + c + 2) = h23;
    } else {
        *(__nv_bfloat162*)(yb + K + c)   = h01; *(__nv_bfloat162*)(yb + K + c + 2)   = h23;
        *(__nv_bfloat162*)(yb + 2*K + c) = l01; *(__nv_bfloat162*)(yb + 2*K + c + 2) = l23;
    }
}

// W[K,N] -> Y[N,3K] = [h|h|l]
__global__ void split_tr_kernel(const float* __restrict__ W, __nv_bfloat16* __restrict__ Y,
                                int K, int N) {
    __shared__ float s[32][33];
    int n0 = blockIdx.x * 32, k0 = blockIdx.y * 32;
    int tx = threadIdx.x, ty = threadIdx.y;
    for (int i = ty; i < 32; i += 8)
        s[i][tx] = W[(size_t)(k0 + i) * N + n0 + tx];
    __syncthreads();
    for (int i = ty; i < 32; i += 8) {
        int n = n0 + i, k = k0 + tx;
        __nv_bfloat16 h, l; split1(s[tx][i], h, l);
        __nv_bfloat16* yb = Y + (size_t)n * 3 * K;
        yb[k] = h; yb[K + k] = h; yb[2*K + k] = l;
    }
}

// q3: (q + rwb/rrb) -> both A-layouts at once
__global__ void q3_kernel(const float* __restrict__ rwb, const float* __restrict__ rrb) {
    int i = blockIdx.x, bn = blockIdx.y, b = bn >> 4, n = bn & 15, d = threadIdx.x;
    float qv = g_q[((size_t)i * BS + b) * DM + n * DH + d];
    float va = qv + rwb[n * DH + d];
    float vb = qv + rrb[n * DH + d];
    __nv_bfloat16 h, l;
    split1(va, h, l);
    __nv_bfloat16* oa = g_q3a + ((size_t)bn * QL + i) * 192;
    oa[d] = h; oa[64 + d] = l; oa[128 + d] = h;
    split1(vb, h, l);
    __nv_bfloat16* ob = g_q3b + ((size_t)bn * QL + i) * 192;
    ob[d] = h; ob[64 + d] = l; ob[128 + d] = h;
}
__global__ void k3_kernel() {
    int j = blockIdx.x, bn = blockIdx.y, b = bn >> 4, n = bn & 15, d = threadIdx.x;
    float v = g_kv[((size_t)j * BS + b) * (2*DM) + n * DH + d];
    __nv_bfloat16 h, l; split1(v, h, l);
    __nv_bfloat16* o = g_k3 + ((size_t)bn * KL + j) * 192;
    o[d] = h; o[64 + d] = h; o[128 + d] = l;
}
__global__ void rk3_kernel() {
    int j = blockIdx.x, n = blockIdx.y, d = threadIdx.x;
    float v = g_rk[(size_t)j * DM + n * DH + d];
    __nv_bfloat16 h, l; split1(v, h, l);
    __nv_bfloat16* o = g_rk3 + ((size_t)n * KL + j) * 192;
    o[d] = h; o[64 + d] = h; o[128 + d] = l;
}
__global__ void vt3_kernel() {
    __shared__ float s[32][33];
    int j0 = blockIdx.x * 32, d0 = blockIdx.y * 32, bn = blockIdx.z;
    int b = bn >> 4, n = bn & 15;
    int tx = threadIdx.x, ty = threadIdx.y;
    for (int jj = ty; jj < 32; jj += 8)
        s[jj][tx] = g_kv[((size_t)(j0 + jj) * BS + b) * (2*DM) + DM + n * DH + d0 + tx];
    __syncthreads();
    for (int dd = ty; dd < 32; dd += 8) {
        __nv_bfloat16 h, l; split1(s[tx][dd], h, l);
        __nv_bfloat16* o = g_v3 + ((size_t)bn * DH + d0 + dd) * (3*KL) + j0 + tx;
        o[0] = h; o[KL] = h; o[2*KL] = l;
    }
}

// ==================== misc kernels ===========================================
__global__ void embed_kernel(const int* __restrict__ data, const float* __restrict__ embW) {
    int t = blockIdx.x;
    int tok = data[t];
    int c = threadIdx.x * 4;
    float4 v = *(const float4*)(embW + (size_t)tok * DM + c);
    *(float4*)(g_core + (size_t)t * DM + c) = v;
    __nv_bfloat16 hx, hy, hz, hw, lx, ly, lz, lw;
    split1(v.x, hx, lx); split1(v.y, hy, ly); split1(v.z, hz, lz); split1(v.w, hw, lw);
    __nv_bfloat16* yb = g_core3 + (size_t)t * (3*DM);
    __nv_bfloat162 h01; h01.x = hx; h01.y = hy;
    __nv_bfloat162 h23; h23.x = hz; h23.y = hw;
    __nv_bfloat162 l01; l01.x = lx; l01.y = ly;
    __nv_bfloat162 l23; l23.x = lz; l23.y = lw;
    *(__nv_bfloat162*)(yb + c)        = h01; *(__nv_bfloat162*)(yb + c + 2)        = h23;
    *(__nv_bfloat162*)(yb + DM + c)   = l01; *(__nv_bfloat162*)(yb + DM + c + 2)   = l23;
    *(__nv_bfloat162*)(yb + 2*DM + c) = h01; *(__nv_bfloat162*)(yb + 2*DM + c + 2) = h23;
}

__global__ void pos_kernel() {
    int p = blockIdx.x;
    float ps = (float)(KL - 1 - p);
    for (int j = threadIdx.x; j < 512; j += 256) {
        float f = powf(10000.0f, -(float)j / 512.0f);
        float a = ps * f;
        g_posbuf[p * DM + j]       = sinf(a);
        g_posbuf[p * DM + 512 + j] = cosf(a);
    }
}

// concat [mem_i ; core] -> xk3 (bf16x3 A-layout) directly into g_a3
__global__ void concat3_kernel(const float* __restrict__ mem_i) {
    long e = ((long)blockIdx.x * 256 + threadIdx.x) * 4;   // over NK*DM
    long r = e >> 10; int c = (int)(e & 1023);
    float4 v;
    if (r < ML * BS) v = *(const float4*)(mem_i + e);
    else             v = *(const float4*)(g_core + (r - ML*BS) * (long)DM + c);
    __nv_bfloat16 hx, hy, hz, hw, lx, ly, lz, lw;
    split1(v.x, hx, lx); split1(v.y, hy, ly); split1(v.z, hz, lz); split1(v.w, hw, lw);
    __nv_bfloat16* yb = g_a3 + r * (3*DM);
    __nv_bfloat162 h01; h01.x = hx; h01.y = hy;
    __nv_bfloat162 h23; h23.x = hz; h23.y = hw;
    __nv_bfloat162 l01; l01.x = lx; l01.y = ly;
    __nv_bfloat162 l23; l23.x = lz; l23.y = lw;
    *(__nv_bfloat162*)(yb + c)        = h01; *(__nv_bfloat162*)(yb + c + 2)        = h23;
    *(__nv_bfloat162*)(yb + DM + c)   = l01; *(__nv_bfloat162*)(yb + DM + c + 2)   = l23;
    *(__nv_bfloat162*)(yb + 2*DM + c) = h01; *(__nv_bfloat162*)(yb + 2*DM + c + 2) = h23;
}

__global__ void copyout_kernel(float* __restrict__ dst) {
    int i = blockIdx.x * 256 + threadIdx.x;
    ((float4*)dst)[i] = ((const float4*)g_core)[i];
}

// combine + rel-shift + mask + softmax -> p3 (bf16x3) directly
__global__ void softmax_kernel() {
    int i = blockIdx.x, bn = blockIdx.y;
    const float* ac = &g_P[((size_t)bn * QL + i) * KL];
    const float* bd = &g_BD[((size_t)bn * QL + i) * KL];
    int tid = threadIdx.x;
    int lim = i + ML;
    float v[4]; float mx = -1e30f;
    #pragma unroll
    for (int r = 0; r < 4; r++) {
        int j = r * 256 + tid;
        float s = (j <= lim) ? ASCALE * (ac[j] + bd[j + QL - 1 - i]) : -1e30f;
        v[r] = s; mx = fmaxf(mx, s);
    }
    __shared__ float red[256];
    red[tid] = mx; __syncthreads();
    for (int st = 128; st > 0; st >>= 1) {
        if (tid < st) red[tid] = fmaxf(red[tid], red[tid + st]);
        __syncthreads();
    }
    mx = red[0]; __syncthreads();
    float sum = 0.f;
    #pragma unroll
    for (int r = 0; r < 4; r++) { v[r] = __expf(v[r] - mx); sum += v[r]; }
    red[tid] = sum; __syncthreads();
    for (int st = 128; st > 0; st >>= 1) {
        if (tid < st) red[tid] += red[tid + st];
        __syncthreads();
    }
    float inv = 1.0f / red[0];
    __nv_bfloat16* p = g_p3 + ((size_t)bn * QL + i) * (3*KL);
    #pragma unroll
    for (int r = 0; r < 4; r++) {
        int j = r * 256 + tid;
        __nv_bfloat16 h, l; split1(v[r] * inv, h, l);
        p[j] = h; p[KL + j] = l; p[2*KL + j] = h;
    }
}

// residual add + LayerNorm; writes core (fp32) and core3 (bf16x3)
__global__ void add_ln_kernel(float* __restrict__ io, const float* __restrict__ add,
                              const float* __restrict__ g, const float* __restrict__ bt,
                              __nv_bfloat16* __restrict__ out3) {
    int t = blockIdx.x, tid = threadIdx.x;
    size_t base = (size_t)t * DM;
    float x[4]; float s = 0.f, sq = 0.f;
    #pragma unroll
    for (int r = 0; r < 4; r++) {
        int d = r * 256 + tid;
        float v = io[base + d] + add[base + d];
        x[r] = v; s += v; sq += v * v;
    }
    __shared__ float rs[256], rq[256];
    rs[tid] = s; rq[tid] = sq; __syncthreads();
    for (int st = 128; st > 0; st >>= 1) {
        if (tid < st) { rs[tid] += rs[tid + st]; rq[tid] += rq[tid + st]; }
        __syncthreads();
    }
    float mean = rs[0] * (1.0f / DM);
    float var  = rq[0] * (1.0f / DM) - mean * mean;
    float rstd = rsqrtf(var + 1e-5f);
    __nv_bfloat16* yb = out3 + (size_t)t * (3*DM);
    #pragma unroll
    for (int r = 0; r < 4; r++) {
        int d = r * 256 + tid;
        float o = (x[r] - mean) * rstd * g[d] + bt[d];
        io[base + d] = o;
        __nv_bfloat16 h, l; split1(o, h, l);
        yb[d] = h; yb[DM + d] = l; yb[2*DM + d] = h;
    }
}

__global__ void loss_kernel(const int* __restrict__ target, float* __restrict__ out) {
    int t = blockIdx.x, tid = threadIdx.x;
    const float* row = &g_logits[(size_t)t * NV];
    float mx = -1e30f;
    for (int j = tid; j < NV; j += 256) mx = fmaxf(mx, row[j]);
    __shared__ float red[256];
    red[tid] = mx; __syncthreads();
    for (int st = 128; st > 0; st >>= 1) {
        if (tid < st) red[tid] = fmaxf(red[tid], red[tid + st]);
        __syncthreads();
    }
    mx = red[0]; __syncthreads();
    float s = 0.f;
    for (int j = tid; j < NV; j += 256) s += __expf(row[j] - mx);
    red[tid] = s; __syncthreads();
    for (int st = 128; st > 0; st >>= 1) {
        if (tid < st) red[tid] += red[tid + st];
        __syncthreads();
    }
    if (tid == 0) {
        float lse = logf(red[0]) + mx;
        out[t] = lse - row[target[t]];
    }
}

// ==================== host orchestration =====================================
static void split_tr(const float* W, __nv_bfloat16* Y, int K, int N) {
    split_tr_kernel<<<dim3(N / 32, K / 32), dim3(32, 8)>>>(W, Y, K, N);
}

extern "C" void kernel_launch(void* const* d_in, const int* in_sizes, int n_in,
                              void* d_out, int out_size) {
    const int*   data   = (const int*)d_in[0];
    const int*   target = (const int*)d_in[1];
    const float* memory = (const float*)d_in[2];
    const float* embW   = (const float*)d_in[3];
    const float* rwb    = (const float*)d_in[4];
    const float* rrb    = (const float*)d_in[5];
    const float* Wq     = (const float*)d_in[6];
    const float* Wkv    = (const float*)d_in[7];
    const float* Wr     = (const float*)d_in[8];
    const float* Wo     = (const float*)d_in[9];
    const float* W1     = (const float*)d_in[10];
    const float* b1     = (const float*)d_in[11];
    const float* W2     = (const float*)d_in[12];
    const float* b2     = (const float*)d_in[13];
    const float* ln1g   = (const float*)d_in[14];
    const float* ln1b   = (const float*)d_in[15];
    const float* ln2g   = (const float*)d_in[16];
    const float* ln2b   = (const float*)d_in[17];

    float* out = (float*)d_out;
    const long SLAB = (long)ML * BS * DM;
    float* out_mems = (out_size >= 4096L + NLAY * SLAB) ? out + 4096 : nullptr;

    float *p_core, *p_q, *p_kv, *p_pos, *p_rk, *p_tmp, *p_logits, *p_P, *p_BD;
    __nv_bfloat16 *p_a3, *p_core3, *p_w3, *p_emb3, *p_pos3, *p_q3a, *p_q3b, *p_k3, *p_rk3;
    cudaGetSymbolAddress((void**)&p_core,   g_core);
    cudaGetSymbolAddress((void**)&p_q,      g_q);
    cudaGetSymbolAddress((void**)&p_kv,     g_kv);
    cudaGetSymbolAddress((void**)&p_pos,    g_posbuf);
    cudaGetSymbolAddress((void**)&p_rk,     g_rk);
    cudaGetSymbolAddress((void**)&p_tmp,    g_tmp);
    cudaGetSymbolAddress((void**)&p_logits, g_logits);
    cudaGetSymbolAddress((void**)&p_P,      g_P);
    cudaGetSymbolAddress((void**)&p_BD,     g_BD);
    cudaGetSymbolAddress((void**)&p_a3,     g_a3);
    cudaGetSymbolAddress((void**)&p_core3,  g_core3);
    cudaGetSymbolAddress((void**)&p_w3,     g_w3);
    cudaGetSymbolAddress((void**)&p_emb3,   g_emb3);
    cudaGetSymbolAddress((void**)&p_pos3,   g_pos3);
    cudaGetSymbolAddress((void**)&p_q3a,    g_q3a);
    cudaGetSymbolAddress((void**)&p_q3b,    g_q3b);
    cudaGetSymbolAddress((void**)&p_k3,     g_k3);
    cudaGetSymbolAddress((void**)&p_rk3,    g_rk3);

    embed_kernel<<<NQ, 256>>>(data, embW);
    pos_kernel<<<KL, 256>>>();
    {   // pos3 (A-layout)
        long total = (long)KL * DM;
        split_rows_kernel<0><<<(int)(total / 4 / 256), 256>>>(p_pos, p_pos3, 10, total);
    }
    {   // emb3 (B-layout [h|h|l]) — logits GEMM B operand
        long total = (long)NV * DM;
        split_rows_kernel<1><<<(int)(total / 4 / 256), 256>>>(embW, p_emb3, 10, total);
    }

    for (int L = 0; L < NLAY; L++) {
        if (out_mems)
            copyout_kernel<<<4096, 256>>>(out_mems + (long)L * SLAB);
        concat3_kernel<<<(int)((long)NK * DM / 4 / 256), 256>>>(memory + (long)L * SLAB);

        // kv = xk3 @ Wkv3 ; q = core3 @ Wq3 ; rk = pos3 @ Wr3
        split_tr(Wkv + (long)L*DM*2*DM, p_w3, DM, 2*DM);
        tc_gemm<0><<<dim3(16, 64), 256>>>(p_a3, p_w3, p_kv, nullptr, NK, 2*DM, 3*DM);
        split_tr(Wq + (long)L*DM*DM, p_w3, DM, DM);
        tc_gemm<0><<<dim3(8, 32), 256>>>(p_core3, p_w3, p_q, nullptr, NQ, DM, 3*DM);
        split_tr(Wr + (long)L*DM*DM, p_w3, DM, DM);
        tc_gemm<0><<<dim3(8, 8), 256>>>(p_pos3, p_w3, p_rk, nullptr, KL, DM, 3*DM);

        // attention operand prep
        q3_kernel<<<dim3(QL, 128), 64>>>(rwb, rrb);
        k3_kernel<<<dim3(KL, 128), 64>>>();
        rk3_kernel<<<dim3(KL, NH), 64>>>();
        vt3_kernel<<<dim3(KL/32, DH/32, 128), dim3(32, 8)>>>();

        // AC and BD_raw scores (with dead-tile skipping)
        tc_gemm_bat<<<dim3(KL/128, QL/128, 128), 256>>>(
            p_q3a, (long)QL*192, p_k3, (long)KL*192, 127,
            p_P, (long)QL*KL, KL, 192, 1);
        tc_gemm_bat<<<dim3(KL/128, QL/128, 128), 256>>>(
            p_q3b, (long)QL*192, p_rk3, (long)KL*192, 15,
            p_BD, (long)QL*KL, KL, 192, 2);

        softmax_kernel<<<dim3(QL, 128), 256>>>();        // -> g_p3 (bf16x3)
        pv_gemm<<<dim3(1, QL/128, 128), 256>>>();        // -> att3 in g_a3

        // attn_out = att3 @ Wo3 ; LN (emits core3)
        split_tr(Wo + (long)L*DM*DM, p_w3, DM, DM);
        tc_gemm<0><<<dim3(8, 32), 256>>>(p_a3, p_w3, p_tmp, nullptr, NQ, DM, 3*DM);
        add_ln_kernel<<<NQ, 256>>>(p_core, p_tmp, ln1g + L*DM, ln1b + L*DM, p_core3);

        // ff3 = relu(core3 @ W1 + b1) (bf16x3 direct) ; W2 ; LN (emits core3)
        split_tr(W1 + (long)L*DM*DI, p_w3, DM, DI);
        tc_gemm_relu3<<<dim3(32, 32), 256>>>(p_core3, p_w3, p_a3, b1 + L*DI, NQ, DI, 3*DM);
        split_tr(W2 + (long)L*DI*DM, p_w3, DI, DM);
        tc_gemm<1><<<dim3(8, 32), 256>>>(p_a3, p_w3, p_tmp, b2 + L*DM, NQ, DM, 3*DI);
        add_ln_kernel<<<NQ, 256>>>(p_core, p_tmp, ln2g + L*DM, ln2b + L*DM, p_core3);
    }

    // logits = core3 @ emb3^T (bf16x3) ; loss
    tc_gemm<0><<<dim3(NV/128, NQ/128), 256>>>(p_core3, p_emb3, p_logits, nullptr, NQ, NV, 3*DM);
    loss_kernel<<<NQ, 256>>>(target, out);
}

// round 13
// speedup vs baseline: 1.7956x; 1.0127x over previous
#include <cuda_runtime.h>
#include <cuda_bf16.h>
#include <math.h>
#include <stdint.h>

#define QL 512
#define ML 512
#define KL 1024
#define BS 8
#define NH 16
#define DH 64
#define DM 1024
#define DI 4096
#define NV 32000
#define NLAY 6
#define NQ (QL*BS)
#define NK (KL*BS)
#define ASCALE 0.125f
#define NTILE (NV/128)          // 250 logits n-tiles
#define NPART (NTILE*4)         // 1000 LSE partials per row

// ---------------- persistent scratch ----------------------------------------
static __device__ float g_core[NQ*DM];
static __device__ float g_q[NQ*DM];
static __device__ float g_kv[(size_t)NK*2*DM];
static __device__ float g_posbuf[KL*DM];
static __device__ float g_rk[KL*DM];
static __device__ float g_P[(size_t)BS*NH*QL*KL];
static __device__ float g_BD[(size_t)BS*NH*QL*KL];
static __device__ float g_tmp[NQ*DM];
static __device__ float g_lsebuf[(size_t)NQ*NPART*2 + NQ];   // partials (float2) + tgt logits
// bf16 triple-K operand buffers
static __device__ __nv_bfloat16 g_a3[(size_t)NQ*3*DI];       // xk3 / att3 / ff3 (time-shared)
static __device__ __nv_bfloat16 g_core3[(size_t)NQ*3*DM];    // core, A-layout (maintained)
static __device__ __nv_bfloat16 g_w3[(size_t)DI*3*DM];       // weights, B-layout
static __device__ __nv_bfloat16 g_emb3[(size_t)NV*3*DM];     // emb, B-layout [h|h|l]
static __device__ __nv_bfloat16 g_pos3[(size_t)KL*3*DM];
// attention operands
static __device__ __nv_bfloat16 g_q3a[(size_t)BS*NH*QL*192];
static __device__ __nv_bfloat16 g_q3b[(size_t)BS*NH*QL*192];
static __device__ __nv_bfloat16 g_k3 [(size_t)BS*NH*KL*192];
static __device__ __nv_bfloat16 g_rk3[(size_t)NH*KL*192];
static __device__ __nv_bfloat16 g_v3 [(size_t)BS*NH*DH*3*KL];
static __device__ __nv_bfloat16 g_p3 [(size_t)BS*NH*QL*3*KL];

__device__ __forceinline__ uint32_t smem_u32(const void* p) {
    uint32_t a;
    asm("{ .reg .u64 t; cvta.to.shared.u64 t, %1; cvt.u32.u64 %0, t; }" : "=r"(a) : "l"(p));
    return a;
}
__device__ __forceinline__ void split1(float v, __nv_bfloat16& h, __nv_bfloat16& l) {
    h = __float2bfloat16(v);
    l = __float2bfloat16(v - __bfloat162float(h));
}

#define MMA_BF16(acc, af, bf) \
    asm volatile("mma.sync.aligned.m16n8k16.row.col.f32.bf16.bf16.f32 " \
        "{%0,%1,%2,%3}, {%4,%5,%6,%7}, {%8,%9}, {%0,%1,%2,%3};\n" \
        : "+f"((acc)[0]), "+f"((acc)[1]), "+f"((acc)[2]), "+f"((acc)[3]) \
        : "r"((af)[0]), "r"((af)[1]), "r"((af)[2]), "r"((af)[3]), \
          "r"((bf)[0]), "r"((bf)[1]))

#define AST 40
#define TILE_ELEMS (128*AST)

// shared 128x128 mainloop body (computes acc from Ag/Bg)
#define GEMM_MAINLOOP()                                                        \
    uint32_t sA = smem_u32(As), sB = smem_u32(Bs);                             \
    int lrow = tid >> 2, lseg = tid & 3;                                       \
    _Pragma("unroll")                                                          \
    for (int i = 0; i < 2; i++) {                                              \
        int row = lrow + i * 64;                                               \
        uint32_t da = sA + (uint32_t)(row * AST + lseg * 8) * 2;               \
        uint32_t db = sB + (uint32_t)(row * AST + lseg * 8) * 2;               \
        const void* ga = Ag + (size_t)row * K3 + lseg * 8;                     \
        const void* gb = Bg + (size_t)row * K3 + lseg * 8;                     \
        asm volatile("cp.async.cg.shared.global [%0], [%1], 16;\n" :: "r"(da), "l"(ga)); \
        asm volatile("cp.async.cg.shared.global [%0], [%1], 16;\n" :: "r"(db), "l"(gb)); \
    }                                                                          \
    asm volatile("cp.async.commit_group;\n");                                  \
    for (int c = 0; c < NC; c++) {                                             \
        int cur = c & 1;                                                       \
        if (c + 1 < NC) {                                                      \
            int nx = cur ^ 1, k0 = (c + 1) * 32;                               \
            _Pragma("unroll")                                                  \
            for (int i = 0; i < 2; i++) {                                      \
                int row = lrow + i * 64;                                       \
                uint32_t da = sA + (uint32_t)(nx * TILE_ELEMS + row * AST + lseg * 8) * 2; \
                uint32_t db = sB + (uint32_t)(nx * TILE_ELEMS + row * AST + lseg * 8) * 2; \
                const void* ga = Ag + (size_t)row * K3 + k0 + lseg * 8;        \
                const void* gb = Bg + (size_t)row * K3 + k0 + lseg * 8;        \
                asm volatile("cp.async.cg.shared.global [%0], [%1], 16;\n" :: "r"(da), "l"(ga)); \
                asm volatile("cp.async.cg.shared.global [%0], [%1], 16;\n" :: "r"(db), "l"(gb)); \
            }                                                                  \
            asm volatile("cp.async.commit_group;\n");                          \
            asm volatile("cp.async.wait_group 1;\n");                          \
        } else {                                                               \
            asm volatile("cp.async.wait_group 0;\n");                          \
        }                                                                      \
        __syncthreads();                                                       \
        const __nv_bfloat16* Ab = &As[cur][0];                                 \
        const __nv_bfloat16* Bb = &Bs[cur][0];                                 \
        _Pragma("unroll")                                                      \
        for (int ks = 0; ks < 2; ks++) {                                       \
            int kk = ks * 16;                                                  \
            uint32_t a_frag[4][4];                                             \
            uint32_t b_frag[4][2];                                             \
            _Pragma("unroll")                                                  \
            for (int mt = 0; mt < 4; mt++) {                                   \
                int r0 = (warp_m * 64 + mt * 16 + gid) * AST + kk + tig * 2;   \
                a_frag[mt][0] = *(const uint32_t*)(Ab + r0);                   \
                a_frag[mt][1] = *(const uint32_t*)(Ab + r0 + 8 * AST);         \
                a_frag[mt][2] = *(const uint32_t*)(Ab + r0 + 8);               \
                a_frag[mt][3] = *(const uint32_t*)(Ab + r0 + 8 * AST + 8);     \
            }                                                                  \
            _Pragma("unroll")                                                  \
            for (int nt = 0; nt < 4; nt++) {                                   \
                int rn = (warp_n * 32 + nt * 8 + gid) * AST + kk + tig * 2;    \
                b_frag[nt][0] = *(const uint32_t*)(Bb + rn);                   \
                b_frag[nt][1] = *(const uint32_t*)(Bb + rn + 8);               \
            }                                                                  \
            _Pragma("unroll")                                                  \
            for (int mt = 0; mt < 4; mt++)                                     \
                _Pragma("unroll")                                              \
                for (int nt = 0; nt < 4; nt++)                                 \
                    MMA_BF16(acc[mt][nt], a_frag[mt], b_frag[nt]);             \
        }                                                                      \
        __syncthreads();                                                       \
    }

// ---- generic GEMM, fp32 C, optional bias ------------------------------------
template<int EPI>   // 0 none, 1 +bias
__global__ __launch_bounds__(256, 2)
void tc_gemm(const __nv_bfloat16* __restrict__ A3, const __nv_bfloat16* __restrict__ B3,
             float* __restrict__ C, const float* __restrict__ bias,
             int M, int N, int K3) {
    __shared__ __align__(16) __nv_bfloat16 As[2][TILE_ELEMS];
    __shared__ __align__(16) __nv_bfloat16 Bs[2][TILE_ELEMS];
    int tid = threadIdx.x, wid = tid >> 5, lane = tid & 31;
    int warp_m = wid >> 2, warp_n = wid & 3;
    int gid = lane >> 2, tig = lane & 3;
    int n0 = blockIdx.x * 128, m0 = blockIdx.y * 128;
    const __nv_bfloat16* Ag = A3 + (size_t)m0 * K3;
    const __nv_bfloat16* Bg = B3 + (size_t)n0 * K3;
    int NC = K3 >> 5;
    float acc[4][4][4] = {};
    GEMM_MAINLOOP()
    #pragma unroll
    for (int mt = 0; mt < 4; mt++)
        #pragma unroll
        for (int nt = 0; nt < 4; nt++) {
            int row0 = m0 + warp_m * 64 + mt * 16 + gid;
            int col  = n0 + warp_n * 32 + nt * 8 + tig * 2;
            float2 v0, v1;
            v0.x = acc[mt][nt][0]; v0.y = acc[mt][nt][1];
            v1.x = acc[mt][nt][2]; v1.y = acc[mt][nt][3];
            if (EPI >= 1) {
                float bx = bias[col], by = bias[col + 1];
                v0.x += bx; v0.y += by; v1.x += bx; v1.y += by;
            }
            *(float2*)(C + (size_t)row0 * N + col)       = v0;
            *(float2*)(C + (size_t)(row0 + 8) * N + col) = v1;
        }
}

// ---- logits GEMM with fused LSE-partials epilogue (grid: x=m-tiles, y=n-tiles)
__global__ __launch_bounds__(256, 2)
void tc_gemm_lse(const __nv_bfloat16* __restrict__ A3, const __nv_bfloat16* __restrict__ B3,
                 const int* __restrict__ target,
                 float2* __restrict__ part, float* __restrict__ tgtlog, int K3) {
    __shared__ __align__(16) __nv_bfloat16 As[2][TILE_ELEMS];
    __shared__ __align__(16) __nv_bfloat16 Bs[2][TILE_ELEMS];
    int tid = threadIdx.x, wid = tid >> 5, lane = tid & 31;
    int warp_m = wid >> 2, warp_n = wid & 3;
    int gid = lane >> 2, tig = lane & 3;
    int bxn = blockIdx.y;                  // n-tile (slow) — 32 CTAs share one B tile
    int n0 = bxn * 128, m0 = blockIdx.x * 128;
    const __nv_bfloat16* Ag = A3 + (size_t)m0 * K3;
    const __nv_bfloat16* Bg = B3 + (size_t)n0 * K3;
    int NC = K3 >> 5;
    float acc[4][4][4] = {};
    GEMM_MAINLOOP()
    // LSE partial per (row, warp_n): reduce thread's 8 values, then across tig lanes
    #pragma unroll
    for (int mt = 0; mt < 4; mt++) {
        #pragma unroll
        for (int half = 0; half < 2; half++) {
            int row = m0 + warp_m * 64 + mt * 16 + gid + half * 8;
            int tgt = target[row];
            float m = -1e30f;
            #pragma unroll
            for (int nt = 0; nt < 4; nt++) {
                float vx = acc[mt][nt][half*2+0], vy = acc[mt][nt][half*2+1];
                int col = n0 + warp_n * 32 + nt * 8 + tig * 2;
                if (col == tgt)     tgtlog[row] = vx;
                if (col + 1 == tgt) tgtlog[row] = vy;
                m = fmaxf(m, fmaxf(vx, vy));
            }
            float s = 0.f;
            #pragma unroll
            for (int nt = 0; nt < 4; nt++) {
                s += __expf(acc[mt][nt][half*2+0] - m);
                s += __expf(acc[mt][nt][half*2+1] - m);
            }
            #pragma unroll
            for (int off = 1; off < 4; off <<= 1) {
                float om = __shfl_xor_sync(0xffffffff, m, off);
                float os = __shfl_xor_sync(0xffffffff, s, off);
                float nm = fmaxf(m, om);
                s = s * __expf(m - nm) + os * __expf(om - nm);
                m = nm;
            }
            if (tig == 0) {
                float2 p; p.x = m; p.y = s;
                part[(size_t)row * NPART + bxn * 4 + warp_n] = p;
            }
        }
    }
}

// ---- W1 GEMM: relu(x+bias) -> bf16x3 A-layout directly ----------------------
__global__ __launch_bounds__(256, 2)
void tc_gemm_relu3(const __nv_bfloat16* __restrict__ A3, const __nv_bfloat16* __restrict__ B3,
                   __nv_bfloat16* __restrict__ Cb, const float* __restrict__ bias,
                   int M, int N, int K3) {
    __shared__ __align__(16) __nv_bfloat16 As[2][TILE_ELEMS];
    __shared__ __align__(16) __nv_bfloat16 Bs[2][TILE_ELEMS];
    int tid = threadIdx.x, wid = tid >> 5, lane = tid & 31;
    int warp_m = wid >> 2, warp_n = wid & 3;
    int gid = lane >> 2, tig = lane & 3;
    int n0 = blockIdx.x * 128, m0 = blockIdx.y * 128;
    const __nv_bfloat16* Ag = A3 + (size_t)m0 * K3;
    const __nv_bfloat16* Bg = B3 + (size_t)n0 * K3;
    int NC = K3 >> 5;
    float acc[4][4][4] = {};
    GEMM_MAINLOOP()
    #pragma unroll
    for (int mt = 0; mt < 4; mt++)
        #pragma unroll
        for (int nt = 0; nt < 4; nt++) {
            int row0 = m0 + warp_m * 64 + mt * 16 + gid;
            int col  = n0 + warp_n * 32 + nt * 8 + tig * 2;
            float bx = bias[col], by = bias[col + 1];
            #pragma unroll
            for (int half = 0; half < 2; half++) {
                float vx = fmaxf(acc[mt][nt][half*2+0] + bx, 0.f);
                float vy = fmaxf(acc[mt][nt][half*2+1] + by, 0.f);
                __nv_bfloat16 hx, lx, hy, ly;
                split1(vx, hx, lx); split1(vy, hy, ly);
                __nv_bfloat162 hh; hh.x = hx; hh.y = hy;
                __nv_bfloat162 ll; ll.x = lx; ll.y = ly;
                __nv_bfloat16* r = Cb + (size_t)(row0 + half*8) * (3*N) + col;
                *(__nv_bfloat162*)(r)         = hh;
                *(__nv_bfloat162*)(r + N)     = ll;
                *(__nv_bfloat162*)(r + 2*N)   = hh;
            }
        }
}

// ---- batched AC/BD scores; skip_mode 1=AC causal skip, 2=BD relshift skip ---
__global__ __launch_bounds__(256, 2)
void tc_gemm_bat(const __nv_bfloat16* __restrict__ A3, long strideA,
                 const __nv_bfloat16* __restrict__ B3, long strideB, int bmask,
                 float* __restrict__ C, long strideC, int ldc,
                 int K3, int skip_mode) {
    int n0 = blockIdx.x * 128, m0 = blockIdx.y * 128, bz = blockIdx.z;
    if (skip_mode == 1 && n0 >= m0 + 640) return;      // AC: fully masked
    if (skip_mode == 2 && n0 + m0 <= 256) return;      // BD: never read
    __shared__ __align__(16) __nv_bfloat16 As[2][TILE_ELEMS];
    __shared__ __align__(16) __nv_bfloat16 Bs[2][TILE_ELEMS];
    int tid = threadIdx.x, wid = tid >> 5, lane = tid & 31;
    int warp_m = wid >> 2, warp_n = wid & 3;
    int gid = lane >> 2, tig = lane & 3;
    const __nv_bfloat16* Ag = A3 + (size_t)bz * strideA + (size_t)m0 * K3;
    const __nv_bfloat16* Bg = B3 + (size_t)(bz & bmask) * strideB + (size_t)n0 * K3;
    float* Cg = C + (size_t)bz * strideC;
    int NC = K3 >> 5;
    float acc[4][4][4] = {};
    GEMM_MAINLOOP()
    #pragma unroll
    for (int mt = 0; mt < 4; mt++)
        #pragma unroll
        for (int nt = 0; nt < 4; nt++) {
            int row0 = m0 + warp_m * 64 + mt * 16 + gid;
            int col  = n0 + warp_n * 32 + nt * 8 + tig * 2;
            float2 v0, v1;
            v0.x = acc[mt][nt][0]; v0.y = acc[mt][nt][1];
            v1.x = acc[mt][nt][2]; v1.y = acc[mt][nt][3];
            *(float2*)(Cg + (size_t)row0 * ldc + col)       = v0;
            *(float2*)(Cg + (size_t)(row0 + 8) * ldc + col) = v1;
        }
}

// ---- PV: 128x64 per (b,n); skips masked K-chunks; writes att3 into g_a3 -----
__global__ __launch_bounds__(256, 2)
void pv_gemm() {
    __shared__ __align__(16) __nv_bfloat16 As[2][128*AST];
    __shared__ __align__(16) __nv_bfloat16 Bs[2][64*AST];
    int tid = threadIdx.x, wid = tid >> 5, lane = tid & 31;
    int warp_m = wid >> 1, warp_n = wid & 1;
    int gid = lane >> 2, tig = lane & 3;
    int m0 = blockIdx.y * 128, bz = blockIdx.z;
    int b = bz >> 4, n = bz & 15;
    const int K3 = 3 * KL;
    int NCV = (m0 >> 5) + 20; if (NCV > 32) NCV = 32;  // valid 32-chunks per block
    int NCT = 3 * NCV;
    const __nv_bfloat16* Ag = g_p3 + ((size_t)bz * QL + m0) * K3;
    const __nv_bfloat16* Bg = g_v3 + (size_t)bz * DH * K3;
    uint32_t sA = smem_u32(As), sB = smem_u32(Bs);
    int lrow = tid >> 2, lseg = tid & 3;

    #pragma unroll
    for (int i = 0; i < 2; i++) {
        int row = lrow + i * 64;
        uint32_t da = sA + (uint32_t)(row * AST + lseg * 8) * 2;
        const void* ga = Ag + (size_t)row * K3 + lseg * 8;
        asm volatile("cp.async.cg.shared.global [%0], [%1], 16;\n" :: "r"(da), "l"(ga));
    }
    {
        uint32_t db = sB + (uint32_t)(lrow * AST + lseg * 8) * 2;
        const void* gb = Bg + (size_t)lrow * K3 + lseg * 8;
        asm volatile("cp.async.cg.shared.global [%0], [%1], 16;\n" :: "r"(db), "l"(gb));
    }
    asm volatile("cp.async.commit_group;\n");

    float acc[2][4][4] = {};

    for (int c = 0; c < NCT; c++) {
        int cur = c & 1;
        if (c + 1 < NCT) {
            int cn = c + 1;
            int blk = cn / NCV, cc = cn - blk * NCV;
            int k0 = blk * KL + cc * 32;
            int nx = cur ^ 1;
            #pragma unroll
            for (int i = 0; i < 2; i++) {
                int row = lrow + i * 64;
                uint32_t da = sA + (uint32_t)(nx * 128*AST + row * AST + lseg * 8) * 2;
                const void* ga = Ag + (size_t)row * K3 + k0 + lseg * 8;
                asm volatile("cp.async.cg.shared.global [%0], [%1], 16;\n" :: "r"(da), "l"(ga));
            }
            {
                uint32_t db = sB + (uint32_t)(nx * 64*AST + lrow * AST + lseg * 8) * 2;
                const void* gb = Bg + (size_t)lrow * K3 + k0 + lseg * 8;
                asm volatile("cp.async.cg.shared.global [%0], [%1], 16;\n" :: "r"(db), "l"(gb));
            }
            asm volatile("cp.async.commit_group;\n");
            asm volatile("cp.async.wait_group 1;\n");
        } else {
            asm volatile("cp.async.wait_group 0;\n");
        }
        __syncthreads();

        const __nv_bfloat16* Ab = &As[cur][0];
        const __nv_bfloat16* Bb = &Bs[cur][0];
        #pragma unroll
        for (int ks = 0; ks < 2; ks++) {
            int kk = ks * 16;
            uint32_t a_frag[2][4];
            uint32_t b_frag[4][2];
            #pragma unroll
            for (int mt = 0; mt < 2; mt++) {
                int r0 = (warp_m * 32 + mt * 16 + gid) * AST + kk + tig * 2;
                a_frag[mt][0] = *(const uint32_t*)(Ab + r0);
                a_frag[mt][1] = *(const uint32_t*)(Ab + r0 + 8 * AST);
                a_frag[mt][2] = *(const uint32_t*)(Ab + r0 + 8);
                a_frag[mt][3] = *(const uint32_t*)(Ab + r0 + 8 * AST + 8);
            }
            #pragma unroll
            for (int nt = 0; nt < 4; nt++) {
                int rn = (warp_n * 32 + nt * 8 + gid) * AST + kk + tig * 2;
                b_frag[nt][0] = *(const uint32_t*)(Bb + rn);
                b_frag[nt][1] = *(const uint32_t*)(Bb + rn + 8);
            }
            #pragma unroll
            for (int mt = 0; mt < 2; mt++)
                #pragma unroll
                for (int nt = 0; nt < 4; nt++)
                    MMA_BF16(acc[mt][nt], a_frag[mt], b_frag[nt]);
        }
        __syncthreads();
    }

    // att3 (A-layout over DM): g_a3[(i*BS+b)*3072 + {0,1024,2048} + n*64 + col]
    #pragma unroll
    for (int mt = 0; mt < 2; mt++)
        #pragma unroll
        for (int nt = 0; nt < 4; nt++) {
            int i0r = m0 + warp_m * 32 + mt * 16 + gid;
            int col = warp_n * 32 + nt * 8 + tig * 2;
            #pragma unroll
            for (int half = 0; half < 2; half++) {
                int i = i0r + half * 8;
                float vx = acc[mt][nt][half*2+0], vy = acc[mt][nt][half*2+1];
                __nv_bfloat16 hx, lx, hy, ly;
                split1(vx, hx, lx); split1(vy, hy, ly);
                __nv_bfloat162 hh; hh.x = hx; hh.y = hy;
                __nv_bfloat162 ll; ll.x = lx; ll.y = ly;
                __nv_bfloat16* r = g_a3 + (size_t)(i * BS + b) * (3*DM) + n * DH + col;
                *(__nv_bfloat162*)(r)          = hh;
                *(__nv_bfloat162*)(r + DM)     = ll;
                *(__nv_bfloat162*)(r + 2*DM)   = hh;
            }
        }
}

// ==================== conversions / prep =====================================
template<int MODE>  // 0: [h|l|h] (A)   1: [h|h|l] (B)
__global__ void split_rows_kernel(const float* __restrict__ X, __nv_bfloat16* __restrict__ Y,
                                  int kshift, long total) {
    long e = ((long)blockIdx.x * 256 + threadIdx.x) * 4;
    if (e >= total) return;
    int K = 1 << kshift;
    long r = e >> kshift; int c = (int)(e & (K - 1));
    float4 v = *(const float4*)(X + e);
    __nv_bfloat16 hx, hy, hz, hw, lx, ly, lz, lw;
    split1(v.x, hx, lx); split1(v.y, hy, ly); split1(v.z, hz, lz); split1(v.w, hw, lw);
    __nv_bfloat16* yb = Y + r * 3 * K;
    __nv_bfloat162 h01; h01.x = hx; h01.y = hy;
    __nv_bfloat162 h23; h23.x = hz; h23.y = hw;
    __nv_bfloat162 l01; l01.x = lx; l01.y = ly;
    __nv_bfloat162 l23; l23.x = lz; l23.y = lw;
    *(__nv_bfloat162*)(yb + c)       = h01; *(__nv_bfloat162*)(yb + c + 2)       = h23;
    if (MODE == 0) {
        *(__nv_bfloat162*)(yb + K + c)   = l01; *(__nv_bfloat162*)(yb + K + c + 2)   = l23;
        *(__nv_bfloat162*)(yb + 2*K + c) = h01; *(__nv_bfloat162*)(yb + 2*K + c + 2) = h23;
    } else {
        *(__nv_bfloat162*)(yb + K + c)   = h01; *(__nv_bfloat162*)(yb + K + c + 2)   = h23;
        *(__nv_bfloat162*)(yb + 2*K + c) = l01; *(__nv_bfloat162*)(yb + 2*K + c + 2) = l23;
    }
}

// W[K,N] -> Y[N,3K] = [h|h|l]
__global__ void split_tr_kernel(const float* __restrict__ W, __nv_bfloat16* __restrict__ Y,
                                int K, int N) {
    __shared__ float s[32][33];
    int n0 = blockIdx.x * 32, k0 = blockIdx.y * 32;
    int tx = threadIdx.x, ty = threadIdx.y;
    for (int i = ty; i < 32; i += 8)
        s[i][tx] = W[(size_t)(k0 + i) * N + n0 + tx];
    __syncthreads();
    for (int i = ty; i < 32; i += 8) {
        int n = n0 + i, k = k0 + tx;
        __nv_bfloat16 h, l; split1(s[tx][i], h, l);
        __nv_bfloat16* yb = Y + (size_t)n * 3 * K;
        yb[k] = h; yb[K + k] = h; yb[2*K + k] = l;
    }
}

// q3: (q + rwb/rrb) -> both A-layouts at once
__global__ void q3_kernel(const float* __restrict__ rwb, const float* __restrict__ rrb) {
    int i = blockIdx.x, bn = blockIdx.y, b = bn >> 4, n = bn & 15, d = threadIdx.x;
    float qv = g_q[((size_t)i * BS + b) * DM + n * DH + d];
    float va = qv + rwb[n * DH + d];
    float vb = qv + rrb[n * DH + d];
    __nv_bfloat16 h, l;
    split1(va, h, l);
    __nv_bfloat16* oa = g_q3a + ((size_t)bn * QL + i) * 192;
    oa[d] = h; oa[64 + d] = l; oa[128 + d] = h;
    split1(vb, h, l);
    __nv_bfloat16* ob = g_q3b + ((size_t)bn * QL + i) * 192;
    ob[d] = h; ob[64 + d] = l; ob[128 + d] = h;
}
__global__ void k3_kernel() {
    int j = blockIdx.x, bn = blockIdx.y, b = bn >> 4, n = bn & 15, d = threadIdx.x;
    float v = g_kv[((size_t)j * BS + b) * (2*DM) + n * DH + d];
    __nv_bfloat16 h, l; split1(v, h, l);
    __nv_bfloat16* o = g_k3 + ((size_t)bn * KL + j) * 192;
    o[d] = h; o[64 + d] = h; o[128 + d] = l;
}
__global__ void rk3_kernel() {
    int j = blockIdx.x, n = blockIdx.y, d = threadIdx.x;
    float v = g_rk[(size_t)j * DM + n * DH + d];
    __nv_bfloat16 h, l; split1(v, h, l);
    __nv_bfloat16* o = g_rk3 + ((size_t)n * KL + j) * 192;
    o[d] = h; o[64 + d] = h; o[128 + d] = l;
}
__global__ void vt3_kernel() {
    __shared__ float s[32][33];
    int j0 = blockIdx.x * 32, d0 = blockIdx.y * 32, bn = blockIdx.z;
    int b = bn >> 4, n = bn & 15;
    int tx = threadIdx.x, ty = threadIdx.y;
    for (int jj = ty; jj < 32; jj += 8)
        s[jj][tx] = g_kv[((size_t)(j0 + jj) * BS + b) * (2*DM) + DM + n * DH + d0 + tx];
    __syncthreads();
    for (int dd = ty; dd < 32; dd += 8) {
        __nv_bfloat16 h, l; split1(s[tx][dd], h, l);
        __nv_bfloat16* o = g_v3 + ((size_t)bn * DH + d0 + dd) * (3*KL) + j0 + tx;
        o[0] = h; o[KL] = h; o[2*KL] = l;
    }
}

// ==================== misc kernels ===========================================
__global__ void embed_kernel(const int* __restrict__ data, const float* __restrict__ embW) {
    int t = blockIdx.x;
    int tok = data[t];
    int c = threadIdx.x * 4;
    float4 v = *(const float4*)(embW + (size_t)tok * DM + c);
    *(float4*)(g_core + (size_t)t * DM + c) = v;
    __nv_bfloat16 hx, hy, hz, hw, lx, ly, lz, lw;
    split1(v.x, hx, lx); split1(v.y, hy, ly); split1(v.z, hz, lz); split1(v.w, hw, lw);
    __nv_bfloat16* yb = g_core3 + (size_t)t * (3*DM);
    __nv_bfloat162 h01; h01.x = hx; h01.y = hy;
    __nv_bfloat162 h23; h23.x = hz; h23.y = hw;
    __nv_bfloat162 l01; l01.x = lx; l01.y = ly;
    __nv_bfloat162 l23; l23.x = lz; l23.y = lw;
    *(__nv_bfloat162*)(yb + c)        = h01; *(__nv_bfloat162*)(yb + c + 2)        = h23;
    *(__nv_bfloat162*)(yb + DM + c)   = l01; *(__nv_bfloat162*)(yb + DM + c + 2)   = l23;
    *(__nv_bfloat162*)(yb + 2*DM + c) = h01; *(__nv_bfloat162*)(yb + 2*DM + c + 2) = h23;
}

__global__ void pos_kernel() {
    int p = blockIdx.x;
    float ps = (float)(KL - 1 - p);
    for (int j = threadIdx.x; j < 512; j += 256) {
        float f = powf(10000.0f, -(float)j / 512.0f);
        float a = ps * f;
        g_posbuf[p * DM + j]       = sinf(a);
        g_posbuf[p * DM + 512 + j] = cosf(a);
    }
}

// concat [mem_i ; core] -> xk3 (bf16x3 A-layout) directly into g_a3
__global__ void concat3_kernel(const float* __restrict__ mem_i) {
    long e = ((long)blockIdx.x * 256 + threadIdx.x) * 4;   // over NK*DM
    long r = e >> 10; int c = (int)(e & 1023);
    float4 v;
    if (r < ML * BS) v = *(const float4*)(mem_i + e);
    else             v = *(const float4*)(g_core + (r - ML*BS) * (long)DM + c);
    __nv_bfloat16 hx, hy, hz, hw, lx, ly, lz, lw;
    split1(v.x, hx, lx); split1(v.y, hy, ly); split1(v.z, hz, lz); split1(v.w, hw, lw);
    __nv_bfloat16* yb = g_a3 + r * (3*DM);
    __nv_bfloat162 h01; h01.x = hx; h01.y = hy;
    __nv_bfloat162 h23; h23.x = hz; h23.y = hw;
    __nv_bfloat162 l01; l01.x = lx; l01.y = ly;
    __nv_bfloat162 l23; l23.x = lz; l23.y = lw;
    *(__nv_bfloat162*)(yb + c)        = h01; *(__nv_bfloat162*)(yb + c + 2)        = h23;
    *(__nv_bfloat162*)(yb + DM + c)   = l01; *(__nv_bfloat162*)(yb + DM + c + 2)   = l23;
    *(__nv_bfloat162*)(yb + 2*DM + c) = h01; *(__nv_bfloat162*)(yb + 2*DM + c + 2) = h23;
}

__global__ void copyout_kernel(float* __restrict__ dst) {
    int i = blockIdx.x * 256 + threadIdx.x;
    ((float4*)dst)[i] = ((const float4*)g_core)[i];
}

// combine + rel-shift + mask + softmax -> p3 (bf16x3); skip writes past tile limit
__global__ void softmax_kernel() {
    int i = blockIdx.x, bn = blockIdx.y;
    const float* ac = &g_P[((size_t)bn * QL + i) * KL];
    const float* bd = &g_BD[((size_t)bn * QL + i) * KL];
    int tid = threadIdx.x;
    int lim = i + ML;
    int limW = (i & ~127) + 640; if (limW > KL) limW = KL;  // PV reads only j < limW
    float v[4]; float mx = -1e30f;
    #pragma unroll
    for (int r = 0; r < 4; r++) {
        int j = r * 256 + tid;
        float s = (j <= lim) ? ASCALE * (ac[j] + bd[j + QL - 1 - i]) : -1e30f;
        v[r] = s; mx = fmaxf(mx, s);
    }
    __shared__ float red[256];
    red[tid] = mx; __syncthreads();
    for (int st = 128; st > 0; st >>= 1) {
        if (tid < st) red[tid] = fmaxf(red[tid], red[tid + st]);
        __syncthreads();
    }
    mx = red[0]; __syncthreads();
    float sum = 0.f;
    #pragma unroll
    for (int r = 0; r < 4; r++) { v[r] = __expf(v[r] - mx); sum += v[r]; }
    red[tid] = sum; __syncthreads();
    for (int st = 128; st > 0; st >>= 1) {
        if (tid < st) red[tid] += red[tid + st];
        __syncthreads();
    }
    float inv = 1.0f / red[0];
    __nv_bfloat16* p = g_p3 + ((size_t)bn * QL + i) * (3*KL);
    #pragma unroll
    for (int r = 0; r < 4; r++) {
        int j = r * 256 + tid;
        if (j < limW) {
            __nv_bfloat16 h, l; split1(v[r] * inv, h, l);
            p[j] = h; p[KL + j] = l; p[2*KL + j] = h;
        }
    }
}

// residual add + LayerNorm; writes core (fp32) and core3 (bf16x3)
__global__ void add_ln_kernel(float* __restrict__ io, const float* __restrict__ add,
                              const float* __restrict__ g, const float* __restrict__ bt,
                              __nv_bfloat16* __restrict__ out3) {
    int t = blockIdx.x, tid = threadIdx.x;
    size_t base = (size_t)t * DM;
    float x[4]; float s = 0.f, sq = 0.f;
    #pragma unroll
    for (int r = 0; r < 4; r++) {
        int d = r * 256 + tid;
        float v = io[base + d] + add[base + d];
        x[r] = v; s += v; sq += v * v;
    }
    __shared__ float rs[256], rq[256];
    rs[tid] = s; rq[tid] = sq; __syncthreads();
    for (int st = 128; st > 0; st >>= 1) {
        if (tid < st) { rs[tid] += rs[tid + st]; rq[tid] += rq[tid + st]; }
        __syncthreads();
    }
    float mean = rs[0] * (1.0f / DM);
    float var  = rq[0] * (1.0f / DM) - mean * mean;
    float rstd = rsqrtf(var + 1e-5f);
    __nv_bfloat16* yb = out3 + (size_t)t * (3*DM);
    #pragma unroll
    for (int r = 0; r < 4; r++) {
        int d = r * 256 + tid;
        float o = (x[r] - mean) * rstd * g[d] + bt[d];
        io[base + d] = o;
        __nv_bfloat16 h, l; split1(o, h, l);
        yb[d] = h; yb[DM + d] = l; yb[2*DM + d] = h;
    }
}

// combine LSE partials -> loss
__global__ void loss2_kernel(const float2* __restrict__ part,
                             const float* __restrict__ tgtlog, float* __restrict__ out) {
    int t = blockIdx.x, tid = threadIdx.x;
    const float2* pp = part + (size_t)t * NPART;
    float m = -1e30f;
    for (int j = tid; j < NPART; j += 256) m = fmaxf(m, pp[j].x);
    __shared__ float red[256];
    red[tid] = m; __syncthreads();
    for (int st = 128; st > 0; st >>= 1) {
        if (tid < st) red[tid] = fmaxf(red[tid], red[tid + st]);
        __syncthreads();
    }
    m = red[0]; __syncthreads();
    float s = 0.f;
    for (int j = tid; j < NPART; j += 256) s += pp[j].y * __expf(pp[j].x - m);
    red[tid] = s; __syncthreads();
    for (int st = 128; st > 0; st >>= 1) {
        if (tid < st) red[tid] += red[tid + st];
        __syncthreads();
    }
    if (tid == 0)
        out[t] = m + logf(red[0]) - tgtlog[t];
}

// ==================== host orchestration =====================================
static void split_tr(const float* W, __nv_bfloat16* Y, int K, int N) {
    split_tr_kernel<<<dim3(N / 32, K / 32), dim3(32, 8)>>>(W, Y, K, N);
}

extern "C" void kernel_launch(void* const* d_in, const int* in_sizes, int n_in,
                              void* d_out, int out_size) {
    const int*   data   = (const int*)d_in[0];
    const int*   target = (const int*)d_in[1];
    const float* memory = (const float*)d_in[2];
    const float* embW   = (const float*)d_in[3];
    const float* rwb    = (const float*)d_in[4];
    const float* rrb    = (const float*)d_in[5];
    const float* Wq     = (const float*)d_in[6];
    const float* Wkv    = (const float*)d_in[7];
    const float* Wr     = (const float*)d_in[8];
    const float* Wo     = (const float*)d_in[9];
    const float* W1     = (const float*)d_in[10];
    const float* b1     = (const float*)d_in[11];
    const float* W2     = (const float*)d_in[12];
    const float* b2     = (const float*)d_in[13];
    const float* ln1g   = (const float*)d_in[14];
    const float* ln1b   = (const float*)d_in[15];
    const float* ln2g   = (const float*)d_in[16];
    const float* ln2b   = (const float*)d_in[17];

    float* out = (float*)d_out;
    const long SLAB = (long)ML * BS * DM;
    float* out_mems = (out_size >= 4096L + NLAY * SLAB) ? out + 4096 : nullptr;

    float *p_core, *p_q, *p_kv, *p_pos, *p_rk, *p_tmp, *p_P, *p_BD, *p_lse;
    __nv_bfloat16 *p_a3, *p_core3, *p_w3, *p_emb3, *p_pos3, *p_q3a, *p_q3b, *p_k3, *p_rk3;
    cudaGetSymbolAddress((void**)&p_core,   g_core);
    cudaGetSymbolAddress((void**)&p_q,      g_q);
    cudaGetSymbolAddress((void**)&p_kv,     g_kv);
    cudaGetSymbolAddress((void**)&p_pos,    g_posbuf);
    cudaGetSymbolAddress((void**)&p_rk,     g_rk);
    cudaGetSymbolAddress((void**)&p_tmp,    g_tmp);
    cudaGetSymbolAddress((void**)&p_lse,    g_lsebuf);
    cudaGetSymbolAddress((void**)&p_P,      g_P);
    cudaGetSymbolAddress((void**)&p_BD,     g_BD);
    cudaGetSymbolAddress((void**)&p_a3,     g_a3);
    cudaGetSymbolAddress((void**)&p_core3,  g_core3);
    cudaGetSymbolAddress((void**)&p_w3,     g_w3);
    cudaGetSymbolAddress((void**)&p_emb3,   g_emb3);
    cudaGetSymbolAddress((void**)&p_pos3,   g_pos3);
    cudaGetSymbolAddress((void**)&p_q3a,    g_q3a);
    cudaGetSymbolAddress((void**)&p_q3b,    g_q3b);
    cudaGetSymbolAddress((void**)&p_k3,     g_k3);
    cudaGetSymbolAddress((void**)&p_rk3,    g_rk3);

    float2* p_part = (float2*)p_lse;                        // 4096 x 1000 float2
    float*  p_tgt  = p_lse + (size_t)NQ * NPART * 2;        // 4096 floats

    embed_kernel<<<NQ, 256>>>(data, embW);
    pos_kernel<<<KL, 256>>>();
    {   // pos3 (A-layout)
        long total = (long)KL * DM;
        split_rows_kernel<0><<<(int)(total / 4 / 256), 256>>>(p_pos, p_pos3, 10, total);
    }
    {   // emb3 (B-layout [h|h|l]) — logits GEMM B operand
        long total = (long)NV * DM;
        split_rows_kernel<1><<<(int)(total / 4 / 256), 256>>>(embW, p_emb3, 10, total);
    }

    for (int L = 0; L < NLAY; L++) {
        if (out_mems)
            copyout_kernel<<<4096, 256>>>(out_mems + (long)L * SLAB);
        concat3_kernel<<<(int)((long)NK * DM / 4 / 256), 256>>>(memory + (long)L * SLAB);

        // kv = xk3 @ Wkv3 ; q = core3 @ Wq3 ; rk = pos3 @ Wr3
        split_tr(Wkv + (long)L*DM*2*DM, p_w3, DM, 2*DM);
        tc_gemm<0><<<dim3(16, 64), 256>>>(p_a3, p_w3, p_kv, nullptr, NK, 2*DM, 3*DM);
        split_tr(Wq + (long)L*DM*DM, p_w3, DM, DM);
        tc_gemm<0><<<dim3(8, 32), 256>>>(p_core3, p_w3, p_q, nullptr, NQ, DM, 3*DM);
        split_tr(Wr + (long)L*DM*DM, p_w3, DM, DM);
        tc_gemm<0><<<dim3(8, 8), 256>>>(p_pos3, p_w3, p_rk, nullptr, KL, DM, 3*DM);

        // attention operand prep
        q3_kernel<<<dim3(QL, 128), 64>>>(rwb, rrb);
        k3_kernel<<<dim3(KL, 128), 64>>>();
        rk3_kernel<<<dim3(KL, NH), 64>>>();
        vt3_kernel<<<dim3(KL/32, DH/32, 128), dim3(32, 8)>>>();

        // AC and BD_raw scores (with dead-tile skipping)
        tc_gemm_bat<<<dim3(KL/128, QL/128, 128), 256>>>(
            p_q3a, (long)QL*192, p_k3, (long)KL*192, 127,
            p_P, (long)QL*KL, KL, 192, 1);
        tc_gemm_bat<<<dim3(KL/128, QL/128, 128), 256>>>(
            p_q3b, (long)QL*192, p_rk3, (long)KL*192, 15,
            p_BD, (long)QL*KL, KL, 192, 2);

        softmax_kernel<<<dim3(QL, 128), 256>>>();        // -> g_p3 (bf16x3, masked skip)
        pv_gemm<<<dim3(1, QL/128, 128), 256>>>();        // -> att3 in g_a3 (chunk skip)

        // attn_out = att3 @ Wo3 ; LN (emits core3)
        split_tr(Wo + (long)L*DM*DM, p_w3, DM, DM);
        tc_gemm<0><<<dim3(8, 32), 256>>>(p_a3, p_w3, p_tmp, nullptr, NQ, DM, 3*DM);
        add_ln_kernel<<<NQ, 256>>>(p_core, p_tmp, ln1g + L*DM, ln1b + L*DM, p_core3);

        // ff3 = relu(core3 @ W1 + b1) (bf16x3 direct) ; W2 ; LN (emits core3)
        split_tr(W1 + (long)L*DM*DI, p_w3, DM, DI);
        tc_gemm_relu3<<<dim3(32, 32), 256>>>(p_core3, p_w3, p_a3, b1 + L*DI, NQ, DI, 3*DM);
        split_tr(W2 + (long)L*DI*DM, p_w3, DI, DM);
        tc_gemm<1><<<dim3(8, 32), 256>>>(p_a3, p_w3, p_tmp, b2 + L*DM, NQ, DM, 3*DI);
        add_ln_kernel<<<NQ, 256>>>(p_core, p_tmp, ln2g + L*DM, ln2b + L*DM, p_core3);
    }

    // logits = core3 @ emb3^T with fused LSE partials (m-tiles fastest for B reuse)
    tc_gemm_lse<<<dim3(NQ/128, NV/128), 256>>>(p_core3, p_emb3, target,
                                               p_part, p_tgt, 3*DM);
    loss2_kernel<<<NQ, 256>>>(p_part, p_tgt, out);
}

// round 14
// speedup vs baseline: 1.8935x; 1.0545x over previous
#include <cuda_runtime.h>
#include <cuda_bf16.h>
#include <math.h>
#include <stdint.h>

#define QL 512
#define ML 512
#define KL 1024
#define BS 8
#define NH 16
#define DH 64
#define DM 1024
#define DI 4096
#define NV 32000
#define NLAY 6
#define NQ (QL*BS)
#define NK (KL*BS)
#define ASCALE 0.125f
#define NTILE (NV/128)
#define NPART (NTILE*4)

// ---------------- persistent scratch ----------------------------------------
static __device__ float g_core[NQ*DM];
static __device__ float g_q[NQ*DM];
static __device__ float g_kv[(size_t)NK*2*DM];
static __device__ float g_posbuf[KL*DM];
static __device__ float g_rk[KL*DM];
static __device__ float g_P[(size_t)BS*NH*QL*KL];
static __device__ float g_BD[(size_t)BS*NH*QL*KL];
static __device__ float g_tmp[NQ*DM];
static __device__ float g_lsebuf[(size_t)NQ*NPART*2 + NQ];
// bf16 triple-K operand buffers
static __device__ __nv_bfloat16 g_a3[(size_t)NQ*3*DI];       // xk3 / att3 / ff3 (time-shared)
static __device__ __nv_bfloat16 g_core3[(size_t)NQ*3*DM];
static __device__ __nv_bfloat16 g_emb3[(size_t)NV*3*DM];
static __device__ __nv_bfloat16 g_pos3[(size_t)KL*3*DM];
// per-layer pre-split weights (B-layout [h|h|l])
static __device__ __nv_bfloat16 g_wq3 [(size_t)NLAY*DM*3*DM];
static __device__ __nv_bfloat16 g_wkv3[(size_t)NLAY*2*DM*3*DM];
static __device__ __nv_bfloat16 g_wr3 [(size_t)NLAY*DM*3*DM];
static __device__ __nv_bfloat16 g_wo3 [(size_t)NLAY*DM*3*DM];
static __device__ __nv_bfloat16 g_w13 [(size_t)NLAY*DI*3*DM];
static __device__ __nv_bfloat16 g_w23 [(size_t)NLAY*DM*3*DI];
// attention operands
static __device__ __nv_bfloat16 g_q3a[(size_t)BS*NH*QL*192];
static __device__ __nv_bfloat16 g_q3b[(size_t)BS*NH*QL*192];
static __device__ __nv_bfloat16 g_k3 [(size_t)BS*NH*KL*192];
static __device__ __nv_bfloat16 g_rk3[(size_t)NH*KL*192];
static __device__ __nv_bfloat16 g_v3 [(size_t)BS*NH*DH*3*KL];
static __device__ __nv_bfloat16 g_p3 [(size_t)BS*NH*QL*3*KL];

__device__ __forceinline__ uint32_t smem_u32(const void* p) {
    uint32_t a;
    asm("{ .reg .u64 t; cvta.to.shared.u64 t, %1; cvt.u32.u64 %0, t; }" : "=r"(a) : "l"(p));
    return a;
}
__device__ __forceinline__ void split1(float v, __nv_bfloat16& h, __nv_bfloat16& l) {
    h = __float2bfloat16(v);
    l = __float2bfloat16(v - __bfloat162float(h));
}

#define MMA_BF16(acc, af, bf) \
    asm volatile("mma.sync.aligned.m16n8k16.row.col.f32.bf16.bf16.f32 " \
        "{%0,%1,%2,%3}, {%4,%5,%6,%7}, {%8,%9}, {%0,%1,%2,%3};\n" \
        : "+f"((acc)[0]), "+f"((acc)[1]), "+f"((acc)[2]), "+f"((acc)[3]) \
        : "r"((af)[0]), "r"((af)[1]), "r"((af)[2]), "r"((af)[3]), \
          "r"((bf)[0]), "r"((bf)[1]))

#define AST 40
#define TILE_ELEMS (128*AST)

#define GEMM_MAINLOOP()                                                        \
    uint32_t sA = smem_u32(As), sB = smem_u32(Bs);                             \
    int lrow = tid >> 2, lseg = tid & 3;                                       \
    _Pragma("unroll")                                                          \
    for (int i = 0; i < 2; i++) {                                              \
        int row = lrow + i * 64;                                               \
        uint32_t da = sA + (uint32_t)(row * AST + lseg * 8) * 2;               \
        uint32_t db = sB + (uint32_t)(row * AST + lseg * 8) * 2;               \
        const void* ga = Ag + (size_t)row * K3 + lseg * 8;                     \
        const void* gb = Bg + (size_t)row * K3 + lseg * 8;                     \
        asm volatile("cp.async.cg.shared.global [%0], [%1], 16;\n" :: "r"(da), "l"(ga)); \
        asm volatile("cp.async.cg.shared.global [%0], [%1], 16;\n" :: "r"(db), "l"(gb)); \
    }                                                                          \
    asm volatile("cp.async.commit_group;\n");                                  \
    for (int c = 0; c < NC; c++) {                                             \
        int cur = c & 1;                                                       \
        if (c + 1 < NC) {                                                      \
            int nx = cur ^ 1, k0 = (c + 1) * 32;                               \
            _Pragma("unroll")                                                  \
            for (int i = 0; i < 2; i++) {                                      \
                int row = lrow + i * 64;                                       \
                uint32_t da = sA + (uint32_t)(nx * TILE_ELEMS + row * AST + lseg * 8) * 2; \
                uint32_t db = sB + (uint32_t)(nx * TILE_ELEMS + row * AST + lseg * 8) * 2; \
                const void* ga = Ag + (size_t)row * K3 + k0 + lseg * 8;        \
                const void* gb = Bg + (size_t)row * K3 + k0 + lseg * 8;        \
                asm volatile("cp.async.cg.shared.global [%0], [%1], 16;\n" :: "r"(da), "l"(ga)); \
                asm volatile("cp.async.cg.shared.global [%0], [%1], 16;\n" :: "r"(db), "l"(gb)); \
            }                                                                  \
            asm volatile("cp.async.commit_group;\n");                          \
            asm volatile("cp.async.wait_group 1;\n");                          \
        } else {                                                               \
            asm volatile("cp.async.wait_group 0;\n");                          \
        }                                                                      \
        __syncthreads();                                                       \
        const __nv_bfloat16* Ab = &As[cur][0];                                 \
        const __nv_bfloat16* Bb = &Bs[cur][0];                                 \
        _Pragma("unroll")                                                      \
        for (int ks = 0; ks < 2; ks++) {                                       \
            int kk = ks * 16;                                                  \
            uint32_t a_frag[4][4];                                             \
            uint32_t b_frag[4][2];                                             \
            _Pragma("unroll")                                                  \
            for (int mt = 0; mt < 4; mt++) {                                   \
                int r0 = (warp_m * 64 + mt * 16 + gid) * AST + kk + tig * 2;   \
                a_frag[mt][0] = *(const uint32_t*)(Ab + r0);                   \
                a_frag[mt][1] = *(const uint32_t*)(Ab + r0 + 8 * AST);         \
                a_frag[mt][2] = *(const uint32_t*)(Ab + r0 + 8);               \
                a_frag[mt][3] = *(const uint32_t*)(Ab + r0 + 8 * AST + 8);     \
            }                                                                  \
            _Pragma("unroll")                                                  \
            for (int nt = 0; nt < 4; nt++) {                                   \
                int rn = (warp_n * 32 + nt * 8 + gid) * AST + kk + tig * 2;    \
                b_frag[nt][0] = *(const uint32_t*)(Bb + rn);                   \
                b_frag[nt][1] = *(const uint32_t*)(Bb + rn + 8);               \
            }                                                                  \
            _Pragma("unroll")                                                  \
            for (int mt = 0; mt < 4; mt++)                                     \
                _Pragma("unroll")                                              \
                for (int nt = 0; nt < 4; nt++)                                 \
                    MMA_BF16(acc[mt][nt], a_frag[mt], b_frag[nt]);             \
        }                                                                      \
        __syncthreads();                                                       \
    }

// ---- generic GEMM, fp32 C, optional bias ------------------------------------
template<int EPI>
__global__ __launch_bounds__(256, 2)
void tc_gemm(const __nv_bfloat16* __restrict__ A3, const __nv_bfloat16* __restrict__ B3,
             float* __restrict__ C, const float* __restrict__ bias,
             int M, int N, int K3) {
    __shared__ __align__(16) __nv_bfloat16 As[2][TILE_ELEMS];
    __shared__ __align__(16) __nv_bfloat16 Bs[2][TILE_ELEMS];
    int tid = threadIdx.x, wid = tid >> 5, lane = tid & 31;
    int warp_m = wid >> 2, warp_n = wid & 3;
    int gid = lane >> 2, tig = lane & 3;
    int n0 = blockIdx.x * 128, m0 = blockIdx.y * 128;
    const __nv_bfloat16* Ag = A3 + (size_t)m0 * K3;
    const __nv_bfloat16* Bg = B3 + (size_t)n0 * K3;
    int NC = K3 >> 5;
    float acc[4][4][4] = {};
    GEMM_MAINLOOP()
    #pragma unroll
    for (int mt = 0; mt < 4; mt++)
        #pragma unroll
        for (int nt = 0; nt < 4; nt++) {
            int row0 = m0 + warp_m * 64 + mt * 16 + gid;
            int col  = n0 + warp_n * 32 + nt * 8 + tig * 2;
            float2 v0, v1;
            v0.x = acc[mt][nt][0]; v0.y = acc[mt][nt][1];
            v1.x = acc[mt][nt][2]; v1.y = acc[mt][nt][3];
            if (EPI >= 1) {
                float bx = bias[col], by = bias[col + 1];
                v0.x += bx; v0.y += by; v1.x += bx; v1.y += by;
            }
            *(float2*)(C + (size_t)row0 * N + col)       = v0;
            *(float2*)(C + (size_t)(row0 + 8) * N + col) = v1;
        }
}

// ---- logits GEMM with fused LSE-partials epilogue ---------------------------
__global__ __launch_bounds__(256, 2)
void tc_gemm_lse(const __nv_bfloat16* __restrict__ A3, const __nv_bfloat16* __restrict__ B3,
                 const int* __restrict__ target,
                 float2* __restrict__ part, float* __restrict__ tgtlog, int K3) {
    __shared__ __align__(16) __nv_bfloat16 As[2][TILE_ELEMS];
    __shared__ __align__(16) __nv_bfloat16 Bs[2][TILE_ELEMS];
    int tid = threadIdx.x, wid = tid >> 5, lane = tid & 31;
    int warp_m = wid >> 2, warp_n = wid & 3;
    int gid = lane >> 2, tig = lane & 3;
    int bxn = blockIdx.y;
    int n0 = bxn * 128, m0 = blockIdx.x * 128;
    const __nv_bfloat16* Ag = A3 + (size_t)m0 * K3;
    const __nv_bfloat16* Bg = B3 + (size_t)n0 * K3;
    int NC = K3 >> 5;
    float acc[4][4][4] = {};
    GEMM_MAINLOOP()
    #pragma unroll
    for (int mt = 0; mt < 4; mt++) {
        #pragma unroll
        for (int half = 0; half < 2; half++) {
            int row = m0 + warp_m * 64 + mt * 16 + gid + half * 8;
            int tgt = target[row];
            float m = -1e30f;
            #pragma unroll
            for (int nt = 0; nt < 4; nt++) {
                float vx = acc[mt][nt][half*2+0], vy = acc[mt][nt][half*2+1];
                int col = n0 + warp_n * 32 + nt * 8 + tig * 2;
                if (col == tgt)     tgtlog[row] = vx;
                if (col + 1 == tgt) tgtlog[row] = vy;
                m = fmaxf(m, fmaxf(vx, vy));
            }
            float s = 0.f;
            #pragma unroll
            for (int nt = 0; nt < 4; nt++) {
                s += __expf(acc[mt][nt][half*2+0] - m);
                s += __expf(acc[mt][nt][half*2+1] - m);
            }
            #pragma unroll
            for (int off = 1; off < 4; off <<= 1) {
                float om = __shfl_xor_sync(0xffffffff, m, off);
                float os = __shfl_xor_sync(0xffffffff, s, off);
                float nm = fmaxf(m, om);
                s = s * __expf(m - nm) + os * __expf(om - nm);
                m = nm;
            }
            if (tig == 0) {
                float2 p; p.x = m; p.y = s;
                part[(size_t)row * NPART + bxn * 4 + warp_n] = p;
            }
        }
    }
}

// ---- W1 GEMM: relu(x+bias) -> bf16x3 A-layout directly ----------------------
__global__ __launch_bounds__(256, 2)
void tc_gemm_relu3(const __nv_bfloat16* __restrict__ A3, const __nv_bfloat16* __restrict__ B3,
                   __nv_bfloat16* __restrict__ Cb, const float* __restrict__ bias,
                   int M, int N, int K3) {
    __shared__ __align__(16) __nv_bfloat16 As[2][TILE_ELEMS];
    __shared__ __align__(16) __nv_bfloat16 Bs[2][TILE_ELEMS];
    int tid = threadIdx.x, wid = tid >> 5, lane = tid & 31;
    int warp_m = wid >> 2, warp_n = wid & 3;
    int gid = lane >> 2, tig = lane & 3;
    int n0 = blockIdx.x * 128, m0 = blockIdx.y * 128;
    const __nv_bfloat16* Ag = A3 + (size_t)m0 * K3;
    const __nv_bfloat16* Bg = B3 + (size_t)n0 * K3;
    int NC = K3 >> 5;
    float acc[4][4][4] = {};
    GEMM_MAINLOOP()
    #pragma unroll
    for (int mt = 0; mt < 4; mt++)
        #pragma unroll
        for (int nt = 0; nt < 4; nt++) {
            int row0 = m0 + warp_m * 64 + mt * 16 + gid;
            int col  = n0 + warp_n * 32 + nt * 8 + tig * 2;
            float bx = bias[col], by = bias[col + 1];
            #pragma unroll
            for (int half = 0; half < 2; half++) {
                float vx = fmaxf(acc[mt][nt][half*2+0] + bx, 0.f);
                float vy = fmaxf(acc[mt][nt][half*2+1] + by, 0.f);
                __nv_bfloat16 hx, lx, hy, ly;
                split1(vx, hx, lx); split1(vy, hy, ly);
                __nv_bfloat162 hh; hh.x = hx; hh.y = hy;
                __nv_bfloat162 ll; ll.x = lx; ll.y = ly;
                __nv_bfloat16* r = Cb + (size_t)(row0 + half*8) * (3*N) + col;
                *(__nv_bfloat162*)(r)         = hh;
                *(__nv_bfloat162*)(r + N)     = ll;
                *(__nv_bfloat162*)(r + 2*N)   = hh;
            }
        }
}

// ---- batched AC/BD scores with dead-tile skipping ---------------------------
__global__ __launch_bounds__(256, 2)
void tc_gemm_bat(const __nv_bfloat16* __restrict__ A3, long strideA,
                 const __nv_bfloat16* __restrict__ B3, long strideB, int bmask,
                 float* __restrict__ C, long strideC, int ldc,
                 int K3, int skip_mode) {
    int n0 = blockIdx.x * 128, m0 = blockIdx.y * 128, bz = blockIdx.z;
    if (skip_mode == 1 && n0 >= m0 + 640) return;
    if (skip_mode == 2 && n0 + m0 <= 256) return;
    __shared__ __align__(16) __nv_bfloat16 As[2][TILE_ELEMS];
    __shared__ __align__(16) __nv_bfloat16 Bs[2][TILE_ELEMS];
    int tid = threadIdx.x, wid = tid >> 5, lane = tid & 31;
    int warp_m = wid >> 2, warp_n = wid & 3;
    int gid = lane >> 2, tig = lane & 3;
    const __nv_bfloat16* Ag = A3 + (size_t)bz * strideA + (size_t)m0 * K3;
    const __nv_bfloat16* Bg = B3 + (size_t)(bz & bmask) * strideB + (size_t)n0 * K3;
    float* Cg = C + (size_t)bz * strideC;
    int NC = K3 >> 5;
    float acc[4][4][4] = {};
    GEMM_MAINLOOP()
    #pragma unroll
    for (int mt = 0; mt < 4; mt++)
        #pragma unroll
        for (int nt = 0; nt < 4; nt++) {
            int row0 = m0 + warp_m * 64 + mt * 16 + gid;
            int col  = n0 + warp_n * 32 + nt * 8 + tig * 2;
            float2 v0, v1;
            v0.x = acc[mt][nt][0]; v0.y = acc[mt][nt][1];
            v1.x = acc[mt][nt][2]; v1.y = acc[mt][nt][3];
            *(float2*)(Cg + (size_t)row0 * ldc + col)       = v0;
            *(float2*)(Cg + (size_t)(row0 + 8) * ldc + col) = v1;
        }
}

// ---- PV: 128x64 per (b,n); masked K-chunk skip; writes att3 into g_a3 -------
__global__ __launch_bounds__(256, 2)
void pv_gemm() {
    __shared__ __align__(16) __nv_bfloat16 As[2][128*AST];
    __shared__ __align__(16) __nv_bfloat16 Bs[2][64*AST];
    int tid = threadIdx.x, wid = tid >> 5, lane = tid & 31;
    int warp_m = wid >> 1, warp_n = wid & 1;
    int gid = lane >> 2, tig = lane & 3;
    int m0 = blockIdx.y * 128, bz = blockIdx.z;
    int b = bz >> 4, n = bz & 15;
    const int K3 = 3 * KL;
    int NCV = (m0 >> 5) + 20; if (NCV > 32) NCV = 32;
    int NCT = 3 * NCV;
    const __nv_bfloat16* Ag = g_p3 + ((size_t)bz * QL + m0) * K3;
    const __nv_bfloat16* Bg = g_v3 + (size_t)bz * DH * K3;
    uint32_t sA = smem_u32(As), sB = smem_u32(Bs);
    int lrow = tid >> 2, lseg = tid & 3;

    #pragma unroll
    for (int i = 0; i < 2; i++) {
        int row = lrow + i * 64;
        uint32_t da = sA + (uint32_t)(row * AST + lseg * 8) * 2;
        const void* ga = Ag + (size_t)row * K3 + lseg * 8;
        asm volatile("cp.async.cg.shared.global [%0], [%1], 16;\n" :: "r"(da), "l"(ga));
    }
    {
        uint32_t db = sB + (uint32_t)(lrow * AST + lseg * 8) * 2;
        const void* gb = Bg + (size_t)lrow * K3 + lseg * 8;
        asm volatile("cp.async.cg.shared.global [%0], [%1], 16;\n" :: "r"(db), "l"(gb));
    }
    asm volatile("cp.async.commit_group;\n");

    float acc[2][4][4] = {};

    for (int c = 0; c < NCT; c++) {
        int cur = c & 1;
        if (c + 1 < NCT) {
            int cn = c + 1;
            int blk = cn / NCV, cc = cn - blk * NCV;
            int k0 = blk * KL + cc * 32;
            int nx = cur ^ 1;
            #pragma unroll
            for (int i = 0; i < 2; i++) {
                int row = lrow + i * 64;
                uint32_t da = sA + (uint32_t)(nx * 128*AST + row * AST + lseg * 8) * 2;
                const void* ga = Ag + (size_t)row * K3 + k0 + lseg * 8;
                asm volatile("cp.async.cg.shared.global [%0], [%1], 16;\n" :: "r"(da), "l"(ga));
            }
            {
                uint32_t db = sB + (uint32_t)(nx * 64*AST + lrow * AST + lseg * 8) * 2;
                const void* gb = Bg + (size_t)lrow * K3 + k0 + lseg * 8;
                asm volatile("cp.async.cg.shared.global [%0], [%1], 16;\n" :: "r"(db), "l"(gb));
            }
            asm volatile("cp.async.commit_group;\n");
            asm volatile("cp.async.wait_group 1;\n");
        } else {
            asm volatile("cp.async.wait_group 0;\n");
        }
        __syncthreads();

        const __nv_bfloat16* Ab = &As[cur][0];
        const __nv_bfloat16* Bb = &Bs[cur][0];
        #pragma unroll
        for (int ks = 0; ks < 2; ks++) {
            int kk = ks * 16;
            uint32_t a_frag[2][4];
            uint32_t b_frag[4][2];
            #pragma unroll
            for (int mt = 0; mt < 2; mt++) {
                int r0 = (warp_m * 32 + mt * 16 + gid) * AST + kk + tig * 2;
                a_frag[mt][0] = *(const uint32_t*)(Ab + r0);
                a_frag[mt][1] = *(const uint32_t*)(Ab + r0 + 8 * AST);
                a_frag[mt][2] = *(const uint32_t*)(Ab + r0 + 8);
                a_frag[mt][3] = *(const uint32_t*)(Ab + r0 + 8 * AST + 8);
            }
            #pragma unroll
            for (int nt = 0; nt < 4; nt++) {
                int rn = (warp_n * 32 + nt * 8 + gid) * AST + kk + tig * 2;
                b_frag[nt][0] = *(const uint32_t*)(Bb + rn);
                b_frag[nt][1] = *(const uint32_t*)(Bb + rn + 8);
            }
            #pragma unroll
            for (int mt = 0; mt < 2; mt++)
                #pragma unroll
                for (int nt = 0; nt < 4; nt++)
                    MMA_BF16(acc[mt][nt], a_frag[mt], b_frag[nt]);
        }
        __syncthreads();
    }

    #pragma unroll
    for (int mt = 0; mt < 2; mt++)
        #pragma unroll
        for (int nt = 0; nt < 4; nt++) {
            int i0r = m0 + warp_m * 32 + mt * 16 + gid;
            int col = warp_n * 32 + nt * 8 + tig * 2;
            #pragma unroll
            for (int half = 0; half < 2; half++) {
                int i = i0r + half * 8;
                float vx = acc[mt][nt][half*2+0], vy = acc[mt][nt][half*2+1];
                __nv_bfloat16 hx, lx, hy, ly;
                split1(vx, hx, lx); split1(vy, hy, ly);
                __nv_bfloat162 hh; hh.x = hx; hh.y = hy;
                __nv_bfloat162 ll; ll.x = lx; ll.y = ly;
                __nv_bfloat16* r = g_a3 + (size_t)(i * BS + b) * (3*DM) + n * DH + col;
                *(__nv_bfloat162*)(r)          = hh;
                *(__nv_bfloat162*)(r + DM)     = ll;
                *(__nv_bfloat162*)(r + 2*DM)   = hh;
            }
        }
}

// ==================== conversions / prep =====================================
template<int MODE>
__global__ void split_rows_kernel(const float* __restrict__ X, __nv_bfloat16* __restrict__ Y,
                                  int kshift, long total) {
    long e = ((long)blockIdx.x * 256 + threadIdx.x) * 4;
    if (e >= total) return;
    int K = 1 << kshift;
    long r = e >> kshift; int c = (int)(e & (K - 1));
    float4 v = *(const float4*)(X + e);
    __nv_bfloat16 hx, hy, hz, hw, lx, ly, lz, lw;
    split1(v.x, hx, lx); split1(v.y, hy, ly); split1(v.z, hz, lz); split1(v.w, hw, lw);
    __nv_bfloat16* yb = Y + r * 3 * K;
    __nv_bfloat162 h01; h01.x = hx; h01.y = hy;
    __nv_bfloat162 h23; h23.x = hz; h23.y = hw;
    __nv_bfloat162 l01; l01.x = lx; l01.y = ly;
    __nv_bfloat162 l23; l23.x = lz; l23.y = lw;
    *(__nv_bfloat162*)(yb + c)       = h01; *(__nv_bfloat162*)(yb + c + 2)       = h23;
    if (MODE == 0) {
        *(__nv_bfloat162*)(yb + K + c)   = l01; *(__nv_bfloat162*)(yb + K + c + 2)   = l23;
        *(__nv_bfloat162*)(yb + 2*K + c) = h01; *(__nv_bfloat162*)(yb + 2*K + c + 2) = h23;
    } else {
        *(__nv_bfloat162*)(yb + K + c)   = h01; *(__nv_bfloat162*)(yb + K + c + 2)   = h23;
        *(__nv_bfloat162*)(yb + 2*K + c) = l01; *(__nv_bfloat162*)(yb + 2*K + c + 2) = l23;
    }
}

__global__ void split_tr_kernel(const float* __restrict__ W, __nv_bfloat16* __restrict__ Y,
                                int K, int N) {
    __shared__ float s[32][33];
    int n0 = blockIdx.x * 32, k0 = blockIdx.y * 32;
    int tx = threadIdx.x, ty = threadIdx.y;
    for (int i = ty; i < 32; i += 8)
        s[i][tx] = W[(size_t)(k0 + i) * N + n0 + tx];
    __syncthreads();
    for (int i = ty; i < 32; i += 8) {
        int n = n0 + i, k = k0 + tx;
        __nv_bfloat16 h, l; split1(s[tx][i], h, l);
        __nv_bfloat16* yb = Y + (size_t)n * 3 * K;
        yb[k] = h; yb[K + k] = h; yb[2*K + k] = l;
    }
}

__global__ void q3_kernel(const float* __restrict__ rwb, const float* __restrict__ rrb) {
    int i = blockIdx.x, bn = blockIdx.y, b = bn >> 4, n = bn & 15, d = threadIdx.x;
    float qv = g_q[((size_t)i * BS + b) * DM + n * DH + d];
    float va = qv + rwb[n * DH + d];
    float vb = qv + rrb[n * DH + d];
    __nv_bfloat16 h, l;
    split1(va, h, l);
    __nv_bfloat16* oa = g_q3a + ((size_t)bn * QL + i) * 192;
    oa[d] = h; oa[64 + d] = l; oa[128 + d] = h;
    split1(vb, h, l);
    __nv_bfloat16* ob = g_q3b + ((size_t)bn * QL + i) * 192;
    ob[d] = h; ob[64 + d] = l; ob[128 + d] = h;
}
__global__ void k3_kernel() {
    int j = blockIdx.x, bn = blockIdx.y, b = bn >> 4, n = bn & 15, d = threadIdx.x;
    float v = g_kv[((size_t)j * BS + b) * (2*DM) + n * DH + d];
    __nv_bfloat16 h, l; split1(v, h, l);
    __nv_bfloat16* o = g_k3 + ((size_t)bn * KL + j) * 192;
    o[d] = h; o[64 + d] = h; o[128 + d] = l;
}
__global__ void rk3_kernel() {
    int j = blockIdx.x, n = blockIdx.y, d = threadIdx.x;
    float v = g_rk[(size_t)j * DM + n * DH + d];
    __nv_bfloat16 h, l; split1(v, h, l);
    __nv_bfloat16* o = g_rk3 + ((size_t)n * KL + j) * 192;
    o[d] = h; o[64 + d] = h; o[128 + d] = l;
}
__global__ void vt3_kernel() {
    __shared__ float s[32][33];
    int j0 = blockIdx.x * 32, d0 = blockIdx.y * 32, bn = blockIdx.z;
    int b = bn >> 4, n = bn & 15;
    int tx = threadIdx.x, ty = threadIdx.y;
    for (int jj = ty; jj < 32; jj += 8)
        s[jj][tx] = g_kv[((size_t)(j0 + jj) * BS + b) * (2*DM) + DM + n * DH + d0 + tx];
    __syncthreads();
    for (int dd = ty; dd < 32; dd += 8) {
        __nv_bfloat16 h, l; split1(s[tx][dd], h, l);
        __nv_bfloat16* o = g_v3 + ((size_t)bn * DH + d0 + dd) * (3*KL) + j0 + tx;
        o[0] = h; o[KL] = h; o[2*KL] = l;
    }
}

// ==================== misc kernels ===========================================
__global__ void embed_kernel(const int* __restrict__ data, const float* __restrict__ embW) {
    int t = blockIdx.x;
    int tok = data[t];
    int c = threadIdx.x * 4;
    float4 v = *(const float4*)(embW + (size_t)tok * DM + c);
    *(float4*)(g_core + (size_t)t * DM + c) = v;
    __nv_bfloat16 hx, hy, hz, hw, lx, ly, lz, lw;
    split1(v.x, hx, lx); split1(v.y, hy, ly); split1(v.z, hz, lz); split1(v.w, hw, lw);
    __nv_bfloat16* yb = g_core3 + (size_t)t * (3*DM);
    __nv_bfloat162 h01; h01.x = hx; h01.y = hy;
    __nv_bfloat162 h23; h23.x = hz; h23.y = hw;
    __nv_bfloat162 l01; l01.x = lx; l01.y = ly;
    __nv_bfloat162 l23; l23.x = lz; l23.y = lw;
    *(__nv_bfloat162*)(yb + c)        = h01; *(__nv_bfloat162*)(yb + c + 2)        = h23;
    *(__nv_bfloat162*)(yb + DM + c)   = l01; *(__nv_bfloat162*)(yb + DM + c + 2)   = l23;
    *(__nv_bfloat162*)(yb + 2*DM + c) = h01; *(__nv_bfloat162*)(yb + 2*DM + c + 2) = h23;
}

__global__ void pos_kernel() {
    int p = blockIdx.x;
    float ps = (float)(KL - 1 - p);
    for (int j = threadIdx.x; j < 512; j += 256) {
        float f = powf(10000.0f, -(float)j / 512.0f);
        float a = ps * f;
        g_posbuf[p * DM + j]       = sinf(a);
        g_posbuf[p * DM + 512 + j] = cosf(a);
    }
}

__global__ void concat3_kernel(const float* __restrict__ mem_i) {
    long e = ((long)blockIdx.x * 256 + threadIdx.x) * 4;
    long r = e >> 10; int c = (int)(e & 1023);
    float4 v;
    if (r < ML * BS) v = *(const float4*)(mem_i + e);
    else             v = *(const float4*)(g_core + (r - ML*BS) * (long)DM + c);
    __nv_bfloat16 hx, hy, hz, hw, lx, ly, lz, lw;
    split1(v.x, hx, lx); split1(v.y, hy, ly); split1(v.z, hz, lz); split1(v.w, hw, lw);
    __nv_bfloat16* yb = g_a3 + r * (3*DM);
    __nv_bfloat162 h01; h01.x = hx; h01.y = hy;
    __nv_bfloat162 h23; h23.x = hz; h23.y = hw;
    __nv_bfloat162 l01; l01.x = lx; l01.y = ly;
    __nv_bfloat162 l23; l23.x = lz; l23.y = lw;
    *(__nv_bfloat162*)(yb + c)        = h01; *(__nv_bfloat162*)(yb + c + 2)        = h23;
    *(__nv_bfloat162*)(yb + DM + c)   = l01; *(__nv_bfloat162*)(yb + DM + c + 2)   = l23;
    *(__nv_bfloat162*)(yb + 2*DM + c) = h01; *(__nv_bfloat162*)(yb + 2*DM + c + 2) = h23;
}

__global__ void copyout_kernel(float* __restrict__ dst) {
    int i = blockIdx.x * 256 + threadIdx.x;
    ((float4*)dst)[i] = ((const float4*)g_core)[i];
}

__global__ void softmax_kernel() {
    int i = blockIdx.x, bn = blockIdx.y;
    const float* ac = &g_P[((size_t)bn * QL + i) * KL];
    const float* bd = &g_BD[((size_t)bn * QL + i) * KL];
    int tid = threadIdx.x;
    int lim = i + ML;
    int limW = (i & ~127) + 640; if (limW > KL) limW = KL;
    float v[4]; float mx = -1e30f;
    #pragma unroll
    for (int r = 0; r < 4; r++) {
        int j = r * 256 + tid;
        float s = (j <= lim) ? ASCALE * (ac[j] + bd[j + QL - 1 - i]) : -1e30f;
        v[r] = s; mx = fmaxf(mx, s);
    }
    __shared__ float red[256];
    red[tid] = mx; __syncthreads();
    for (int st = 128; st > 0; st >>= 1) {
        if (tid < st) red[tid] = fmaxf(red[tid], red[tid + st]);
        __syncthreads();
    }
    mx = red[0]; __syncthreads();
    float sum = 0.f;
    #pragma unroll
    for (int r = 0; r < 4; r++) { v[r] = __expf(v[r] - mx); sum += v[r]; }
    red[tid] = sum; __syncthreads();
    for (int st = 128; st > 0; st >>= 1) {
        if (tid < st) red[tid] += red[tid + st];
        __syncthreads();
    }
    float inv = 1.0f / red[0];
    __nv_bfloat16* p = g_p3 + ((size_t)bn * QL + i) * (3*KL);
    #pragma unroll
    for (int r = 0; r < 4; r++) {
        int j = r * 256 + tid;
        if (j < limW) {
            __nv_bfloat16 h, l; split1(v[r] * inv, h, l);
            p[j] = h; p[KL + j] = l; p[2*KL + j] = h;
        }
    }
}

__global__ void add_ln_kernel(float* __restrict__ io, const float* __restrict__ add,
                              const float* __restrict__ g, const float* __restrict__ bt,
                              __nv_bfloat16* __restrict__ out3) {
    int t = blockIdx.x, tid = threadIdx.x;
    size_t base = (size_t)t * DM;
    float x[4]; float s = 0.f, sq = 0.f;
    #pragma unroll
    for (int r = 0; r < 4; r++) {
        int d = r * 256 + tid;
        float v = io[base + d] + add[base + d];
        x[r] = v; s += v; sq += v * v;
    }
    __shared__ float rs[256], rq[256];
    rs[tid] = s; rq[tid] = sq; __syncthreads();
    for (int st = 128; st > 0; st >>= 1) {
        if (tid < st) { rs[tid] += rs[tid + st]; rq[tid] += rq[tid + st]; }
        __syncthreads();
    }
    float mean = rs[0] * (1.0f / DM);
    float var  = rq[0] * (1.0f / DM) - mean * mean;
    float rstd = rsqrtf(var + 1e-5f);
    __nv_bfloat16* yb = out3 + (size_t)t * (3*DM);
    #pragma unroll
    for (int r = 0; r < 4; r++) {
        int d = r * 256 + tid;
        float o = (x[r] - mean) * rstd * g[d] + bt[d];
        io[base + d] = o;
        __nv_bfloat16 h, l; split1(o, h, l);
        yb[d] = h; yb[DM + d] = l; yb[2*DM + d] = h;
    }
}

__global__ void loss2_kernel(const float2* __restrict__ part,
                             const float* __restrict__ tgtlog, float* __restrict__ out) {
    int t = blockIdx.x, tid = threadIdx.x;
    const float2* pp = part + (size_t)t * NPART;
    float m = -1e30f;
    for (int j = tid; j < NPART; j += 256) m = fmaxf(m, pp[j].x);
    __shared__ float red[256];
    red[tid] = m; __syncthreads();
    for (int st = 128; st > 0; st >>= 1) {
        if (tid < st) red[tid] = fmaxf(red[tid], red[tid + st]);
        __syncthreads();
    }
    m = red[0]; __syncthreads();
    float s = 0.f;
    for (int j = tid; j < NPART; j += 256) s += pp[j].y * __expf(pp[j].x - m);
    red[tid] = s; __syncthreads();
    for (int st = 128; st > 0; st >>= 1) {
        if (tid < st) red[tid] += red[tid + st];
        __syncthreads();
    }
    if (tid == 0)
        out[t] = m + logf(red[0]) - tgtlog[t];
}

// ==================== host orchestration =====================================
static void split_tr_s(const float* W, __nv_bfloat16* Y, int K, int N, cudaStream_t st) {
    split_tr_kernel<<<dim3(N / 32, K / 32), dim3(32, 8), 0, st>>>(W, Y, K, N);
}

extern "C" void kernel_launch(void* const* d_in, const int* in_sizes, int n_in,
                              void* d_out, int out_size) {
    const int*   data   = (const int*)d_in[0];
    const int*   target = (const int*)d_in[1];
    const float* memory = (const float*)d_in[2];
    const float* embW   = (const float*)d_in[3];
    const float* rwb    = (const float*)d_in[4];
    const float* rrb    = (const float*)d_in[5];
    const float* Wq     = (const float*)d_in[6];
    const float* Wkv    = (const float*)d_in[7];
    const float* Wr     = (const float*)d_in[8];
    const float* Wo     = (const float*)d_in[9];
    const float* W1     = (const float*)d_in[10];
    const float* b1     = (const float*)d_in[11];
    const float* W2     = (const float*)d_in[12];
    const float* b2     = (const float*)d_in[13];
    const float* ln1g   = (const float*)d_in[14];
    const float* ln1b   = (const float*)d_in[15];
    const float* ln2g   = (const float*)d_in[16];
    const float* ln2b   = (const float*)d_in[17];

    float* out = (float*)d_out;
    const long SLAB = (long)ML * BS * DM;
    float* out_mems = (out_size >= 4096L + NLAY * SLAB) ? out + 4096 : nullptr;

    float *p_core, *p_q, *p_kv, *p_pos, *p_rk, *p_tmp, *p_P, *p_BD, *p_lse;
    __nv_bfloat16 *p_a3, *p_core3, *p_emb3, *p_pos3, *p_q3a, *p_q3b, *p_k3, *p_rk3;
    __nv_bfloat16 *p_wq3, *p_wkv3, *p_wr3, *p_wo3, *p_w13, *p_w23;
    cudaGetSymbolAddress((void**)&p_core,   g_core);
    cudaGetSymbolAddress((void**)&p_q,      g_q);
    cudaGetSymbolAddress((void**)&p_kv,     g_kv);
    cudaGetSymbolAddress((void**)&p_pos,    g_posbuf);
    cudaGetSymbolAddress((void**)&p_rk,     g_rk);
    cudaGetSymbolAddress((void**)&p_tmp,    g_tmp);
    cudaGetSymbolAddress((void**)&p_lse,    g_lsebuf);
    cudaGetSymbolAddress((void**)&p_P,      g_P);
    cudaGetSymbolAddress((void**)&p_BD,     g_BD);
    cudaGetSymbolAddress((void**)&p_a3,     g_a3);
    cudaGetSymbolAddress((void**)&p_core3,  g_core3);
    cudaGetSymbolAddress((void**)&p_emb3,   g_emb3);
    cudaGetSymbolAddress((void**)&p_pos3,   g_pos3);
    cudaGetSymbolAddress((void**)&p_q3a,    g_q3a);
    cudaGetSymbolAddress((void**)&p_q3b,    g_q3b);
    cudaGetSymbolAddress((void**)&p_k3,     g_k3);
    cudaGetSymbolAddress((void**)&p_rk3,    g_rk3);
    cudaGetSymbolAddress((void**)&p_wq3,    g_wq3);
    cudaGetSymbolAddress((void**)&p_wkv3,   g_wkv3);
    cudaGetSymbolAddress((void**)&p_wr3,    g_wr3);
    cudaGetSymbolAddress((void**)&p_wo3,    g_wo3);
    cudaGetSymbolAddress((void**)&p_w13,    g_w13);
    cudaGetSymbolAddress((void**)&p_w23,    g_w23);

    float2* p_part = (float2*)p_lse;
    float*  p_tgt  = p_lse + (size_t)NQ * NPART * 2;

    // streams/events: created once (resource init only; per-call work identical)
    static cudaStream_t s_a = nullptr, s_b = nullptr;
    static cudaEvent_t  s_ev[32];
    if (!s_a) {
        cudaStreamCreateWithFlags(&s_a, cudaStreamNonBlocking);
        cudaStreamCreateWithFlags(&s_b, cudaStreamNonBlocking);
        for (int i = 0; i < 32; i++) cudaEventCreateWithFlags(&s_ev[i], cudaEventDisableTiming);
    }
    cudaStream_t sa = s_a, sb = s_b;
    cudaEvent_t* E0  = s_ev;         // [6]
    cudaEvent_t* EA  = s_ev + 6;     // [6]
    cudaEvent_t* EB  = s_ev + 12;    // [6]
    cudaEvent_t* EBD = s_ev + 18;    // [6]
    cudaEvent_t  Estart = s_ev[24], EsplitA = s_ev[25], EsplitB = s_ev[26];

    // ---- fork: weight splits on sa/sb; embed/pos on default stream ----------
    cudaEventRecord(Estart, 0);
    cudaStreamWaitEvent(sa, Estart, 0);
    cudaStreamWaitEvent(sb, Estart, 0);
    {   // emb3 (biggest) on sb; weights alternated
        long total = (long)NV * DM;
        split_rows_kernel<1><<<(int)(total / 4 / 256), 256, 0, sb>>>(embW, p_emb3, 10, total);
    }
    for (int L = 0; L < NLAY; L++) {
        split_tr_s(Wkv + (long)L*DM*2*DM, p_wkv3 + (size_t)L*2*DM*3*DM, DM, 2*DM, sa);
        split_tr_s(W1  + (long)L*DM*DI,   p_w13  + (size_t)L*DI*3*DM,   DM, DI,   sa);
        split_tr_s(Wq  + (long)L*DM*DM,   p_wq3  + (size_t)L*DM*3*DM,   DM, DM,   sa);
        split_tr_s(W2  + (long)L*DI*DM,   p_w23  + (size_t)L*DM*3*DI,   DI, DM,   sb);
        split_tr_s(Wr  + (long)L*DM*DM,   p_wr3  + (size_t)L*DM*3*DM,   DM, DM,   sb);
        split_tr_s(Wo  + (long)L*DM*DM,   p_wo3  + (size_t)L*DM*3*DM,   DM, DM,   sb);
    }
    cudaEventRecord(EsplitA, sa);
    cudaEventRecord(EsplitB, sb);
    embed_kernel<<<NQ, 256>>>(data, embW);
    pos_kernel<<<KL, 256>>>();
    {
        long total = (long)KL * DM;
        split_rows_kernel<0><<<(int)(total / 4 / 256), 256>>>(p_pos, p_pos3, 10, total);
    }
    cudaStreamWaitEvent(0, EsplitA, 0);
    cudaStreamWaitEvent(0, EsplitB, 0);

    for (int L = 0; L < NLAY; L++) {
        cudaEventRecord(E0[L], 0);
        // --- SA: q chain ---
        cudaStreamWaitEvent(sa, E0[L], 0);
        tc_gemm<0><<<dim3(8, 32), 256, 0, sa>>>(p_core3, p_wq3 + (size_t)L*DM*3*DM,
                                                p_q, nullptr, NQ, DM, 3*DM);
        q3_kernel<<<dim3(QL, 128), 64, 0, sa>>>(rwb, rrb);
        cudaEventRecord(EA[L], sa);
        // --- SB: copyout + rk chain ---
        cudaStreamWaitEvent(sb, E0[L], 0);
        if (out_mems)
            copyout_kernel<<<4096, 256, 0, sb>>>(out_mems + (long)L * SLAB);
        tc_gemm<0><<<dim3(8, 8), 256, 0, sb>>>(p_pos3, p_wr3 + (size_t)L*DM*3*DM,
                                               p_rk, nullptr, KL, DM, 3*DM);
        rk3_kernel<<<dim3(KL, NH), 64, 0, sb>>>();
        cudaEventRecord(EB[L], sb);
        // --- S0: kv chain ---
        concat3_kernel<<<(int)((long)NK * DM / 4 / 256), 256>>>(memory + (long)L * SLAB);
        tc_gemm<0><<<dim3(16, 64), 256>>>(p_a3, p_wkv3 + (size_t)L*2*DM*3*DM,
                                          p_kv, nullptr, NK, 2*DM, 3*DM);
        k3_kernel<<<dim3(KL, 128), 64>>>();
        vt3_kernel<<<dim3(KL/32, DH/32, 128), dim3(32, 8)>>>();
        // --- AC on S0 (needs q3a via EA; k3 in-order) ---
        cudaStreamWaitEvent(0, EA[L], 0);
        tc_gemm_bat<<<dim3(KL/128, QL/128, 128), 256>>>(
            p_q3a, (long)QL*192, p_k3, (long)KL*192, 127,
            p_P, (long)QL*KL, KL, 192, 1);
        // --- BD on SA (q3b in-order; rk3 via EB) ---
        cudaStreamWaitEvent(sa, EB[L], 0);
        tc_gemm_bat<<<dim3(KL/128, QL/128, 128), 256, 0, sa>>>(
            p_q3b, (long)QL*192, p_rk3, (long)KL*192, 15,
            p_BD, (long)QL*KL, KL, 192, 2);
        cudaEventRecord(EBD[L], sa);
        // --- S0: softmax -> pv -> Wo -> LN1 -> FF -> LN2 ---
        cudaStreamWaitEvent(0, EBD[L], 0);
        softmax_kernel<<<dim3(QL, 128), 256>>>();
        pv_gemm<<<dim3(1, QL/128, 128), 256>>>();
        tc_gemm<0><<<dim3(8, 32), 256>>>(p_a3, p_wo3 + (size_t)L*DM*3*DM,
                                         p_tmp, nullptr, NQ, DM, 3*DM);
        add_ln_kernel<<<NQ, 256>>>(p_core, p_tmp, ln1g + L*DM, ln1b + L*DM, p_core3);
        tc_gemm_relu3<<<dim3(32, 32), 256>>>(p_core3, p_w13 + (size_t)L*DI*3*DM,
                                             p_a3, b1 + L*DI, NQ, DI, 3*DM);
        tc_gemm<1><<<dim3(8, 32), 256>>>(p_a3, p_w23 + (size_t)L*DM*3*DI,
                                         p_tmp, b2 + L*DM, NQ, DM, 3*DI);
        add_ln_kernel<<<NQ, 256>>>(p_core, p_tmp, ln2g + L*DM, ln2b + L*DM, p_core3);
    }

    // logits + fused LSE ; loss (S0; all forked streams joined via EBD/EB chain)
    tc_gemm_lse<<<dim3(NQ/128, NV/128), 256>>>(p_core3, p_emb3, target,
                                               p_part, p_tgt, 3*DM);
    loss2_kernel<<<NQ, 256>>>(p_part, p_tgt, out);
}

// round 15
// speedup vs baseline: 1.9392x; 1.0241x over previous
#include <cuda_runtime.h>
#include <cuda_bf16.h>
#include <math.h>
#include <stdint.h>

#define QL 512
#define ML 512
#define KL 1024
#define BS 8
#define NH 16
#define DH 64
#define DM 1024
#define DI 4096
#define NV 32000
#define NLAY 6
#define NQ (QL*BS)
#define NK (KL*BS)
#define ASCALE 0.125f
#define NTILE (NV/128)
#define NPART (NTILE*4)

// ---------------- persistent scratch ----------------------------------------
static __device__ float g_core[NQ*DM];
static __device__ float g_kvV[(size_t)NK*DM];                // compact V (fp32)
static __device__ float g_posbuf[KL*DM];
static __device__ float g_P[(size_t)BS*NH*QL*KL];
static __device__ float g_BD[(size_t)BS*NH*QL*KL];
static __device__ float g_tmp[NQ*DM];
static __device__ float g_lsebuf[(size_t)NQ*NPART*2 + NQ];
// bf16 triple-K operand buffers
static __device__ __nv_bfloat16 g_a3[(size_t)NQ*3*DI];       // xk3 / att3 / ff3 (time-shared)
static __device__ __nv_bfloat16 g_core3[(size_t)NQ*3*DM];
static __device__ __nv_bfloat16 g_emb3[(size_t)NV*3*DM];
static __device__ __nv_bfloat16 g_pos3[(size_t)KL*3*DM];
// per-layer pre-split weights (B-layout [h|h|l])
static __device__ __nv_bfloat16 g_wq3 [(size_t)NLAY*DM*3*DM];
static __device__ __nv_bfloat16 g_wkv3[(size_t)NLAY*2*DM*3*DM];
static __device__ __nv_bfloat16 g_wr3 [(size_t)NLAY*DM*3*DM];
static __device__ __nv_bfloat16 g_wo3 [(size_t)NLAY*DM*3*DM];
static __device__ __nv_bfloat16 g_w13 [(size_t)NLAY*DI*3*DM];
static __device__ __nv_bfloat16 g_w23 [(size_t)NLAY*DM*3*DI];
// attention operands
static __device__ __nv_bfloat16 g_q3a[(size_t)BS*NH*QL*192];
static __device__ __nv_bfloat16 g_q3b[(size_t)BS*NH*QL*192];
static __device__ __nv_bfloat16 g_k3 [(size_t)BS*NH*KL*192];
static __device__ __nv_bfloat16 g_rk3[(size_t)NH*KL*192];
static __device__ __nv_bfloat16 g_v3 [(size_t)BS*NH*DH*3*KL];
static __device__ __nv_bfloat16 g_p3 [(size_t)BS*NH*QL*3*KL];

__device__ __forceinline__ uint32_t smem_u32(const void* p) {
    uint32_t a;
    asm("{ .reg .u64 t; cvta.to.shared.u64 t, %1; cvt.u32.u64 %0, t; }" : "=r"(a) : "l"(p));
    return a;
}
__device__ __forceinline__ void split1(float v, __nv_bfloat16& h, __nv_bfloat16& l) {
    h = __float2bfloat16(v);
    l = __float2bfloat16(v - __bfloat162float(h));
}
// pack two values into h/l bf162 pairs
__device__ __forceinline__ void split2(float vx, float vy, __nv_bfloat162& hh, __nv_bfloat162& ll) {
    __nv_bfloat16 hx, lx, hy, ly;
    split1(vx, hx, lx); split1(vy, hy, ly);
    hh.x = hx; hh.y = hy; ll.x = lx; ll.y = ly;
}

#define MMA_BF16(acc, af, bf) \
    asm volatile("mma.sync.aligned.m16n8k16.row.col.f32.bf16.bf16.f32 " \
        "{%0,%1,%2,%3}, {%4,%5,%6,%7}, {%8,%9}, {%0,%1,%2,%3};\n" \
        : "+f"((acc)[0]), "+f"((acc)[1]), "+f"((acc)[2]), "+f"((acc)[3]) \
        : "r"((af)[0]), "r"((af)[1]), "r"((af)[2]), "r"((af)[3]), \
          "r"((bf)[0]), "r"((bf)[1]))

#define AST 40
#define TILE_ELEMS (128*AST)

#define GEMM_MAINLOOP()                                                        \
    uint32_t sA = smem_u32(As), sB = smem_u32(Bs);                             \
    int lrow = tid >> 2, lseg = tid & 3;                                       \
    _Pragma("unroll")                                                          \
    for (int i = 0; i < 2; i++) {                                              \
        int row = lrow + i * 64;                                               \
        uint32_t da = sA + (uint32_t)(row * AST + lseg * 8) * 2;               \
        uint32_t db = sB + (uint32_t)(row * AST + lseg * 8) * 2;               \
        const void* ga = Ag + (size_t)row * K3 + lseg * 8;                     \
        const void* gb = Bg + (size_t)row * K3 + lseg * 8;                     \
        asm volatile("cp.async.cg.shared.global [%0], [%1], 16;\n" :: "r"(da), "l"(ga)); \
        asm volatile("cp.async.cg.shared.global [%0], [%1], 16;\n" :: "r"(db), "l"(gb)); \
    }                                                                          \
    asm volatile("cp.async.commit_group;\n");                                  \
    for (int c = 0; c < NC; c++) {                                             \
        int cur = c & 1;                                                       \
        if (c + 1 < NC) {                                                      \
            int nx = cur ^ 1, k0 = (c + 1) * 32;                               \
            _Pragma("unroll")                                                  \
            for (int i = 0; i < 2; i++) {                                      \
                int row = lrow + i * 64;                                       \
                uint32_t da = sA + (uint32_t)(nx * TILE_ELEMS + row * AST + lseg * 8) * 2; \
                uint32_t db = sB + (uint32_t)(nx * TILE_ELEMS + row * AST + lseg * 8) * 2; \
                const void* ga = Ag + (size_t)row * K3 + k0 + lseg * 8;        \
                const void* gb = Bg + (size_t)row * K3 + k0 + lseg * 8;        \
                asm volatile("cp.async.cg.shared.global [%0], [%1], 16;\n" :: "r"(da), "l"(ga)); \
                asm volatile("cp.async.cg.shared.global [%0], [%1], 16;\n" :: "r"(db), "l"(gb)); \
            }                                                                  \
            asm volatile("cp.async.commit_group;\n");                          \
            asm volatile("cp.async.wait_group 1;\n");                          \
        } else {                                                               \
            asm volatile("cp.async.wait_group 0;\n");                          \
        }                                                                      \
        __syncthreads();                                                       \
        const __nv_bfloat16* Ab = &As[cur][0];                                 \
        const __nv_bfloat16* Bb = &Bs[cur][0];                                 \
        _Pragma("unroll")                                                      \
        for (int ks = 0; ks < 2; ks++) {                                       \
            int kk = ks * 16;                                                  \
            uint32_t a_frag[4][4];                                             \
            uint32_t b_frag[4][2];                                             \
            _Pragma("unroll")                                                  \
            for (int mt = 0; mt < 4; mt++) {                                   \
                int r0 = (warp_m * 64 + mt * 16 + gid) * AST + kk + tig * 2;   \
                a_frag[mt][0] = *(const uint32_t*)(Ab + r0);                   \
                a_frag[mt][1] = *(const uint32_t*)(Ab + r0 + 8 * AST);         \
                a_frag[mt][2] = *(const uint32_t*)(Ab + r0 + 8);               \
                a_frag[mt][3] = *(const uint32_t*)(Ab + r0 + 8 * AST + 8);     \
            }                                                                  \
            _Pragma("unroll")                                                  \
            for (int nt = 0; nt < 4; nt++) {                                   \
                int rn = (warp_n * 32 + nt * 8 + gid) * AST + kk + tig * 2;    \
                b_frag[nt][0] = *(const uint32_t*)(Bb + rn);                   \
                b_frag[nt][1] = *(const uint32_t*)(Bb + rn + 8);               \
            }                                                                  \
            _Pragma("unroll")                                                  \
            for (int mt = 0; mt < 4; mt++)                                     \
                _Pragma("unroll")                                              \
                for (int nt = 0; nt < 4; nt++)                                 \
                    MMA_BF16(acc[mt][nt], a_frag[mt], b_frag[nt]);             \
        }                                                                      \
        __syncthreads();                                                       \
    }

// ---- generic GEMM, fp32 C, optional bias ------------------------------------
template<int EPI>
__global__ __launch_bounds__(256, 2)
void tc_gemm(const __nv_bfloat16* __restrict__ A3, const __nv_bfloat16* __restrict__ B3,
             float* __restrict__ C, const float* __restrict__ bias,
             int M, int N, int K3) {
    __shared__ __align__(16) __nv_bfloat16 As[2][TILE_ELEMS];
    __shared__ __align__(16) __nv_bfloat16 Bs[2][TILE_ELEMS];
    int tid = threadIdx.x, wid = tid >> 5, lane = tid & 31;
    int warp_m = wid >> 2, warp_n = wid & 3;
    int gid = lane >> 2, tig = lane & 3;
    int n0 = blockIdx.x * 128, m0 = blockIdx.y * 128;
    const __nv_bfloat16* Ag = A3 + (size_t)m0 * K3;
    const __nv_bfloat16* Bg = B3 + (size_t)n0 * K3;
    int NC = K3 >> 5;
    float acc[4][4][4] = {};
    GEMM_MAINLOOP()
    #pragma unroll
    for (int mt = 0; mt < 4; mt++)
        #pragma unroll
        for (int nt = 0; nt < 4; nt++) {
            int row0 = m0 + warp_m * 64 + mt * 16 + gid;
            int col  = n0 + warp_n * 32 + nt * 8 + tig * 2;
            float2 v0, v1;
            v0.x = acc[mt][nt][0]; v0.y = acc[mt][nt][1];
            v1.x = acc[mt][nt][2]; v1.y = acc[mt][nt][3];
            if (EPI >= 1) {
                float bx = bias[col], by = bias[col + 1];
                v0.x += bx; v0.y += by; v1.x += bx; v1.y += by;
            }
            *(float2*)(C + (size_t)row0 * N + col)       = v0;
            *(float2*)(C + (size_t)(row0 + 8) * N + col) = v1;
        }
}

// ---- q-GEMM: N=DM; epilogue adds rwb/rrb, writes q3a/q3b (A-layout, head idx)
__global__ __launch_bounds__(256, 2)
void tc_gemm_q(const __nv_bfloat16* __restrict__ A3, const __nv_bfloat16* __restrict__ B3,
               const float* __restrict__ rwb, const float* __restrict__ rrb, int K3) {
    __shared__ __align__(16) __nv_bfloat16 As[2][TILE_ELEMS];
    __shared__ __align__(16) __nv_bfloat16 Bs[2][TILE_ELEMS];
    int tid = threadIdx.x, wid = tid >> 5, lane = tid & 31;
    int warp_m = wid >> 2, warp_n = wid & 3;
    int gid = lane >> 2, tig = lane & 3;
    int n0 = blockIdx.x * 128, m0 = blockIdx.y * 128;
    const __nv_bfloat16* Ag = A3 + (size_t)m0 * K3;
    const __nv_bfloat16* Bg = B3 + (size_t)n0 * K3;
    int NC = K3 >> 5;
    float acc[4][4][4] = {};
    GEMM_MAINLOOP()
    #pragma unroll
    for (int mt = 0; mt < 4; mt++)
        #pragma unroll
        for (int nt = 0; nt < 4; nt++) {
            int row0 = m0 + warp_m * 64 + mt * 16 + gid;
            int col  = n0 + warp_n * 32 + nt * 8 + tig * 2;
            int n = col >> 6, d = col & 63;
            float wax = rwb[col], way = rwb[col + 1];
            float wbx = rrb[col], wby = rrb[col + 1];
            #pragma unroll
            for (int half = 0; half < 2; half++) {
                int row = row0 + half * 8;          // i*8+b
                int i = row >> 3, b = row & 7;
                float vx = acc[mt][nt][half*2+0], vy = acc[mt][nt][half*2+1];
                __nv_bfloat162 hh, ll;
                size_t base = ((size_t)(b * 16 + n) * QL + i) * 192 + d;
                split2(vx + wax, vy + way, hh, ll);
                *(__nv_bfloat162*)(g_q3a + base)       = hh;
                *(__nv_bfloat162*)(g_q3a + base + 64)  = ll;
                *(__nv_bfloat162*)(g_q3a + base + 128) = hh;
                split2(vx + wbx, vy + wby, hh, ll);
                *(__nv_bfloat162*)(g_q3b + base)       = hh;
                *(__nv_bfloat162*)(g_q3b + base + 64)  = ll;
                *(__nv_bfloat162*)(g_q3b + base + 128) = hh;
            }
        }
}

// ---- kv-GEMM: N=2*DM; K half -> g_k3 (B-layout), V half -> compact fp32 -----
__global__ __launch_bounds__(256, 2)
void tc_gemm_kv(const __nv_bfloat16* __restrict__ A3, const __nv_bfloat16* __restrict__ B3,
                int K3) {
    __shared__ __align__(16) __nv_bfloat16 As[2][TILE_ELEMS];
    __shared__ __align__(16) __nv_bfloat16 Bs[2][TILE_ELEMS];
    int tid = threadIdx.x, wid = tid >> 5, lane = tid & 31;
    int warp_m = wid >> 2, warp_n = wid & 3;
    int gid = lane >> 2, tig = lane & 3;
    int n0 = blockIdx.x * 128, m0 = blockIdx.y * 128;
    const __nv_bfloat16* Ag = A3 + (size_t)m0 * K3;
    const __nv_bfloat16* Bg = B3 + (size_t)n0 * K3;
    int NC = K3 >> 5;
    float acc[4][4][4] = {};
    GEMM_MAINLOOP()
    #pragma unroll
    for (int mt = 0; mt < 4; mt++)
        #pragma unroll
        for (int nt = 0; nt < 4; nt++) {
            int row0 = m0 + warp_m * 64 + mt * 16 + gid;
            int col  = n0 + warp_n * 32 + nt * 8 + tig * 2;
            #pragma unroll
            for (int half = 0; half < 2; half++) {
                int row = row0 + half * 8;          // j*8+b
                float vx = acc[mt][nt][half*2+0], vy = acc[mt][nt][half*2+1];
                if (col < DM) {
                    int j = row >> 3, b = row & 7;
                    int n = col >> 6, d = col & 63;
                    __nv_bfloat162 hh, ll;
                    split2(vx, vy, hh, ll);
                    __nv_bfloat16* o = g_k3 + ((size_t)(b * 16 + n) * KL + j) * 192 + d;
                    *(__nv_bfloat162*)(o)       = hh;   // B-layout [h|h|l]
                    *(__nv_bfloat162*)(o + 64)  = hh;
                    *(__nv_bfloat162*)(o + 128) = ll;
                } else {
                    float2 v; v.x = vx; v.y = vy;
                    *(float2*)(g_kvV + (size_t)row * DM + (col - DM)) = v;
                }
            }
        }
}

// ---- rk-GEMM: M=KL, N=DM; epilogue writes rk3 (B-layout, head idx) ----------
__global__ __launch_bounds__(256, 2)
void tc_gemm_rk(const __nv_bfloat16* __restrict__ A3, const __nv_bfloat16* __restrict__ B3,
                int K3) {
    __shared__ __align__(16) __nv_bfloat16 As[2][TILE_ELEMS];
    __shared__ __align__(16) __nv_bfloat16 Bs[2][TILE_ELEMS];
    int tid = threadIdx.x, wid = tid >> 5, lane = tid & 31;
    int warp_m = wid >> 2, warp_n = wid & 3;
    int gid = lane >> 2, tig = lane & 3;
    int n0 = blockIdx.x * 128, m0 = blockIdx.y * 128;
    const __nv_bfloat16* Ag = A3 + (size_t)m0 * K3;
    const __nv_bfloat16* Bg = B3 + (size_t)n0 * K3;
    int NC = K3 >> 5;
    float acc[4][4][4] = {};
    GEMM_MAINLOOP()
    #pragma unroll
    for (int mt = 0; mt < 4; mt++)
        #pragma unroll
        for (int nt = 0; nt < 4; nt++) {
            int row0 = m0 + warp_m * 64 + mt * 16 + gid;
            int col  = n0 + warp_n * 32 + nt * 8 + tig * 2;
            int n = col >> 6, d = col & 63;
            #pragma unroll
            for (int half = 0; half < 2; half++) {
                int j = row0 + half * 8;
                float vx = acc[mt][nt][half*2+0], vy = acc[mt][nt][half*2+1];
                __nv_bfloat162 hh, ll;
                split2(vx, vy, hh, ll);
                __nv_bfloat16* o = g_rk3 + ((size_t)n * KL + j) * 192 + d;
                *(__nv_bfloat162*)(o)       = hh;
                *(__nv_bfloat162*)(o + 64)  = hh;
                *(__nv_bfloat162*)(o + 128) = ll;
            }
        }
}

// ---- logits GEMM with fused LSE-partials epilogue ---------------------------
__global__ __launch_bounds__(256, 2)
void tc_gemm_lse(const __nv_bfloat16* __restrict__ A3, const __nv_bfloat16* __restrict__ B3,
                 const int* __restrict__ target,
                 float2* __restrict__ part, float* __restrict__ tgtlog, int K3) {
    __shared__ __align__(16) __nv_bfloat16 As[2][TILE_ELEMS];
    __shared__ __align__(16) __nv_bfloat16 Bs[2][TILE_ELEMS];
    int tid = threadIdx.x, wid = tid >> 5, lane = tid & 31;
    int warp_m = wid >> 2, warp_n = wid & 3;
    int gid = lane >> 2, tig = lane & 3;
    int bxn = blockIdx.y;
    int n0 = bxn * 128, m0 = blockIdx.x * 128;
    const __nv_bfloat16* Ag = A3 + (size_t)m0 * K3;
    const __nv_bfloat16* Bg = B3 + (size_t)n0 * K3;
    int NC = K3 >> 5;
    float acc[4][4][4] = {};
    GEMM_MAINLOOP()
    #pragma unroll
    for (int mt = 0; mt < 4; mt++) {
        #pragma unroll
        for (int half = 0; half < 2; half++) {
            int row = m0 + warp_m * 64 + mt * 16 + gid + half * 8;
            int tgt = target[row];
            float m = -1e30f;
            #pragma unroll
            for (int nt = 0; nt < 4; nt++) {
                float vx = acc[mt][nt][half*2+0], vy = acc[mt][nt][half*2+1];
                int col = n0 + warp_n * 32 + nt * 8 + tig * 2;
                if (col == tgt)     tgtlog[row] = vx;
                if (col + 1 == tgt) tgtlog[row] = vy;
                m = fmaxf(m, fmaxf(vx, vy));
            }
            float s = 0.f;
            #pragma unroll
            for (int nt = 0; nt < 4; nt++) {
                s += __expf(acc[mt][nt][half*2+0] - m);
                s += __expf(acc[mt][nt][half*2+1] - m);
            }
            #pragma unroll
            for (int off = 1; off < 4; off <<= 1) {
                float om = __shfl_xor_sync(0xffffffff, m, off);
                float os = __shfl_xor_sync(0xffffffff, s, off);
                float nm = fmaxf(m, om);
                s = s * __expf(m - nm) + os * __expf(om - nm);
                m = nm;
            }
            if (tig == 0) {
                float2 p; p.x = m; p.y = s;
                part[(size_t)row * NPART + bxn * 4 + warp_n] = p;
            }
        }
    }
}

// ---- W1 GEMM: relu(x+bias) -> bf16x3 A-layout directly ----------------------
__global__ __launch_bounds__(256, 2)
void tc_gemm_relu3(const __nv_bfloat16* __restrict__ A3, const __nv_bfloat16* __restrict__ B3,
                   __nv_bfloat16* __restrict__ Cb, const float* __restrict__ bias,
                   int M, int N, int K3) {
    __shared__ __align__(16) __nv_bfloat16 As[2][TILE_ELEMS];
    __shared__ __align__(16) __nv_bfloat16 Bs[2][TILE_ELEMS];
    int tid = threadIdx.x, wid = tid >> 5, lane = tid & 31;
    int warp_m = wid >> 2, warp_n = wid & 3;
    int gid = lane >> 2, tig = lane & 3;
    int n0 = blockIdx.x * 128, m0 = blockIdx.y * 128;
    const __nv_bfloat16* Ag = A3 + (size_t)m0 * K3;
    const __nv_bfloat16* Bg = B3 + (size_t)n0 * K3;
    int NC = K3 >> 5;
    float acc[4][4][4] = {};
    GEMM_MAINLOOP()
    #pragma unroll
    for (int mt = 0; mt < 4; mt++)
        #pragma unroll
        for (int nt = 0; nt < 4; nt++) {
            int row0 = m0 + warp_m * 64 + mt * 16 + gid;
            int col  = n0 + warp_n * 32 + nt * 8 + tig * 2;
            float bx = bias[col], by = bias[col + 1];
            #pragma unroll
            for (int half = 0; half < 2; half++) {
                float vx = fmaxf(acc[mt][nt][half*2+0] + bx, 0.f);
                float vy = fmaxf(acc[mt][nt][half*2+1] + by, 0.f);
                __nv_bfloat162 hh, ll;
                split2(vx, vy, hh, ll);
                __nv_bfloat16* r = Cb + (size_t)(row0 + half*8) * (3*N) + col;
                *(__nv_bfloat162*)(r)         = hh;
                *(__nv_bfloat162*)(r + N)     = ll;
                *(__nv_bfloat162*)(r + 2*N)   = hh;
            }
        }
}

// ---- batched AC/BD scores with dead-tile skipping ---------------------------
__global__ __launch_bounds__(256, 2)
void tc_gemm_bat(const __nv_bfloat16* __restrict__ A3, long strideA,
                 const __nv_bfloat16* __restrict__ B3, long strideB, int bmask,
                 float* __restrict__ C, long strideC, int ldc,
                 int K3, int skip_mode) {
    int n0 = blockIdx.x * 128, m0 = blockIdx.y * 128, bz = blockIdx.z;
    if (skip_mode == 1 && n0 >= m0 + 640) return;
    if (skip_mode == 2 && n0 + m0 <= 256) return;
    __shared__ __align__(16) __nv_bfloat16 As[2][TILE_ELEMS];
    __shared__ __align__(16) __nv_bfloat16 Bs[2][TILE_ELEMS];
    int tid = threadIdx.x, wid = tid >> 5, lane = tid & 31;
    int warp_m = wid >> 2, warp_n = wid & 3;
    int gid = lane >> 2, tig = lane & 3;
    const __nv_bfloat16* Ag = A3 + (size_t)bz * strideA + (size_t)m0 * K3;
    const __nv_bfloat16* Bg = B3 + (size_t)(bz & bmask) * strideB + (size_t)n0 * K3;
    float* Cg = C + (size_t)bz * strideC;
    int NC = K3 >> 5;
    float acc[4][4][4] = {};
    GEMM_MAINLOOP()
    #pragma unroll
    for (int mt = 0; mt < 4; mt++)
        #pragma unroll
        for (int nt = 0; nt < 4; nt++) {
            int row0 = m0 + warp_m * 64 + mt * 16 + gid;
            int col  = n0 + warp_n * 32 + nt * 8 + tig * 2;
            float2 v0, v1;
            v0.x = acc[mt][nt][0]; v0.y = acc[mt][nt][1];
            v1.x = acc[mt][nt][2]; v1.y = acc[mt][nt][3];
            *(float2*)(Cg + (size_t)row0 * ldc + col)       = v0;
            *(float2*)(Cg + (size_t)(row0 + 8) * ldc + col) = v1;
        }
}

// ---- PV: 128x64 per (b,n); masked K-chunk skip; writes att3 into g_a3 -------
__global__ __launch_bounds__(256, 2)
void pv_gemm() {
    __shared__ __align__(16) __nv_bfloat16 As[2][128*AST];
    __shared__ __align__(16) __nv_bfloat16 Bs[2][64*AST];
    int tid = threadIdx.x, wid = tid >> 5, lane = tid & 31;
    int warp_m = wid >> 1, warp_n = wid & 1;
    int gid = lane >> 2, tig = lane & 3;
    int m0 = blockIdx.y * 128, bz = blockIdx.z;
    int b = bz >> 4, n = bz & 15;
    const int K3 = 3 * KL;
    int NCV = (m0 >> 5) + 20; if (NCV > 32) NCV = 32;
    int NCT = 3 * NCV;
    const __nv_bfloat16* Ag = g_p3 + ((size_t)bz * QL + m0) * K3;
    const __nv_bfloat16* Bg = g_v3 + (size_t)bz * DH * K3;
    uint32_t sA = smem_u32(As), sB = smem_u32(Bs);
    int lrow = tid >> 2, lseg = tid & 3;

    #pragma unroll
    for (int i = 0; i < 2; i++) {
        int row = lrow + i * 64;
        uint32_t da = sA + (uint32_t)(row * AST + lseg * 8) * 2;
        const void* ga = Ag + (size_t)row * K3 + lseg * 8;
        asm volatile("cp.async.cg.shared.global [%0], [%1], 16;\n" :: "r"(da), "l"(ga));
    }
    {
        uint32_t db = sB + (uint32_t)(lrow * AST + lseg * 8) * 2;
        const void* gb = Bg + (size_t)lrow * K3 + lseg * 8;
        asm volatile("cp.async.cg.shared.global [%0], [%1], 16;\n" :: "r"(db), "l"(gb));
    }
    asm volatile("cp.async.commit_group;\n");

    float acc[2][4][4] = {};

    for (int c = 0; c < NCT; c++) {
        int cur = c & 1;
        if (c + 1 < NCT) {
            int cn = c + 1;
            int blk = cn / NCV, cc = cn - blk * NCV;
            int k0 = blk * KL + cc * 32;
            int nx = cur ^ 1;
            #pragma unroll
            for (int i = 0; i < 2; i++) {
                int row = lrow + i * 64;
                uint32_t da = sA + (uint32_t)(nx * 128*AST + row * AST + lseg * 8) * 2;
                const void* ga = Ag + (size_t)row * K3 + k0 + lseg * 8;
                asm volatile("cp.async.cg.shared.global [%0], [%1], 16;\n" :: "r"(da), "l"(ga));
            }
            {
                uint32_t db = sB + (uint32_t)(nx * 64*AST + lrow * AST + lseg * 8) * 2;
                const void* gb = Bg + (size_t)lrow * K3 + k0 + lseg * 8;
                asm volatile("cp.async.cg.shared.global [%0], [%1], 16;\n" :: "r"(db), "l"(gb));
            }
            asm volatile("cp.async.commit_group;\n");
            asm volatile("cp.async.wait_group 1;\n");
        } else {
            asm volatile("cp.async.wait_group 0;\n");
        }
        __syncthreads();

        const __nv_bfloat16* Ab = &As[cur][0];
        const __nv_bfloat16* Bb = &Bs[cur][0];
        #pragma unroll
        for (int ks = 0; ks < 2; ks++) {
            int kk = ks * 16;
            uint32_t a_frag[2][4];
            uint32_t b_frag[4][2];
            #pragma unroll
            for (int mt = 0; mt < 2; mt++) {
                int r0 = (warp_m * 32 + mt * 16 + gid) * AST + kk + tig * 2;
                a_frag[mt][0] = *(const uint32_t*)(Ab + r0);
                a_frag[mt][1] = *(const uint32_t*)(Ab + r0 + 8 * AST);
                a_frag[mt][2] = *(const uint32_t*)(Ab + r0 + 8);
                a_frag[mt][3] = *(const uint32_t*)(Ab + r0 + 8 * AST + 8);
            }
            #pragma unroll
            for (int nt = 0; nt < 4; nt++) {
                int rn = (warp_n * 32 + nt * 8 + gid) * AST + kk + tig * 2;
                b_frag[nt][0] = *(const uint32_t*)(Bb + rn);
                b_frag[nt][1] = *(const uint32_t*)(Bb + rn + 8);
            }
            #pragma unroll
            for (int mt = 0; mt < 2; mt++)
                #pragma unroll
                for (int nt = 0; nt < 4; nt++)
                    MMA_BF16(acc[mt][nt], a_frag[mt], b_frag[nt]);
        }
        __syncthreads();
    }

    #pragma unroll
    for (int mt = 0; mt < 2; mt++)
        #pragma unroll
        for (int nt = 0; nt < 4; nt++) {
            int i0r = m0 + warp_m * 32 + mt * 16 + gid;
            int col = warp_n * 32 + nt * 8 + tig * 2;
            #pragma unroll
            for (int half = 0; half < 2; half++) {
                int i = i0r + half * 8;
                float vx = acc[mt][nt][half*2+0], vy = acc[mt][nt][half*2+1];
                __nv_bfloat162 hh, ll;
                split2(vx, vy, hh, ll);
                __nv_bfloat16* r = g_a3 + (size_t)(i * BS + b) * (3*DM) + n * DH + col;
                *(__nv_bfloat162*)(r)          = hh;
                *(__nv_bfloat162*)(r + DM)     = ll;
                *(__nv_bfloat162*)(r + 2*DM)   = hh;
            }
        }
}

// ==================== conversions / prep =====================================
template<int MODE>
__global__ void split_rows_kernel(const float* __restrict__ X, __nv_bfloat16* __restrict__ Y,
                                  int kshift, long total) {
    long e = ((long)blockIdx.x * 256 + threadIdx.x) * 4;
    if (e >= total) return;
    int K = 1 << kshift;
    long r = e >> kshift; int c = (int)(e & (K - 1));
    float4 v = *(const float4*)(X + e);
    __nv_bfloat162 h01, l01, h23, l23;
    split2(v.x, v.y, h01, l01);
    split2(v.z, v.w, h23, l23);
    __nv_bfloat16* yb = Y + r * 3 * K;
    *(__nv_bfloat162*)(yb + c)       = h01; *(__nv_bfloat162*)(yb + c + 2)       = h23;
    if (MODE == 0) {
        *(__nv_bfloat162*)(yb + K + c)   = l01; *(__nv_bfloat162*)(yb + K + c + 2)   = l23;
        *(__nv_bfloat162*)(yb + 2*K + c) = h01; *(__nv_bfloat162*)(yb + 2*K + c + 2) = h23;
    } else {
        *(__nv_bfloat162*)(yb + K + c)   = h01; *(__nv_bfloat162*)(yb + K + c + 2)   = h23;
        *(__nv_bfloat162*)(yb + 2*K + c) = l01; *(__nv_bfloat162*)(yb + 2*K + c + 2) = l23;
    }
}

__global__ void split_tr_kernel(const float* __restrict__ W, __nv_bfloat16* __restrict__ Y,
                                int K, int N) {
    __shared__ float s[32][33];
    int n0 = blockIdx.x * 32, k0 = blockIdx.y * 32;
    int tx = threadIdx.x, ty = threadIdx.y;
    for (int i = ty; i < 32; i += 8)
        s[i][tx] = W[(size_t)(k0 + i) * N + n0 + tx];
    __syncthreads();
    for (int i = ty; i < 32; i += 8) {
        int n = n0 + i, k = k0 + tx;
        __nv_bfloat16 h, l; split1(s[tx][i], h, l);
        __nv_bfloat16* yb = Y + (size_t)n * 3 * K;
        yb[k] = h; yb[K + k] = h; yb[2*K + k] = l;
    }
}

// V^T from compact g_kvV -> g_v3 (B-layout over KL)
__global__ void vt3_kernel() {
    __shared__ float s[32][33];
    int j0 = blockIdx.x * 32, d0 = blockIdx.y * 32, bn = blockIdx.z;
    int b = bn >> 4, n = bn & 15;
    int tx = threadIdx.x, ty = threadIdx.y;
    for (int jj = ty; jj < 32; jj += 8)
        s[jj][tx] = g_kvV[((size_t)(j0 + jj) * BS + b) * DM + n * DH + d0 + tx];
    __syncthreads();
    for (int dd = ty; dd < 32; dd += 8) {
        __nv_bfloat16 h, l; split1(s[tx][dd], h, l);
        __nv_bfloat16* o = g_v3 + ((size_t)bn * DH + d0 + dd) * (3*KL) + j0 + tx;
        o[0] = h; o[KL] = h; o[2*KL] = l;
    }
}

// ==================== misc kernels ===========================================
__global__ void embed_kernel(const int* __restrict__ data, const float* __restrict__ embW) {
    int t = blockIdx.x;
    int tok = data[t];
    int c = threadIdx.x * 4;
    float4 v = *(const float4*)(embW + (size_t)tok * DM + c);
    *(float4*)(g_core + (size_t)t * DM + c) = v;
    __nv_bfloat162 h01, l01, h23, l23;
    split2(v.x, v.y, h01, l01);
    split2(v.z, v.w, h23, l23);
    __nv_bfloat16* yb = g_core3 + (size_t)t * (3*DM);
    *(__nv_bfloat162*)(yb + c)        = h01; *(__nv_bfloat162*)(yb + c + 2)        = h23;
    *(__nv_bfloat162*)(yb + DM + c)   = l01; *(__nv_bfloat162*)(yb + DM + c + 2)   = l23;
    *(__nv_bfloat162*)(yb + 2*DM + c) = h01; *(__nv_bfloat162*)(yb + 2*DM + c + 2) = h23;
}

__global__ void pos_kernel() {
    int p = blockIdx.x;
    float ps = (float)(KL - 1 - p);
    for (int j = threadIdx.x; j < 512; j += 256) {
        float f = powf(10000.0f, -(float)j / 512.0f);
        float a = ps * f;
        g_posbuf[p * DM + j]       = sinf(a);
        g_posbuf[p * DM + 512 + j] = cosf(a);
    }
}

__global__ void concat3_kernel(const float* __restrict__ mem_i) {
    long e = ((long)blockIdx.x * 256 + threadIdx.x) * 4;
    long r = e >> 10; int c = (int)(e & 1023);
    float4 v;
    if (r < ML * BS) v = *(const float4*)(mem_i + e);
    else             v = *(const float4*)(g_core + (r - ML*BS) * (long)DM + c);
    __nv_bfloat162 h01, l01, h23, l23;
    split2(v.x, v.y, h01, l01);
    split2(v.z, v.w, h23, l23);
    __nv_bfloat16* yb = g_a3 + r * (3*DM);
    *(__nv_bfloat162*)(yb + c)        = h01; *(__nv_bfloat162*)(yb + c + 2)        = h23;
    *(__nv_bfloat162*)(yb + DM + c)   = l01; *(__nv_bfloat162*)(yb + DM + c + 2)   = l23;
    *(__nv_bfloat162*)(yb + 2*DM + c) = h01; *(__nv_bfloat162*)(yb + 2*DM + c + 2) = h23;
}

__global__ void copyout_kernel(float* __restrict__ dst) {
    int i = blockIdx.x * 256 + threadIdx.x;
    ((float4*)dst)[i] = ((const float4*)g_core)[i];
}

__global__ void softmax_kernel() {
    int i = blockIdx.x, bn = blockIdx.y;
    const float* ac = &g_P[((size_t)bn * QL + i) * KL];
    const float* bd = &g_BD[((size_t)bn * QL + i) * KL];
    int tid = threadIdx.x;
    int lim = i + ML;
    int limW = (i & ~127) + 640; if (limW > KL) limW = KL;
    float v[4]; float mx = -1e30f;
    #pragma unroll
    for (int r = 0; r < 4; r++) {
        int j = r * 256 + tid;
        float s = (j <= lim) ? ASCALE * (ac[j] + bd[j + QL - 1 - i]) : -1e30f;
        v[r] = s; mx = fmaxf(mx, s);
    }
    __shared__ float red[256];
    red[tid] = mx; __syncthreads();
    for (int st = 128; st > 0; st >>= 1) {
        if (tid < st) red[tid] = fmaxf(red[tid], red[tid + st]);
        __syncthreads();
    }
    mx = red[0]; __syncthreads();
    float sum = 0.f;
    #pragma unroll
    for (int r = 0; r < 4; r++) { v[r] = __expf(v[r] - mx); sum += v[r]; }
    red[tid] = sum; __syncthreads();
    for (int st = 128; st > 0; st >>= 1) {
        if (tid < st) red[tid] += red[tid + st];
        __syncthreads();
    }
    float inv = 1.0f / red[0];
    __nv_bfloat16* p = g_p3 + ((size_t)bn * QL + i) * (3*KL);
    #pragma unroll
    for (int r = 0; r < 4; r++) {
        int j = r * 256 + tid;
        if (j < limW) {
            __nv_bfloat16 h, l; split1(v[r] * inv, h, l);
            p[j] = h; p[KL + j] = l; p[2*KL + j] = h;
        }
    }
}

__global__ void add_ln_kernel(float* __restrict__ io, const float* __restrict__ add,
                              const float* __restrict__ g, const float* __restrict__ bt,
                              __nv_bfloat16* __restrict__ out3) {
    int t = blockIdx.x, tid = threadIdx.x;
    size_t base = (size_t)t * DM;
    float x[4]; float s = 0.f, sq = 0.f;
    #pragma unroll
    for (int r = 0; r < 4; r++) {
        int d = r * 256 + tid;
        float v = io[base + d] + add[base + d];
        x[r] = v; s += v; sq += v * v;
    }
    __shared__ float rs[256], rq[256];
    rs[tid] = s; rq[tid] = sq; __syncthreads();
    for (int st = 128; st > 0; st >>= 1) {
        if (tid < st) { rs[tid] += rs[tid + st]; rq[tid] += rq[tid + st]; }
        __syncthreads();
    }
    float mean = rs[0] * (1.0f / DM);
    float var  = rq[0] * (1.0f / DM) - mean * mean;
    float rstd = rsqrtf(var + 1e-5f);
    __nv_bfloat16* yb = out3 + (size_t)t * (3*DM);
    #pragma unroll
    for (int r = 0; r < 4; r++) {
        int d = r * 256 + tid;
        float o = (x[r] - mean) * rstd * g[d] + bt[d];
        io[base + d] = o;
        __nv_bfloat16 h, l; split1(o, h, l);
        yb[d] = h; yb[DM + d] = l; yb[2*DM + d] = h;
    }
}

__global__ void loss2_kernel(const float2* __restrict__ part,
                             const float* __restrict__ tgtlog, float* __restrict__ out) {
    int t = blockIdx.x, tid = threadIdx.x;
    const float2* pp = part + (size_t)t * NPART;
    float m = -1e30f;
    for (int j = tid; j < NPART; j += 256) m = fmaxf(m, pp[j].x);
    __shared__ float red[256];
    red[tid] = m; __syncthreads();
    for (int st = 128; st > 0; st >>= 1) {
        if (tid < st) red[tid] = fmaxf(red[tid], red[tid + st]);
        __syncthreads();
    }
    m = red[0]; __syncthreads();
    float s = 0.f;
    for (int j = tid; j < NPART; j += 256) s += pp[j].y * __expf(pp[j].x - m);
    red[tid] = s; __syncthreads();
    for (int st = 128; st > 0; st >>= 1) {
        if (tid < st) red[tid] += red[tid + st];
        __syncthreads();
    }
    if (tid == 0)
        out[t] = m + logf(red[0]) - tgtlog[t];
}

// ==================== host orchestration =====================================
static void split_tr_s(const float* W, __nv_bfloat16* Y, int K, int N, cudaStream_t st) {
    split_tr_kernel<<<dim3(N / 32, K / 32), dim3(32, 8), 0, st>>>(W, Y, K, N);
}

extern "C" void kernel_launch(void* const* d_in, const int* in_sizes, int n_in,
                              void* d_out, int out_size) {
    const int*   data   = (const int*)d_in[0];
    const int*   target = (const int*)d_in[1];
    const float* memory = (const float*)d_in[2];
    const float* embW   = (const float*)d_in[3];
    const float* rwb    = (const float*)d_in[4];
    const float* rrb    = (const float*)d_in[5];
    const float* Wq     = (const float*)d_in[6];
    const float* Wkv    = (const float*)d_in[7];
    const float* Wr     = (const float*)d_in[8];
    const float* Wo     = (const float*)d_in[9];
    const float* W1     = (const float*)d_in[10];
    const float* b1     = (const float*)d_in[11];
    const float* W2     = (const float*)d_in[12];
    const float* b2     = (const float*)d_in[13];
    const float* ln1g   = (const float*)d_in[14];
    const float* ln1b   = (const float*)d_in[15];
    const float* ln2g   = (const float*)d_in[16];
    const float* ln2b   = (const float*)d_in[17];

    float* out = (float*)d_out;
    const long SLAB = (long)ML * BS * DM;
    float* out_mems = (out_size >= 4096L + NLAY * SLAB) ? out + 4096 : nullptr;

    float *p_core, *p_pos, *p_tmp, *p_P, *p_BD, *p_lse;
    __nv_bfloat16 *p_a3, *p_core3, *p_emb3, *p_pos3, *p_q3a, *p_q3b, *p_k3, *p_rk3;
    __nv_bfloat16 *p_wq3, *p_wkv3, *p_wr3, *p_wo3, *p_w13, *p_w23;
    cudaGetSymbolAddress((void**)&p_core,   g_core);
    cudaGetSymbolAddress((void**)&p_pos,    g_posbuf);
    cudaGetSymbolAddress((void**)&p_tmp,    g_tmp);
    cudaGetSymbolAddress((void**)&p_lse,    g_lsebuf);
    cudaGetSymbolAddress((void**)&p_P,      g_P);
    cudaGetSymbolAddress((void**)&p_BD,     g_BD);
    cudaGetSymbolAddress((void**)&p_a3,     g_a3);
    cudaGetSymbolAddress((void**)&p_core3,  g_core3);
    cudaGetSymbolAddress((void**)&p_emb3,   g_emb3);
    cudaGetSymbolAddress((void**)&p_pos3,   g_pos3);
    cudaGetSymbolAddress((void**)&p_q3a,    g_q3a);
    cudaGetSymbolAddress((void**)&p_q3b,    g_q3b);
    cudaGetSymbolAddress((void**)&p_k3,     g_k3);
    cudaGetSymbolAddress((void**)&p_rk3,    g_rk3);
    cudaGetSymbolAddress((void**)&p_wq3,    g_wq3);
    cudaGetSymbolAddress((void**)&p_wkv3,   g_wkv3);
    cudaGetSymbolAddress((void**)&p_wr3,    g_wr3);
    cudaGetSymbolAddress((void**)&p_wo3,    g_wo3);
    cudaGetSymbolAddress((void**)&p_w13,    g_w13);
    cudaGetSymbolAddress((void**)&p_w23,    g_w23);

    float2* p_part = (float2*)p_lse;
    float*  p_tgt  = p_lse + (size_t)NQ * NPART * 2;

    static cudaStream_t s_a = nullptr, s_b = nullptr;
    static cudaEvent_t  s_ev[32];
    if (!s_a) {
        cudaStreamCreateWithFlags(&s_a, cudaStreamNonBlocking);
        cudaStreamCreateWithFlags(&s_b, cudaStreamNonBlocking);
        for (int i = 0; i < 32; i++) cudaEventCreateWithFlags(&s_ev[i], cudaEventDisableTiming);
    }
    cudaStream_t sa = s_a, sb = s_b;
    cudaEvent_t* E0  = s_ev;
    cudaEvent_t* EA  = s_ev + 6;
    cudaEvent_t* EB  = s_ev + 12;
    cudaEvent_t* EBD = s_ev + 18;
    cudaEvent_t  Estart = s_ev[24], EsplitA = s_ev[25], EsplitB = s_ev[26];

    // ---- fork: weight splits on sa/sb; embed/pos on default stream ----------
    cudaEventRecord(Estart, 0);
    cudaStreamWaitEvent(sa, Estart, 0);
    cudaStreamWaitEvent(sb, Estart, 0);
    {
        long total = (long)NV * DM;
        split_rows_kernel<1><<<(int)(total / 4 / 256), 256, 0, sb>>>(embW, p_emb3, 10, total);
    }
    for (int L = 0; L < NLAY; L++) {
        split_tr_s(Wkv + (long)L*DM*2*DM, p_wkv3 + (size_t)L*2*DM*3*DM, DM, 2*DM, sa);
        split_tr_s(W1  + (long)L*DM*DI,   p_w13  + (size_t)L*DI*3*DM,   DM, DI,   sa);
        split_tr_s(Wq  + (long)L*DM*DM,   p_wq3  + (size_t)L*DM*3*DM,   DM, DM,   sa);
        split_tr_s(W2  + (long)L*DI*DM,   p_w23  + (size_t)L*DM*3*DI,   DI, DM,   sb);
        split_tr_s(Wr  + (long)L*DM*DM,   p_wr3  + (size_t)L*DM*3*DM,   DM, DM,   sb);
        split_tr_s(Wo  + (long)L*DM*DM,   p_wo3  + (size_t)L*DM*3*DM,   DM, DM,   sb);
    }
    cudaEventRecord(EsplitA, sa);
    cudaEventRecord(EsplitB, sb);
    embed_kernel<<<NQ, 256>>>(data, embW);
    pos_kernel<<<KL, 256>>>();
    {
        long total = (long)KL * DM;
        split_rows_kernel<0><<<(int)(total / 4 / 256), 256>>>(p_pos, p_pos3, 10, total);
    }
    cudaStreamWaitEvent(0, EsplitA, 0);
    cudaStreamWaitEvent(0, EsplitB, 0);

    for (int L = 0; L < NLAY; L++) {
        cudaEventRecord(E0[L], 0);
        // --- SA: q chain (emits q3a/q3b directly) ---
        cudaStreamWaitEvent(sa, E0[L], 0);
        tc_gemm_q<<<dim3(8, 32), 256, 0, sa>>>(p_core3, p_wq3 + (size_t)L*DM*3*DM,
                                               rwb, rrb, 3*DM);
        cudaEventRecord(EA[L], sa);
        // --- SB: copyout + rk chain (emits rk3 directly) ---
        cudaStreamWaitEvent(sb, E0[L], 0);
        if (out_mems)
            copyout_kernel<<<4096, 256, 0, sb>>>(out_mems + (long)L * SLAB);
        tc_gemm_rk<<<dim3(8, 8), 256, 0, sb>>>(p_pos3, p_wr3 + (size_t)L*DM*3*DM, 3*DM);
        cudaEventRecord(EB[L], sb);
        // --- S0: kv chain (emits k3 + compact V directly) ---
        concat3_kernel<<<(int)((long)NK * DM / 4 / 256), 256>>>(memory + (long)L * SLAB);
        tc_gemm_kv<<<dim3(16, 64), 256>>>(p_a3, p_wkv3 + (size_t)L*2*DM*3*DM, 3*DM);
        vt3_kernel<<<dim3(KL/32, DH/32, 128), dim3(32, 8)>>>();
        // --- AC on S0 (needs q3a via EA; k3 in-order) ---
        cudaStreamWaitEvent(0, EA[L], 0);
        tc_gemm_bat<<<dim3(KL/128, QL/128, 128), 256>>>(
            p_q3a, (long)QL*192, p_k3, (long)KL*192, 127,
            p_P, (long)QL*KL, KL, 192, 1);
        // --- BD on SA (q3b in-order; rk3 via EB) ---
        cudaStreamWaitEvent(sa, EB[L], 0);
        tc_gemm_bat<<<dim3(KL/128, QL/128, 128), 256, 0, sa>>>(
            p_q3b, (long)QL*192, p_rk3, (long)KL*192, 15,
            p_BD, (long)QL*KL, KL, 192, 2);
        cudaEventRecord(EBD[L], sa);
        // --- S0: softmax -> pv -> Wo -> LN1 -> FF -> LN2 ---
        cudaStreamWaitEvent(0, EBD[L], 0);
        softmax_kernel<<<dim3(QL, 128), 256>>>();
        pv_gemm<<<dim3(1, QL/128, 128), 256>>>();
        tc_gemm<0><<<dim3(8, 32), 256>>>(p_a3, p_wo3 + (size_t)L*DM*3*DM,
                                         p_tmp, nullptr, NQ, DM, 3*DM);
        add_ln_kernel<<<NQ, 256>>>(p_core, p_tmp, ln1g + L*DM, ln1b + L*DM, p_core3);
        tc_gemm_relu3<<<dim3(32, 32), 256>>>(p_core3, p_w13 + (size_t)L*DI*3*DM,
                                             p_a3, b1 + L*DI, NQ, DI, 3*DM);
        tc_gemm<1><<<dim3(8, 32), 256>>>(p_a3, p_w23 + (size_t)L*DM*3*DI,
                                         p_tmp, b2 + L*DM, NQ, DM, 3*DI);
        add_ln_kernel<<<NQ, 256>>>(p_core, p_tmp, ln2g + L*DM, ln2b + L*DM, p_core3);
    }

    // logits + fused LSE ; loss
    tc_gemm_lse<<<dim3(NQ/128, NV/128), 256>>>(p_core3, p_emb3, target,
                                               p_part, p_tgt, 3*DM);
    loss2_kernel<<<NQ, 256>>>(p_part, p_tgt, out);
}